// round 10
// baseline (speedup 1.0000x reference)
#include <cuda_runtime.h>
#include <math.h>
#include <mma.h>

using namespace nvcuda;

#define Bc 4
#define Lc 1024
#define Kc 30
#define Dc 256
#define Hc 8
#define DKc 32

#define M1c (Bc*Lc)          // 4096
#define M2c (Bc*Lc*Kc)       // 122880

// ---------------- scratch (static device globals; no allocations) ----------------
__device__ float g_q[M1c*Dc];
__device__ float g_k[M1c*Dc];
__device__ float g_v[M1c*Dc];
__device__ float g_bias[Bc*Lc*Lc];              // 16 MB (fits in L2)
__device__ float g_ctx[M1c*Dc];
__device__ float g_tmp[M1c*Dc];
__device__ float g_hvp[M1c*Dc];                 // raw h_V_new @ W11[0:256]
__device__ float g_m1[M2c*Dc];                  // 126 MB
__device__ float g_m2[M2c*Dc];                  // 126 MB
__device__ float g_base;

__device__ __forceinline__ float to_tf32(float x) {
    float y;
    asm("cvt.rna.tf32.f32 %0, %1;" : "=f"(y) : "f"(x));
    return y;
}

// ---------------- reduction helpers ----------------
__device__ __forceinline__ float blockSum(float v, float* sh) {
    int lane = threadIdx.x & 31, wid = threadIdx.x >> 5;
#pragma unroll
    for (int o = 16; o; o >>= 1) v += __shfl_down_sync(0xffffffffu, v, o);
    if (lane == 0) sh[wid] = v;
    __syncthreads();
    if (wid == 0) {
        float r = (lane < 8) ? sh[lane] : 0.f;
#pragma unroll
        for (int o = 4; o; o >>= 1) r += __shfl_down_sync(0xffffffffu, r, o);
        if (lane == 0) sh[0] = r;
    }
    __syncthreads();
    float out = sh[0];
    __syncthreads();
    return out;
}

__device__ __forceinline__ float gelu_exact(float x) {
    return 0.5f * x * (1.0f + erff(x * 0.70710678118654752f));
}

// ---------------- bias base / fill / scatter ----------------
__global__ void bias_base_kernel(const float* __restrict__ nonE,
                                 const float* __restrict__ bias_W,
                                 const float* __restrict__ bias_b) {
    __shared__ float sh[8];
    int t = threadIdx.x;
    float p = nonE[t] * bias_W[t];
    float s = blockSum(p, sh);
    if (t == 0) g_base = s + bias_b[0];
}

__global__ void bias_fill_kernel() {
    int i = blockIdx.x * 256 + threadIdx.x;
    g_bias[i] = g_base;
}

// one warp per (b,l); k loop serial on lane 0 => last write wins for duplicate idx
__global__ void bias_scatter_kernel(const float* __restrict__ E,
                                    const int* __restrict__ E_idx,
                                    const float* __restrict__ bias_W,
                                    const float* __restrict__ bias_b) {
    int w = (blockIdx.x * blockDim.x + threadIdx.x) >> 5;
    int lane = threadIdx.x & 31;
    if (w >= Bc * Lc) return;
    float bb = bias_b[0];
    for (int k = 0; k < Kc; k++) {
        const float* er = E + (w * Kc + k) * Dc;
        float p = 0.f;
#pragma unroll
        for (int c = lane; c < Dc; c += 32) p += er[c] * bias_W[c];
#pragma unroll
        for (int o = 16; o; o >>= 1) p += __shfl_down_sync(0xffffffffu, p, o);
        if (lane == 0) {
            int idx = E_idx[w * Kc + k];
            g_bias[w * Lc + idx] = p + bb;
        }
    }
}

// ====== pipelined tensor-core tf32 128x128 GEMM, raw-accumulator store ======
// 2-stage smem double buffer + register prefetch; one sync per k-step.
// MODE 0: A_eff = A
// MODE 1: A_eff = gelu(A + aux[rowbase + k] + aux2[k])   (hvp + b11)
// MODE 2: A_eff = gelu(A + aux[k])                        (b12)
template<int MODE>
__global__ void __launch_bounds__(256, 2)
gemm_tc(const float* __restrict__ A, const float* __restrict__ Bm,
        float* __restrict__ C, int M, int N, int Kd,
        const float* __restrict__ aux, const float* __restrict__ aux2) {
    __shared__ float As[2][128][24];
    __shared__ float Bs[2][16][136];
    __shared__ int hvb[128];
    int t = threadIdx.x;
    int wid = t >> 5;
    int wm = wid & 3, wn = wid >> 2;
    int m0 = blockIdx.y * 128, n0 = blockIdx.x * 128;
    if (MODE == 1) {
        if (t < 128) hvb[t] = ((m0 + t) / Kc) * Dc;
        __syncthreads();
    }
    const float* Ablk = A + (size_t)m0 * Kd;
    const float* Bblk = Bm + n0;
    const int nk = Kd / 16;

    float4 av[2], bv[2], xv[2], yv[2];

    auto load_regs = [&](int kt) {
        int k0 = kt * 16;
#pragma unroll
        for (int i = 0; i < 2; i++) {
            int f = t * 2 + i;                 // 0..511
            int r = f >> 2, c4 = (f & 3) * 4;
            av[i] = *reinterpret_cast<const float4*>(Ablk + (size_t)r * Kd + k0 + c4);
            if (MODE == 1) {
                xv[i] = *reinterpret_cast<const float4*>(aux + hvb[r] + k0 + c4);
                yv[i] = *reinterpret_cast<const float4*>(aux2 + k0 + c4);
            }
            if (MODE == 2)
                xv[i] = *reinterpret_cast<const float4*>(aux + k0 + c4);
            int kk = f >> 5, c = (f & 31) * 4;
            bv[i] = *reinterpret_cast<const float4*>(Bblk + (size_t)(k0 + kk) * N + c);
        }
    };
    auto store_smem = [&](int buf) {
#pragma unroll
        for (int i = 0; i < 2; i++) {
            int f = t * 2 + i;
            int r = f >> 2, c4 = (f & 3) * 4;
            float vv[4] = {av[i].x, av[i].y, av[i].z, av[i].w};
            float xx[4] = {xv[i].x, xv[i].y, xv[i].z, xv[i].w};
            float yy[4] = {yv[i].x, yv[i].y, yv[i].z, yv[i].w};
#pragma unroll
            for (int j = 0; j < 4; j++) {
                float x = vv[j];
                if (MODE == 1) x = gelu_exact(x + xx[j] + yy[j]);
                if (MODE == 2) x = gelu_exact(x + xx[j]);
                As[buf][r][c4 + j] = to_tf32(x);
            }
            int kk = f >> 5, c = (f & 31) * 4;
            Bs[buf][kk][c + 0] = to_tf32(bv[i].x);
            Bs[buf][kk][c + 1] = to_tf32(bv[i].y);
            Bs[buf][kk][c + 2] = to_tf32(bv[i].z);
            Bs[buf][kk][c + 3] = to_tf32(bv[i].w);
        }
    };

    wmma::fragment<wmma::accumulator, 16, 16, 8, float> acc[2][4];
#pragma unroll
    for (int i = 0; i < 2; i++)
#pragma unroll
        for (int j = 0; j < 4; j++) wmma::fill_fragment(acc[i][j], 0.f);

    load_regs(0);
    store_smem(0);
    __syncthreads();

    for (int kt = 0; kt < nk; kt++) {
        int buf = kt & 1;
        if (kt + 1 < nk) load_regs(kt + 1);     // LDG issue, hidden under MMA
#pragma unroll
        for (int k8 = 0; k8 < 16; k8 += 8) {
            wmma::fragment<wmma::matrix_a, 16, 16, 8, wmma::precision::tf32, wmma::row_major> af[2];
            wmma::load_matrix_sync(af[0], &As[buf][wm * 32][k8], 24);
            wmma::load_matrix_sync(af[1], &As[buf][wm * 32 + 16][k8], 24);
#pragma unroll
            for (int ni = 0; ni < 4; ni++) {
                wmma::fragment<wmma::matrix_b, 16, 16, 8, wmma::precision::tf32, wmma::row_major> bf;
                wmma::load_matrix_sync(bf, &Bs[buf][k8][wn * 64 + ni * 16], 136);
                wmma::mma_sync(acc[0][ni], af[0], bf, acc[0][ni]);
                wmma::mma_sync(acc[1][ni], af[1], bf, acc[1][ni]);
            }
        }
        if (kt + 1 < nk) {
            store_smem(1 - buf);
            __syncthreads();
        }
    }
#pragma unroll
    for (int mi = 0; mi < 2; mi++)
#pragma unroll
        for (int ni = 0; ni < 4; ni++) {
            float* cp = C + (size_t)(m0 + wm * 32 + mi * 16) * N + n0 + wn * 64 + ni * 16;
            wmma::store_matrix_sync(cp, acc[mi][ni], N, wmma::mem_row_major);
        }
}

// ---- layer1: gather + pipelined tf32 TC GEMM, Kd=512 over [E | hVnew[E_idx]] ----
__global__ void __launch_bounds__(256, 2)
layer1_tc(const float* __restrict__ Ein,
          const int* __restrict__ E_idx,
          const float* __restrict__ hVnew,
          const float* __restrict__ W11) {
    __shared__ float As[2][128][24];
    __shared__ float Bs[2][16][136];
    __shared__ int nbb[128];
    int t = threadIdx.x;
    int wid = t >> 5;
    int wm = wid & 3, wn = wid >> 2;
    int m0 = blockIdx.y * 128, n0 = blockIdx.x * 128;
    if (t < 128) {
        int r = m0 + t;
        int b_ = r / (Lc * Kc);
        nbb[t] = (b_ * Lc + E_idx[r]) * Dc;
    }
    __syncthreads();
    const float* Bblk = W11 + (size_t)256 * Dc + n0;
    const int nk = 512 / 16;

    float4 av[2], bv[2];

    auto load_regs = [&](int kt) {
        int k0 = kt * 16;
#pragma unroll
        for (int i = 0; i < 2; i++) {
            int f = t * 2 + i;
            int r = f >> 2, c4 = (f & 3) * 4;
            int kc = k0 + c4;
            if (kc < 256)
                av[i] = *reinterpret_cast<const float4*>(Ein + (size_t)(m0 + r) * Dc + kc);
            else
                av[i] = *reinterpret_cast<const float4*>(hVnew + nbb[r] + kc - 256);
            int kk = f >> 5, c = (f & 31) * 4;
            bv[i] = *reinterpret_cast<const float4*>(Bblk + (size_t)(k0 + kk) * Dc + c);
        }
    };
    auto store_smem = [&](int buf) {
#pragma unroll
        for (int i = 0; i < 2; i++) {
            int f = t * 2 + i;
            int r = f >> 2, c4 = (f & 3) * 4;
            As[buf][r][c4 + 0] = to_tf32(av[i].x);
            As[buf][r][c4 + 1] = to_tf32(av[i].y);
            As[buf][r][c4 + 2] = to_tf32(av[i].z);
            As[buf][r][c4 + 3] = to_tf32(av[i].w);
            int kk = f >> 5, c = (f & 31) * 4;
            Bs[buf][kk][c + 0] = to_tf32(bv[i].x);
            Bs[buf][kk][c + 1] = to_tf32(bv[i].y);
            Bs[buf][kk][c + 2] = to_tf32(bv[i].z);
            Bs[buf][kk][c + 3] = to_tf32(bv[i].w);
        }
    };

    wmma::fragment<wmma::accumulator, 16, 16, 8, float> acc[2][4];
#pragma unroll
    for (int i = 0; i < 2; i++)
#pragma unroll
        for (int j = 0; j < 4; j++) wmma::fill_fragment(acc[i][j], 0.f);

    load_regs(0);
    store_smem(0);
    __syncthreads();

    for (int kt = 0; kt < nk; kt++) {
        int buf = kt & 1;
        if (kt + 1 < nk) load_regs(kt + 1);
#pragma unroll
        for (int k8 = 0; k8 < 16; k8 += 8) {
            wmma::fragment<wmma::matrix_a, 16, 16, 8, wmma::precision::tf32, wmma::row_major> af[2];
            wmma::load_matrix_sync(af[0], &As[buf][wm * 32][k8], 24);
            wmma::load_matrix_sync(af[1], &As[buf][wm * 32 + 16][k8], 24);
#pragma unroll
            for (int ni = 0; ni < 4; ni++) {
                wmma::fragment<wmma::matrix_b, 16, 16, 8, wmma::precision::tf32, wmma::row_major> bf;
                wmma::load_matrix_sync(bf, &Bs[buf][k8][wn * 64 + ni * 16], 136);
                wmma::mma_sync(acc[0][ni], af[0], bf, acc[0][ni]);
                wmma::mma_sync(acc[1][ni], af[1], bf, acc[1][ni]);
            }
        }
        if (kt + 1 < nk) {
            store_smem(1 - buf);
            __syncthreads();
        }
    }
#pragma unroll
    for (int mi = 0; mi < 2; mi++)
#pragma unroll
        for (int ni = 0; ni < 4; ni++) {
            float* cp = g_m1 + (size_t)(m0 + wm * 32 + mi * 16) * Dc + n0 + wn * 64 + ni * 16;
            wmma::store_matrix_sync(cp, acc[mi][ni], Dc, wmma::mem_row_major);
        }
}

// ================= fused flash attention (tf32 WMMA QK^T & PV, exact softmax) ========
// q/k/v inputs are RAW projections; bq/bk/bv added at smem-load time.
__global__ void __launch_bounds__(128)
flash_kernel(const float* __restrict__ mask,
             const float* __restrict__ bq,
             const float* __restrict__ bk,
             const float* __restrict__ bv) {
    __shared__ float Qs[64][36];
    __shared__ float Ks[64][36];
    __shared__ float Vs[64][36];
    __shared__ float Ss[64][68];
    __shared__ float rowm[64][2];
    __shared__ float rowl[64][2];
    __shared__ float maskS[64];

    int t = threadIdx.x;
    int wid = t >> 5;
    int m0 = blockIdx.x * 64;
    int bh = blockIdx.y; int b = bh >> 3, h = bh & 7;
    int bL = b * Lc;
    int myrow = t >> 1, myhalf = (t & 1) * 32;
    const float scale = 0.17677669529663687f;  // 1/sqrt(32)

    // load Q tile (bias added, pre-scaled, tf32)
#pragma unroll
    for (int f = t; f < 512; f += 128) {
        int r = f >> 3, c4 = (f & 7) * 4;
        float4 v = *reinterpret_cast<const float4*>(
            g_q + (size_t)(bL + m0 + r) * Dc + h * DKc + c4);
        float4 b4 = *reinterpret_cast<const float4*>(bq + h * DKc + c4);
        Qs[r][c4 + 0] = to_tf32((v.x + b4.x) * scale);
        Qs[r][c4 + 1] = to_tf32((v.y + b4.y) * scale);
        Qs[r][c4 + 2] = to_tf32((v.z + b4.z) * scale);
        Qs[r][c4 + 3] = to_tf32((v.w + b4.w) * scale);
    }

    // ---------- pass A: row max ----------
    float mymax = -3.0e38f;
    for (int kt = 0; kt < 16; kt++) {
        int k0 = kt * 64;
#pragma unroll
        for (int f = t; f < 512; f += 128) {
            int r = f >> 3, c4 = (f & 7) * 4;
            float4 v = *reinterpret_cast<const float4*>(
                g_k + (size_t)(bL + k0 + r) * Dc + h * DKc + c4);
            float4 b4 = *reinterpret_cast<const float4*>(bk + h * DKc + c4);
            Ks[r][c4 + 0] = to_tf32(v.x + b4.x);
            Ks[r][c4 + 1] = to_tf32(v.y + b4.y);
            Ks[r][c4 + 2] = to_tf32(v.z + b4.z);
            Ks[r][c4 + 3] = to_tf32(v.w + b4.w);
        }
        if (t < 64) maskS[t] = mask[bL + k0 + t];
        __syncthreads();

        wmma::fragment<wmma::accumulator, 16, 16, 8, float> sfr[4];
#pragma unroll
        for (int ni = 0; ni < 4; ni++) wmma::fill_fragment(sfr[ni], 0.f);
#pragma unroll
        for (int k8 = 0; k8 < 32; k8 += 8) {
            wmma::fragment<wmma::matrix_a, 16, 16, 8, wmma::precision::tf32, wmma::row_major> af;
            wmma::load_matrix_sync(af, &Qs[wid * 16][k8], 36);
#pragma unroll
            for (int ni = 0; ni < 4; ni++) {
                wmma::fragment<wmma::matrix_b, 16, 16, 8, wmma::precision::tf32, wmma::col_major> bf;
                wmma::load_matrix_sync(bf, &Ks[ni * 16][k8], 36);
                wmma::mma_sync(sfr[ni], af, bf, sfr[ni]);
            }
        }
#pragma unroll
        for (int ni = 0; ni < 4; ni++)
            wmma::store_matrix_sync(&Ss[wid * 16][ni * 16], sfr[ni], 68, wmma::mem_row_major);
        __syncthreads();

        const float* brow = g_bias + (size_t)(bL + m0 + myrow) * Lc + k0 + myhalf;
        const float* srow = &Ss[myrow][myhalf];
#pragma unroll
        for (int i = 0; i < 32; i += 4) {
            float4 bb = *reinterpret_cast<const float4*>(brow + i);
            float s0 = srow[i + 0] + bb.x; if (maskS[myhalf + i + 0] <= 0.f) s0 = -1e9f;
            float s1 = srow[i + 1] + bb.y; if (maskS[myhalf + i + 1] <= 0.f) s1 = -1e9f;
            float s2 = srow[i + 2] + bb.z; if (maskS[myhalf + i + 2] <= 0.f) s2 = -1e9f;
            float s3 = srow[i + 3] + bb.w; if (maskS[myhalf + i + 3] <= 0.f) s3 = -1e9f;
            mymax = fmaxf(mymax, fmaxf(fmaxf(s0, s1), fmaxf(s2, s3)));
        }
        __syncthreads();
    }
    rowm[myrow][t & 1] = mymax;
    __syncthreads();
    float m_final = fmaxf(rowm[myrow][0], rowm[myrow][1]);

    // ---------- pass B: exp + sum + PV ----------
    float myl = 0.f;
    wmma::fragment<wmma::accumulator, 16, 16, 8, float> ofr[2];
    wmma::fill_fragment(ofr[0], 0.f);
    wmma::fill_fragment(ofr[1], 0.f);

    for (int kt = 0; kt < 16; kt++) {
        int k0 = kt * 64;
#pragma unroll
        for (int f = t; f < 1024; f += 128) {
            int r = (f >> 3) & 63, c4 = (f & 7) * 4;
            const float* src = (f < 512) ? g_k : g_v;
            const float* bsrc = (f < 512) ? bk : bv;
            float4 v = *reinterpret_cast<const float4*>(
                src + (size_t)(bL + k0 + r) * Dc + h * DKc + c4);
            float4 b4 = *reinterpret_cast<const float4*>(bsrc + h * DKc + c4);
            float* dst = (f < 512) ? &Ks[r][c4] : &Vs[r][c4];
            dst[0] = to_tf32(v.x + b4.x);
            dst[1] = to_tf32(v.y + b4.y);
            dst[2] = to_tf32(v.z + b4.z);
            dst[3] = to_tf32(v.w + b4.w);
        }
        if (t < 64) maskS[t] = mask[bL + k0 + t];
        __syncthreads();

        wmma::fragment<wmma::accumulator, 16, 16, 8, float> sfr[4];
#pragma unroll
        for (int ni = 0; ni < 4; ni++) wmma::fill_fragment(sfr[ni], 0.f);
#pragma unroll
        for (int k8 = 0; k8 < 32; k8 += 8) {
            wmma::fragment<wmma::matrix_a, 16, 16, 8, wmma::precision::tf32, wmma::row_major> af;
            wmma::load_matrix_sync(af, &Qs[wid * 16][k8], 36);
#pragma unroll
            for (int ni = 0; ni < 4; ni++) {
                wmma::fragment<wmma::matrix_b, 16, 16, 8, wmma::precision::tf32, wmma::col_major> bf;
                wmma::load_matrix_sync(bf, &Ks[ni * 16][k8], 36);
                wmma::mma_sync(sfr[ni], af, bf, sfr[ni]);
            }
        }
#pragma unroll
        for (int ni = 0; ni < 4; ni++)
            wmma::store_matrix_sync(&Ss[wid * 16][ni * 16], sfr[ni], 68, wmma::mem_row_major);
        __syncthreads();

        const float* brow = g_bias + (size_t)(bL + m0 + myrow) * Lc + k0 + myhalf;
        float* srow = &Ss[myrow][myhalf];
#pragma unroll
        for (int i = 0; i < 32; i += 4) {
            float4 bb = *reinterpret_cast<const float4*>(brow + i);
            float s0 = srow[i + 0] + bb.x; if (maskS[myhalf + i + 0] <= 0.f) s0 = -1e9f;
            float s1 = srow[i + 1] + bb.y; if (maskS[myhalf + i + 1] <= 0.f) s1 = -1e9f;
            float s2 = srow[i + 2] + bb.z; if (maskS[myhalf + i + 2] <= 0.f) s2 = -1e9f;
            float s3 = srow[i + 3] + bb.w; if (maskS[myhalf + i + 3] <= 0.f) s3 = -1e9f;
            float p0 = __expf(s0 - m_final);
            float p1 = __expf(s1 - m_final);
            float p2 = __expf(s2 - m_final);
            float p3 = __expf(s3 - m_final);
            myl += (p0 + p1) + (p2 + p3);
            srow[i + 0] = to_tf32(p0);
            srow[i + 1] = to_tf32(p1);
            srow[i + 2] = to_tf32(p2);
            srow[i + 3] = to_tf32(p3);
        }
        __syncthreads();

#pragma unroll
        for (int k8 = 0; k8 < 64; k8 += 8) {
            wmma::fragment<wmma::matrix_a, 16, 16, 8, wmma::precision::tf32, wmma::row_major> af;
            wmma::load_matrix_sync(af, &Ss[wid * 16][k8], 68);
#pragma unroll
            for (int ni = 0; ni < 2; ni++) {
                wmma::fragment<wmma::matrix_b, 16, 16, 8, wmma::precision::tf32, wmma::row_major> bf;
                wmma::load_matrix_sync(bf, &Vs[k8][ni * 16], 36);
                wmma::mma_sync(ofr[ni], af, bf, ofr[ni]);
            }
        }
        __syncthreads();
    }

    rowl[myrow][t & 1] = myl;
    wmma::store_matrix_sync(&Ss[wid * 16][0], ofr[0], 68, wmma::mem_row_major);
    wmma::store_matrix_sync(&Ss[wid * 16][16], ofr[1], 68, wmma::mem_row_major);
    __syncthreads();
    float linv = 1.f / (rowl[myrow][0] + rowl[myrow][1]);
    int myq = (t & 1) * 16;
    float* op = g_ctx + (size_t)(bL + m0 + myrow) * Dc + h * DKc + myq;
#pragma unroll
    for (int i = 0; i < 16; i += 4) {
        float4 o;
        o.x = Ss[myrow][myq + i + 0] * linv;
        o.y = Ss[myrow][myq + i + 1] * linv;
        o.z = Ss[myrow][myq + i + 2] * linv;
        o.w = Ss[myrow][myq + i + 3] * linv;
        *reinterpret_cast<float4*>(op + i) = o;
    }
}

// -------- LN1: h_V_new = LN(h_V + ctx@Wo(raw) + bo) * mask --------
__global__ void ln1_kernel(const float* __restrict__ hV,
                           const float* __restrict__ bo,
                           const float* __restrict__ gvec, const float* __restrict__ bvec,
                           const float* __restrict__ mask, float* __restrict__ out) {
    __shared__ float sh[8];
    int row = blockIdx.x, t = threadIdx.x;
    float x = hV[row * Dc + t] + g_tmp[row * Dc + t] + bo[t];
    float mean = blockSum(x, sh) * (1.f / Dc);
    float d = x - mean;
    float var = blockSum(d * d, sh) * (1.f / Dc);
    float y = d * rsqrtf(var + 1e-5f) * gvec[t] + bvec[t];
    out[row * Dc + t] = y * mask[row];
}

// ------- LN2 vectorized: h_E = LN(E + m1_raw + b13); 4 rows/block, float4 -------
__global__ void __launch_bounds__(256)
ln2v_kernel(const float* __restrict__ Ein,
            const float* __restrict__ b13,
            const float* __restrict__ gvec, const float* __restrict__ bvec,
            float* __restrict__ out) {
    __shared__ float s1[4][2], s2[4][2];
    int t = threadIdx.x;
    int rb = t >> 6;              // row in block 0..3
    int l6 = t & 63;              // lane within row
    int w2 = (t >> 5) & 1;        // warp-half within row
    size_t row = (size_t)blockIdx.x * 4 + rb;
    int c = l6 * 4;
    float4 e = *reinterpret_cast<const float4*>(Ein + row * Dc + c);
    float4 m = *reinterpret_cast<const float4*>(g_m1 + row * Dc + c);
    float4 bb = *reinterpret_cast<const float4*>(b13 + c);
    float x0 = e.x + m.x + bb.x;
    float x1 = e.y + m.y + bb.y;
    float x2 = e.z + m.z + bb.z;
    float x3 = e.w + m.w + bb.w;
    float sum = (x0 + x1) + (x2 + x3);
    float sq = x0 * x0 + x1 * x1 + x2 * x2 + x3 * x3;
#pragma unroll
    for (int o = 16; o; o >>= 1) {
        sum += __shfl_down_sync(0xffffffffu, sum, o);
        sq  += __shfl_down_sync(0xffffffffu, sq, o);
    }
    if ((t & 31) == 0) { s1[rb][w2] = sum; s2[rb][w2] = sq; }
    __syncthreads();
    float tot = s1[rb][0] + s1[rb][1];
    float tsq = s2[rb][0] + s2[rb][1];
    float mean = tot * (1.f / Dc);
    float var = tsq * (1.f / Dc) - mean * mean;
    float inv = rsqrtf(var + 1e-5f);
    float4 g4 = *reinterpret_cast<const float4*>(gvec + c);
    float4 b4 = *reinterpret_cast<const float4*>(bvec + c);
    float4 o;
    o.x = (x0 - mean) * inv * g4.x + b4.x;
    o.y = (x1 - mean) * inv * g4.y + b4.y;
    o.z = (x2 - mean) * inv * g4.z + b4.z;
    o.w = (x3 - mean) * inv * g4.w + b4.w;
    *reinterpret_cast<float4*>(out + row * Dc + c) = o;
}

// ---------------- host launch ----------------
extern "C" void kernel_launch(void* const* d_in, const int* in_sizes, int n_in,
                              void* d_out, int out_size) {
    const float* h_V    = (const float*)d_in[0];
    const float* E      = (const float*)d_in[1];
    const int*   E_idx  = (const int*)  d_in[2];
    const float* mask   = (const float*)d_in[3];
    const float* nonE   = (const float*)d_in[4];
    const float* bias_W = (const float*)d_in[5];
    const float* bias_b = (const float*)d_in[6];
    const float* Wq = (const float*)d_in[7];  const float* bq = (const float*)d_in[8];
    const float* Wk = (const float*)d_in[9];  const float* bk = (const float*)d_in[10];
    const float* Wv = (const float*)d_in[11]; const float* bv = (const float*)d_in[12];
    const float* Wo = (const float*)d_in[13]; const float* bo = (const float*)d_in[14];
    const float* ln1g = (const float*)d_in[15]; const float* ln1b = (const float*)d_in[16];
    const float* W11 = (const float*)d_in[17]; const float* b11 = (const float*)d_in[18];
    const float* W12 = (const float*)d_in[19]; const float* b12 = (const float*)d_in[20];
    const float* W13 = (const float*)d_in[21]; const float* b13 = (const float*)d_in[22];
    const float* ln2g = (const float*)d_in[23]; const float* ln2b = (const float*)d_in[24];

    float* out_hV = (float*)d_out;
    float* out_hE = out_hV + M1c * Dc;

    float *p_q, *p_k, *p_v, *p_ctx, *p_tmp, *p_hvp, *p_m1, *p_m2;
    cudaGetSymbolAddress((void**)&p_q,   g_q);
    cudaGetSymbolAddress((void**)&p_k,   g_k);
    cudaGetSymbolAddress((void**)&p_v,   g_v);
    cudaGetSymbolAddress((void**)&p_ctx, g_ctx);
    cudaGetSymbolAddress((void**)&p_tmp, g_tmp);
    cudaGetSymbolAddress((void**)&p_hvp, g_hvp);
    cudaGetSymbolAddress((void**)&p_m1,  g_m1);
    cudaGetSymbolAddress((void**)&p_m2,  g_m2);

    // attention bias
    bias_base_kernel<<<1, 256>>>(nonE, bias_W, bias_b);
    bias_fill_kernel<<<(Bc * Lc * Lc) / 256, 256>>>();
    bias_scatter_kernel<<<(Bc * Lc) / 8, 256>>>(E, E_idx, bias_W, bias_b);

    // qkv (TC, raw; biases folded into flash)
    dim3 gsmall(Dc / 128, M1c / 128);
    gemm_tc<0><<<gsmall, 256>>>(h_V, Wq, p_q, M1c, Dc, Dc, nullptr, nullptr);
    gemm_tc<0><<<gsmall, 256>>>(h_V, Wk, p_k, M1c, Dc, Dc, nullptr, nullptr);
    gemm_tc<0><<<gsmall, 256>>>(h_V, Wv, p_v, M1c, Dc, Dc, nullptr, nullptr);

    // fused flash attention -> g_ctx
    flash_kernel<<<dim3(Lc / 64, Bc * Hc), 128>>>(mask, bq, bk, bv);

    // out proj (raw) + LN1 (adds bo; writes h_V_new into d_out)
    gemm_tc<0><<<gsmall, 256>>>(p_ctx, Wo, p_tmp, M1c, Dc, Dc, nullptr, nullptr);
    ln1_kernel<<<M1c, 256>>>(h_V, bo, ln1g, ln1b, mask, out_hV);

    // MLP (pipelined TC tf32, raw-acc stores, bias+gelu fused into next consumer's load)
    gemm_tc<0><<<gsmall, 256>>>(out_hV, W11, p_hvp, M1c, Dc, Dc, nullptr, nullptr); // hvp raw
    dim3 gbig(Dc / 128, M2c / 128);
    layer1_tc<<<gbig, 256>>>(E, E_idx, out_hV, W11);                       // m1 = raw
    gemm_tc<1><<<gbig, 256>>>(p_m1, W12, p_m2, M2c, Dc, Dc, p_hvp, b11);  // m2 = gelu(m1+hvp+b11) @ W12
    gemm_tc<2><<<gbig, 256>>>(p_m2, W13, p_m1, M2c, Dc, Dc, b12, nullptr);// m1 = gelu(m2+b12) @ W13
    ln2v_kernel<<<M2c / 4, 256>>>(E, b13, ln2g, ln2b, out_hE);
}

// round 11
// speedup vs baseline: 1.0019x; 1.0019x over previous
#include <cuda_runtime.h>
#include <math.h>
#include <mma.h>

using namespace nvcuda;

#define Bc 4
#define Lc 1024
#define Kc 30
#define Dc 256
#define Hc 8
#define DKc 32

#define M1c (Bc*Lc)          // 4096
#define M2c (Bc*Lc*Kc)       // 122880

// ---------------- scratch (static device globals; no allocations) ----------------
__device__ float g_q[M1c*Dc];
__device__ float g_k[M1c*Dc];
__device__ float g_v[M1c*Dc];
__device__ float g_bias[Bc*Lc*Lc];              // 16 MB (fits in L2)
__device__ float g_ctx[M1c*Dc];
__device__ float g_tmp[M1c*Dc];
__device__ float g_hvp[M1c*Dc];                 // raw h_V_new @ W11[0:256]
__device__ float g_m1[M2c*Dc];                  // 126 MB
__device__ float g_m2[M2c*Dc];                  // 126 MB
__device__ float g_base;

__device__ __forceinline__ float to_tf32(float x) {
    float y;
    asm("cvt.rna.tf32.f32 %0, %1;" : "=f"(y) : "f"(x));
    return y;
}

// ---------------- reduction helpers ----------------
__device__ __forceinline__ float blockSum(float v, float* sh) {
    int lane = threadIdx.x & 31, wid = threadIdx.x >> 5;
#pragma unroll
    for (int o = 16; o; o >>= 1) v += __shfl_down_sync(0xffffffffu, v, o);
    if (lane == 0) sh[wid] = v;
    __syncthreads();
    if (wid == 0) {
        float r = (lane < 8) ? sh[lane] : 0.f;
#pragma unroll
        for (int o = 4; o; o >>= 1) r += __shfl_down_sync(0xffffffffu, r, o);
        if (lane == 0) sh[0] = r;
    }
    __syncthreads();
    float out = sh[0];
    __syncthreads();
    return out;
}

__device__ __forceinline__ float gelu_exact(float x) {
    return 0.5f * x * (1.0f + erff(x * 0.70710678118654752f));
}

// ---------------- bias base / fill / scatter ----------------
__global__ void bias_base_kernel(const float* __restrict__ nonE,
                                 const float* __restrict__ bias_W,
                                 const float* __restrict__ bias_b) {
    __shared__ float sh[8];
    int t = threadIdx.x;
    float p = nonE[t] * bias_W[t];
    float s = blockSum(p, sh);
    if (t == 0) g_base = s + bias_b[0];
}

__global__ void bias_fill_kernel() {
    int i = blockIdx.x * 256 + threadIdx.x;
    g_bias[i] = g_base;
}

// one warp per (b,l); k loop serial on lane 0 => last write wins for duplicate idx
__global__ void bias_scatter_kernel(const float* __restrict__ E,
                                    const int* __restrict__ E_idx,
                                    const float* __restrict__ bias_W,
                                    const float* __restrict__ bias_b) {
    int w = (blockIdx.x * blockDim.x + threadIdx.x) >> 5;
    int lane = threadIdx.x & 31;
    if (w >= Bc * Lc) return;
    float bb = bias_b[0];
    for (int k = 0; k < Kc; k++) {
        const float* er = E + (w * Kc + k) * Dc;
        float p = 0.f;
#pragma unroll
        for (int c = lane; c < Dc; c += 32) p += er[c] * bias_W[c];
#pragma unroll
        for (int o = 16; o; o >>= 1) p += __shfl_down_sync(0xffffffffu, p, o);
        if (lane == 0) {
            int idx = E_idx[w * Kc + k];
            g_bias[w * Lc + idx] = p + bb;
        }
    }
}

// ====== pipelined tensor-core tf32 128x128 GEMM, raw-accumulator store ======
// 2-stage smem double buffer + register prefetch; one sync per k-step.
// MODE 0: A_eff = A
// MODE 1: A_eff = gelu(A + aux[rowbase + k] + aux2[k])   (hvp + b11)
// MODE 2: A_eff = gelu(A + aux[k])                        (b12)
template<int MODE>
__global__ void __launch_bounds__(256, 2)
gemm_tc(const float* __restrict__ A, const float* __restrict__ Bm,
        float* __restrict__ C, int M, int N, int Kd,
        const float* __restrict__ aux, const float* __restrict__ aux2) {
    __shared__ float As[2][128][24];
    __shared__ float Bs[2][16][136];
    __shared__ int hvb[128];
    int t = threadIdx.x;
    int wid = t >> 5;
    int wm = wid & 3, wn = wid >> 2;
    int m0 = blockIdx.y * 128, n0 = blockIdx.x * 128;
    if (MODE == 1) {
        if (t < 128) hvb[t] = ((m0 + t) / Kc) * Dc;
        __syncthreads();
    }
    const float* Ablk = A + (size_t)m0 * Kd;
    const float* Bblk = Bm + n0;
    const int nk = Kd / 16;

    float4 av[2], bv[2], xv[2], yv[2];

    auto load_regs = [&](int kt) {
        int k0 = kt * 16;
#pragma unroll
        for (int i = 0; i < 2; i++) {
            int f = t * 2 + i;                 // 0..511
            int r = f >> 2, c4 = (f & 3) * 4;
            av[i] = *reinterpret_cast<const float4*>(Ablk + (size_t)r * Kd + k0 + c4);
            if (MODE == 1) {
                xv[i] = *reinterpret_cast<const float4*>(aux + hvb[r] + k0 + c4);
                yv[i] = *reinterpret_cast<const float4*>(aux2 + k0 + c4);
            }
            if (MODE == 2)
                xv[i] = *reinterpret_cast<const float4*>(aux + k0 + c4);
            int kk = f >> 5, c = (f & 31) * 4;
            bv[i] = *reinterpret_cast<const float4*>(Bblk + (size_t)(k0 + kk) * N + c);
        }
    };
    auto store_smem = [&](int buf) {
#pragma unroll
        for (int i = 0; i < 2; i++) {
            int f = t * 2 + i;
            int r = f >> 2, c4 = (f & 3) * 4;
            float vv[4] = {av[i].x, av[i].y, av[i].z, av[i].w};
            float xx[4] = {xv[i].x, xv[i].y, xv[i].z, xv[i].w};
            float yy[4] = {yv[i].x, yv[i].y, yv[i].z, yv[i].w};
#pragma unroll
            for (int j = 0; j < 4; j++) {
                float x = vv[j];
                if (MODE == 1) x = gelu_exact(x + xx[j] + yy[j]);
                if (MODE == 2) x = gelu_exact(x + xx[j]);
                As[buf][r][c4 + j] = to_tf32(x);
            }
            int kk = f >> 5, c = (f & 31) * 4;
            Bs[buf][kk][c + 0] = to_tf32(bv[i].x);
            Bs[buf][kk][c + 1] = to_tf32(bv[i].y);
            Bs[buf][kk][c + 2] = to_tf32(bv[i].z);
            Bs[buf][kk][c + 3] = to_tf32(bv[i].w);
        }
    };

    wmma::fragment<wmma::accumulator, 16, 16, 8, float> acc[2][4];
#pragma unroll
    for (int i = 0; i < 2; i++)
#pragma unroll
        for (int j = 0; j < 4; j++) wmma::fill_fragment(acc[i][j], 0.f);

    load_regs(0);
    store_smem(0);
    __syncthreads();

    for (int kt = 0; kt < nk; kt++) {
        int buf = kt & 1;
        if (kt + 1 < nk) load_regs(kt + 1);     // LDG issue, hidden under MMA
#pragma unroll
        for (int k8 = 0; k8 < 16; k8 += 8) {
            wmma::fragment<wmma::matrix_a, 16, 16, 8, wmma::precision::tf32, wmma::row_major> af[2];
            wmma::load_matrix_sync(af[0], &As[buf][wm * 32][k8], 24);
            wmma::load_matrix_sync(af[1], &As[buf][wm * 32 + 16][k8], 24);
#pragma unroll
            for (int ni = 0; ni < 4; ni++) {
                wmma::fragment<wmma::matrix_b, 16, 16, 8, wmma::precision::tf32, wmma::row_major> bf;
                wmma::load_matrix_sync(bf, &Bs[buf][k8][wn * 64 + ni * 16], 136);
                wmma::mma_sync(acc[0][ni], af[0], bf, acc[0][ni]);
                wmma::mma_sync(acc[1][ni], af[1], bf, acc[1][ni]);
            }
        }
        if (kt + 1 < nk) {
            store_smem(1 - buf);
            __syncthreads();
        }
    }
#pragma unroll
    for (int mi = 0; mi < 2; mi++)
#pragma unroll
        for (int ni = 0; ni < 4; ni++) {
            float* cp = C + (size_t)(m0 + wm * 32 + mi * 16) * N + n0 + wn * 64 + ni * 16;
            wmma::store_matrix_sync(cp, acc[mi][ni], N, wmma::mem_row_major);
        }
}

// ---- layer1: gather + pipelined tf32 TC GEMM, Kd=512 over [E | hVnew[E_idx]] ----
__global__ void __launch_bounds__(256, 2)
layer1_tc(const float* __restrict__ Ein,
          const int* __restrict__ E_idx,
          const float* __restrict__ hVnew,
          const float* __restrict__ W11) {
    __shared__ float As[2][128][24];
    __shared__ float Bs[2][16][136];
    __shared__ int nbb[128];
    int t = threadIdx.x;
    int wid = t >> 5;
    int wm = wid & 3, wn = wid >> 2;
    int m0 = blockIdx.y * 128, n0 = blockIdx.x * 128;
    if (t < 128) {
        int r = m0 + t;
        int b_ = r / (Lc * Kc);
        nbb[t] = (b_ * Lc + E_idx[r]) * Dc;
    }
    __syncthreads();
    const float* Bblk = W11 + (size_t)256 * Dc + n0;
    const int nk = 512 / 16;

    float4 av[2], bv[2];

    auto load_regs = [&](int kt) {
        int k0 = kt * 16;
#pragma unroll
        for (int i = 0; i < 2; i++) {
            int f = t * 2 + i;
            int r = f >> 2, c4 = (f & 3) * 4;
            int kc = k0 + c4;
            if (kc < 256)
                av[i] = *reinterpret_cast<const float4*>(Ein + (size_t)(m0 + r) * Dc + kc);
            else
                av[i] = *reinterpret_cast<const float4*>(hVnew + nbb[r] + kc - 256);
            int kk = f >> 5, c = (f & 31) * 4;
            bv[i] = *reinterpret_cast<const float4*>(Bblk + (size_t)(k0 + kk) * Dc + c);
        }
    };
    auto store_smem = [&](int buf) {
#pragma unroll
        for (int i = 0; i < 2; i++) {
            int f = t * 2 + i;
            int r = f >> 2, c4 = (f & 3) * 4;
            As[buf][r][c4 + 0] = to_tf32(av[i].x);
            As[buf][r][c4 + 1] = to_tf32(av[i].y);
            As[buf][r][c4 + 2] = to_tf32(av[i].z);
            As[buf][r][c4 + 3] = to_tf32(av[i].w);
            int kk = f >> 5, c = (f & 31) * 4;
            Bs[buf][kk][c + 0] = to_tf32(bv[i].x);
            Bs[buf][kk][c + 1] = to_tf32(bv[i].y);
            Bs[buf][kk][c + 2] = to_tf32(bv[i].z);
            Bs[buf][kk][c + 3] = to_tf32(bv[i].w);
        }
    };

    wmma::fragment<wmma::accumulator, 16, 16, 8, float> acc[2][4];
#pragma unroll
    for (int i = 0; i < 2; i++)
#pragma unroll
        for (int j = 0; j < 4; j++) wmma::fill_fragment(acc[i][j], 0.f);

    load_regs(0);
    store_smem(0);
    __syncthreads();

    for (int kt = 0; kt < nk; kt++) {
        int buf = kt & 1;
        if (kt + 1 < nk) load_regs(kt + 1);
#pragma unroll
        for (int k8 = 0; k8 < 16; k8 += 8) {
            wmma::fragment<wmma::matrix_a, 16, 16, 8, wmma::precision::tf32, wmma::row_major> af[2];
            wmma::load_matrix_sync(af[0], &As[buf][wm * 32][k8], 24);
            wmma::load_matrix_sync(af[1], &As[buf][wm * 32 + 16][k8], 24);
#pragma unroll
            for (int ni = 0; ni < 4; ni++) {
                wmma::fragment<wmma::matrix_b, 16, 16, 8, wmma::precision::tf32, wmma::row_major> bf;
                wmma::load_matrix_sync(bf, &Bs[buf][k8][wn * 64 + ni * 16], 136);
                wmma::mma_sync(acc[0][ni], af[0], bf, acc[0][ni]);
                wmma::mma_sync(acc[1][ni], af[1], bf, acc[1][ni]);
            }
        }
        if (kt + 1 < nk) {
            store_smem(1 - buf);
            __syncthreads();
        }
    }
#pragma unroll
    for (int mi = 0; mi < 2; mi++)
#pragma unroll
        for (int ni = 0; ni < 4; ni++) {
            float* cp = g_m1 + (size_t)(m0 + wm * 32 + mi * 16) * Dc + n0 + wn * 64 + ni * 16;
            wmma::store_matrix_sync(cp, acc[mi][ni], Dc, wmma::mem_row_major);
        }
}

// ================= fused flash attention (tf32 WMMA QK^T & PV, exact softmax) ========
// q/k/v inputs are RAW projections; bq/bk/bv added at smem-load time.
__global__ void __launch_bounds__(128)
flash_kernel(const float* __restrict__ mask,
             const float* __restrict__ bq,
             const float* __restrict__ bk,
             const float* __restrict__ bv) {
    __shared__ float Qs[64][36];
    __shared__ float Ks[64][36];
    __shared__ float Vs[64][36];
    __shared__ float Ss[64][68];
    __shared__ float rowm[64][2];
    __shared__ float rowl[64][2];
    __shared__ float maskS[64];

    int t = threadIdx.x;
    int wid = t >> 5;
    int m0 = blockIdx.x * 64;
    int bh = blockIdx.y; int b = bh >> 3, h = bh & 7;
    int bL = b * Lc;
    int myrow = t >> 1, myhalf = (t & 1) * 32;
    const float scale = 0.17677669529663687f;  // 1/sqrt(32)

    // load Q tile (bias added, pre-scaled, tf32)
#pragma unroll
    for (int f = t; f < 512; f += 128) {
        int r = f >> 3, c4 = (f & 7) * 4;
        float4 v = *reinterpret_cast<const float4*>(
            g_q + (size_t)(bL + m0 + r) * Dc + h * DKc + c4);
        float4 b4 = *reinterpret_cast<const float4*>(bq + h * DKc + c4);
        Qs[r][c4 + 0] = to_tf32((v.x + b4.x) * scale);
        Qs[r][c4 + 1] = to_tf32((v.y + b4.y) * scale);
        Qs[r][c4 + 2] = to_tf32((v.z + b4.z) * scale);
        Qs[r][c4 + 3] = to_tf32((v.w + b4.w) * scale);
    }

    // ---------- pass A: row max ----------
    float mymax = -3.0e38f;
    for (int kt = 0; kt < 16; kt++) {
        int k0 = kt * 64;
#pragma unroll
        for (int f = t; f < 512; f += 128) {
            int r = f >> 3, c4 = (f & 7) * 4;
            float4 v = *reinterpret_cast<const float4*>(
                g_k + (size_t)(bL + k0 + r) * Dc + h * DKc + c4);
            float4 b4 = *reinterpret_cast<const float4*>(bk + h * DKc + c4);
            Ks[r][c4 + 0] = to_tf32(v.x + b4.x);
            Ks[r][c4 + 1] = to_tf32(v.y + b4.y);
            Ks[r][c4 + 2] = to_tf32(v.z + b4.z);
            Ks[r][c4 + 3] = to_tf32(v.w + b4.w);
        }
        if (t < 64) maskS[t] = mask[bL + k0 + t];
        __syncthreads();

        wmma::fragment<wmma::accumulator, 16, 16, 8, float> sfr[4];
#pragma unroll
        for (int ni = 0; ni < 4; ni++) wmma::fill_fragment(sfr[ni], 0.f);
#pragma unroll
        for (int k8 = 0; k8 < 32; k8 += 8) {
            wmma::fragment<wmma::matrix_a, 16, 16, 8, wmma::precision::tf32, wmma::row_major> af;
            wmma::load_matrix_sync(af, &Qs[wid * 16][k8], 36);
#pragma unroll
            for (int ni = 0; ni < 4; ni++) {
                wmma::fragment<wmma::matrix_b, 16, 16, 8, wmma::precision::tf32, wmma::col_major> bf;
                wmma::load_matrix_sync(bf, &Ks[ni * 16][k8], 36);
                wmma::mma_sync(sfr[ni], af, bf, sfr[ni]);
            }
        }
#pragma unroll
        for (int ni = 0; ni < 4; ni++)
            wmma::store_matrix_sync(&Ss[wid * 16][ni * 16], sfr[ni], 68, wmma::mem_row_major);
        __syncthreads();

        const float* brow = g_bias + (size_t)(bL + m0 + myrow) * Lc + k0 + myhalf;
        const float* srow = &Ss[myrow][myhalf];
#pragma unroll
        for (int i = 0; i < 32; i += 4) {
            float4 bb = *reinterpret_cast<const float4*>(brow + i);
            float s0 = srow[i + 0] + bb.x; if (maskS[myhalf + i + 0] <= 0.f) s0 = -1e9f;
            float s1 = srow[i + 1] + bb.y; if (maskS[myhalf + i + 1] <= 0.f) s1 = -1e9f;
            float s2 = srow[i + 2] + bb.z; if (maskS[myhalf + i + 2] <= 0.f) s2 = -1e9f;
            float s3 = srow[i + 3] + bb.w; if (maskS[myhalf + i + 3] <= 0.f) s3 = -1e9f;
            mymax = fmaxf(mymax, fmaxf(fmaxf(s0, s1), fmaxf(s2, s3)));
        }
        __syncthreads();
    }
    rowm[myrow][t & 1] = mymax;
    __syncthreads();
    float m_final = fmaxf(rowm[myrow][0], rowm[myrow][1]);

    // ---------- pass B: exp + sum + PV ----------
    float myl = 0.f;
    wmma::fragment<wmma::accumulator, 16, 16, 8, float> ofr[2];
    wmma::fill_fragment(ofr[0], 0.f);
    wmma::fill_fragment(ofr[1], 0.f);

    for (int kt = 0; kt < 16; kt++) {
        int k0 = kt * 64;
#pragma unroll
        for (int f = t; f < 1024; f += 128) {
            int r = (f >> 3) & 63, c4 = (f & 7) * 4;
            const float* src = (f < 512) ? g_k : g_v;
            const float* bsrc = (f < 512) ? bk : bv;
            float4 v = *reinterpret_cast<const float4*>(
                src + (size_t)(bL + k0 + r) * Dc + h * DKc + c4);
            float4 b4 = *reinterpret_cast<const float4*>(bsrc + h * DKc + c4);
            float* dst = (f < 512) ? &Ks[r][c4] : &Vs[r][c4];
            dst[0] = to_tf32(v.x + b4.x);
            dst[1] = to_tf32(v.y + b4.y);
            dst[2] = to_tf32(v.z + b4.z);
            dst[3] = to_tf32(v.w + b4.w);
        }
        if (t < 64) maskS[t] = mask[bL + k0 + t];
        __syncthreads();

        wmma::fragment<wmma::accumulator, 16, 16, 8, float> sfr[4];
#pragma unroll
        for (int ni = 0; ni < 4; ni++) wmma::fill_fragment(sfr[ni], 0.f);
#pragma unroll
        for (int k8 = 0; k8 < 32; k8 += 8) {
            wmma::fragment<wmma::matrix_a, 16, 16, 8, wmma::precision::tf32, wmma::row_major> af;
            wmma::load_matrix_sync(af, &Qs[wid * 16][k8], 36);
#pragma unroll
            for (int ni = 0; ni < 4; ni++) {
                wmma::fragment<wmma::matrix_b, 16, 16, 8, wmma::precision::tf32, wmma::col_major> bf;
                wmma::load_matrix_sync(bf, &Ks[ni * 16][k8], 36);
                wmma::mma_sync(sfr[ni], af, bf, sfr[ni]);
            }
        }
#pragma unroll
        for (int ni = 0; ni < 4; ni++)
            wmma::store_matrix_sync(&Ss[wid * 16][ni * 16], sfr[ni], 68, wmma::mem_row_major);
        __syncthreads();

        const float* brow = g_bias + (size_t)(bL + m0 + myrow) * Lc + k0 + myhalf;
        float* srow = &Ss[myrow][myhalf];
#pragma unroll
        for (int i = 0; i < 32; i += 4) {
            float4 bb = *reinterpret_cast<const float4*>(brow + i);
            float s0 = srow[i + 0] + bb.x; if (maskS[myhalf + i + 0] <= 0.f) s0 = -1e9f;
            float s1 = srow[i + 1] + bb.y; if (maskS[myhalf + i + 1] <= 0.f) s1 = -1e9f;
            float s2 = srow[i + 2] + bb.z; if (maskS[myhalf + i + 2] <= 0.f) s2 = -1e9f;
            float s3 = srow[i + 3] + bb.w; if (maskS[myhalf + i + 3] <= 0.f) s3 = -1e9f;
            float p0 = __expf(s0 - m_final);
            float p1 = __expf(s1 - m_final);
            float p2 = __expf(s2 - m_final);
            float p3 = __expf(s3 - m_final);
            myl += (p0 + p1) + (p2 + p3);
            srow[i + 0] = to_tf32(p0);
            srow[i + 1] = to_tf32(p1);
            srow[i + 2] = to_tf32(p2);
            srow[i + 3] = to_tf32(p3);
        }
        __syncthreads();

#pragma unroll
        for (int k8 = 0; k8 < 64; k8 += 8) {
            wmma::fragment<wmma::matrix_a, 16, 16, 8, wmma::precision::tf32, wmma::row_major> af;
            wmma::load_matrix_sync(af, &Ss[wid * 16][k8], 68);
#pragma unroll
            for (int ni = 0; ni < 2; ni++) {
                wmma::fragment<wmma::matrix_b, 16, 16, 8, wmma::precision::tf32, wmma::row_major> bf;
                wmma::load_matrix_sync(bf, &Vs[k8][ni * 16], 36);
                wmma::mma_sync(ofr[ni], af, bf, ofr[ni]);
            }
        }
        __syncthreads();
    }

    rowl[myrow][t & 1] = myl;
    wmma::store_matrix_sync(&Ss[wid * 16][0], ofr[0], 68, wmma::mem_row_major);
    wmma::store_matrix_sync(&Ss[wid * 16][16], ofr[1], 68, wmma::mem_row_major);
    __syncthreads();
    float linv = 1.f / (rowl[myrow][0] + rowl[myrow][1]);
    int myq = (t & 1) * 16;
    float* op = g_ctx + (size_t)(bL + m0 + myrow) * Dc + h * DKc + myq;
#pragma unroll
    for (int i = 0; i < 16; i += 4) {
        float4 o;
        o.x = Ss[myrow][myq + i + 0] * linv;
        o.y = Ss[myrow][myq + i + 1] * linv;
        o.z = Ss[myrow][myq + i + 2] * linv;
        o.w = Ss[myrow][myq + i + 3] * linv;
        *reinterpret_cast<float4*>(op + i) = o;
    }
}

// -------- LN1: h_V_new = LN(h_V + ctx@Wo(raw) + bo) * mask --------
__global__ void ln1_kernel(const float* __restrict__ hV,
                           const float* __restrict__ bo,
                           const float* __restrict__ gvec, const float* __restrict__ bvec,
                           const float* __restrict__ mask, float* __restrict__ out) {
    __shared__ float sh[8];
    int row = blockIdx.x, t = threadIdx.x;
    float x = hV[row * Dc + t] + g_tmp[row * Dc + t] + bo[t];
    float mean = blockSum(x, sh) * (1.f / Dc);
    float d = x - mean;
    float var = blockSum(d * d, sh) * (1.f / Dc);
    float y = d * rsqrtf(var + 1e-5f) * gvec[t] + bvec[t];
    out[row * Dc + t] = y * mask[row];
}

// ------- LN2 vectorized: h_E = LN(E + m1_raw + b13); 4 rows/block, float4 -------
__global__ void __launch_bounds__(256)
ln2v_kernel(const float* __restrict__ Ein,
            const float* __restrict__ b13,
            const float* __restrict__ gvec, const float* __restrict__ bvec,
            float* __restrict__ out) {
    __shared__ float s1[4][2], s2[4][2];
    int t = threadIdx.x;
    int rb = t >> 6;              // row in block 0..3
    int l6 = t & 63;              // lane within row
    int w2 = (t >> 5) & 1;        // warp-half within row
    size_t row = (size_t)blockIdx.x * 4 + rb;
    int c = l6 * 4;
    float4 e = *reinterpret_cast<const float4*>(Ein + row * Dc + c);
    float4 m = *reinterpret_cast<const float4*>(g_m1 + row * Dc + c);
    float4 bb = *reinterpret_cast<const float4*>(b13 + c);
    float x0 = e.x + m.x + bb.x;
    float x1 = e.y + m.y + bb.y;
    float x2 = e.z + m.z + bb.z;
    float x3 = e.w + m.w + bb.w;
    float sum = (x0 + x1) + (x2 + x3);
    float sq = x0 * x0 + x1 * x1 + x2 * x2 + x3 * x3;
#pragma unroll
    for (int o = 16; o; o >>= 1) {
        sum += __shfl_down_sync(0xffffffffu, sum, o);
        sq  += __shfl_down_sync(0xffffffffu, sq, o);
    }
    if ((t & 31) == 0) { s1[rb][w2] = sum; s2[rb][w2] = sq; }
    __syncthreads();
    float tot = s1[rb][0] + s1[rb][1];
    float tsq = s2[rb][0] + s2[rb][1];
    float mean = tot * (1.f / Dc);
    float var = tsq * (1.f / Dc) - mean * mean;
    float inv = rsqrtf(var + 1e-5f);
    float4 g4 = *reinterpret_cast<const float4*>(gvec + c);
    float4 b4 = *reinterpret_cast<const float4*>(bvec + c);
    float4 o;
    o.x = (x0 - mean) * inv * g4.x + b4.x;
    o.y = (x1 - mean) * inv * g4.y + b4.y;
    o.z = (x2 - mean) * inv * g4.z + b4.z;
    o.w = (x3 - mean) * inv * g4.w + b4.w;
    *reinterpret_cast<float4*>(out + row * Dc + c) = o;
}

// ---------------- host launch ----------------
extern "C" void kernel_launch(void* const* d_in, const int* in_sizes, int n_in,
                              void* d_out, int out_size) {
    const float* h_V    = (const float*)d_in[0];
    const float* E      = (const float*)d_in[1];
    const int*   E_idx  = (const int*)  d_in[2];
    const float* mask   = (const float*)d_in[3];
    const float* nonE   = (const float*)d_in[4];
    const float* bias_W = (const float*)d_in[5];
    const float* bias_b = (const float*)d_in[6];
    const float* Wq = (const float*)d_in[7];  const float* bq = (const float*)d_in[8];
    const float* Wk = (const float*)d_in[9];  const float* bk = (const float*)d_in[10];
    const float* Wv = (const float*)d_in[11]; const float* bv = (const float*)d_in[12];
    const float* Wo = (const float*)d_in[13]; const float* bo = (const float*)d_in[14];
    const float* ln1g = (const float*)d_in[15]; const float* ln1b = (const float*)d_in[16];
    const float* W11 = (const float*)d_in[17]; const float* b11 = (const float*)d_in[18];
    const float* W12 = (const float*)d_in[19]; const float* b12 = (const float*)d_in[20];
    const float* W13 = (const float*)d_in[21]; const float* b13 = (const float*)d_in[22];
    const float* ln2g = (const float*)d_in[23]; const float* ln2b = (const float*)d_in[24];

    float* out_hV = (float*)d_out;
    float* out_hE = out_hV + M1c * Dc;

    float *p_q, *p_k, *p_v, *p_ctx, *p_tmp, *p_hvp, *p_m1, *p_m2;
    cudaGetSymbolAddress((void**)&p_q,   g_q);
    cudaGetSymbolAddress((void**)&p_k,   g_k);
    cudaGetSymbolAddress((void**)&p_v,   g_v);
    cudaGetSymbolAddress((void**)&p_ctx, g_ctx);
    cudaGetSymbolAddress((void**)&p_tmp, g_tmp);
    cudaGetSymbolAddress((void**)&p_hvp, g_hvp);
    cudaGetSymbolAddress((void**)&p_m1,  g_m1);
    cudaGetSymbolAddress((void**)&p_m2,  g_m2);

    // attention bias
    bias_base_kernel<<<1, 256>>>(nonE, bias_W, bias_b);
    bias_fill_kernel<<<(Bc * Lc * Lc) / 256, 256>>>();
    bias_scatter_kernel<<<(Bc * Lc) / 8, 256>>>(E, E_idx, bias_W, bias_b);

    // qkv (TC, raw; biases folded into flash)
    dim3 gsmall(Dc / 128, M1c / 128);
    gemm_tc<0><<<gsmall, 256>>>(h_V, Wq, p_q, M1c, Dc, Dc, nullptr, nullptr);
    gemm_tc<0><<<gsmall, 256>>>(h_V, Wk, p_k, M1c, Dc, Dc, nullptr, nullptr);
    gemm_tc<0><<<gsmall, 256>>>(h_V, Wv, p_v, M1c, Dc, Dc, nullptr, nullptr);

    // fused flash attention -> g_ctx
    flash_kernel<<<dim3(Lc / 64, Bc * Hc), 128>>>(mask, bq, bk, bv);

    // out proj (raw) + LN1 (adds bo; writes h_V_new into d_out)
    gemm_tc<0><<<gsmall, 256>>>(p_ctx, Wo, p_tmp, M1c, Dc, Dc, nullptr, nullptr);
    ln1_kernel<<<M1c, 256>>>(h_V, bo, ln1g, ln1b, mask, out_hV);

    // MLP (pipelined TC tf32, raw-acc stores, bias+gelu fused into next consumer's load)
    gemm_tc<0><<<gsmall, 256>>>(out_hV, W11, p_hvp, M1c, Dc, Dc, nullptr, nullptr); // hvp raw
    dim3 gbig(Dc / 128, M2c / 128);
    layer1_tc<<<gbig, 256>>>(E, E_idx, out_hV, W11);                       // m1 = raw
    gemm_tc<1><<<gbig, 256>>>(p_m1, W12, p_m2, M2c, Dc, Dc, p_hvp, b11);  // m2 = gelu(m1+hvp+b11) @ W12
    gemm_tc<2><<<gbig, 256>>>(p_m2, W13, p_m1, M2c, Dc, Dc, b12, nullptr);// m1 = gelu(m2+b12) @ W13
    ln2v_kernel<<<M2c / 4, 256>>>(E, b13, ln2g, ln2b, out_hE);
}

// round 13
// speedup vs baseline: 1.0865x; 1.0845x over previous
#include <cuda_runtime.h>
#include <cstdint>
#include <math.h>
#include <mma.h>

using namespace nvcuda;

#define Bc 4
#define Lc 1024
#define Kc 30
#define Dc 256
#define Hc 8
#define DKc 32

#define M1c (Bc*Lc)          // 4096
#define M2c (Bc*Lc*Kc)       // 122880

#define NSTAGE 3

// ---------------- scratch (static device globals; no allocations) ----------------
__device__ float g_q[M1c*Dc];
__device__ float g_k[M1c*Dc];
__device__ float g_v[M1c*Dc];
__device__ float g_bias[Bc*Lc*Lc];              // 16 MB (fits in L2)
__device__ float g_ctx[M1c*Dc];
__device__ float g_tmp[M1c*Dc];
__device__ float g_hvp[M1c*Dc];                 // h_V_new @ W11[0:256] + b11
__device__ float g_m1[M2c*Dc];                  // 126 MB
__device__ float g_m2[M2c*Dc];                  // 126 MB
__device__ float g_base;

// ---------------- packed f32x2 helpers (for gemm64) ----------------
typedef unsigned long long u64;

__device__ __forceinline__ u64 pack2(float x, float y) {
    u64 r;
    asm("mov.b64 %0, {%1, %2};" : "=l"(r) : "f"(x), "f"(y));
    return r;
}
__device__ __forceinline__ void fma2(u64& d, u64 a, u64 b) {
    asm("fma.rn.f32x2 %0, %1, %2, %0;" : "+l"(d) : "l"(a), "l"(b));
}
__device__ __forceinline__ float2 unpack2(u64 v) {
    float2 f;
    asm("mov.b64 {%0, %1}, %2;" : "=f"(f.x), "=f"(f.y) : "l"(v));
    return f;
}
__device__ __forceinline__ float to_tf32(float x) {
    float y;
    asm("cvt.rna.tf32.f32 %0, %1;" : "=f"(y) : "f"(x));
    return y;
}

// ---------------- cp.async helpers ----------------
__device__ __forceinline__ void cp_async16(void* smem_dst, const void* gsrc) {
    uint32_t s = (uint32_t)__cvta_generic_to_shared(smem_dst);
    asm volatile("cp.async.cg.shared.global [%0], [%1], 16;" :: "r"(s), "l"(gsrc));
}
__device__ __forceinline__ void cp_commit() {
    asm volatile("cp.async.commit_group;");
}
template<int N>
__device__ __forceinline__ void cp_wait() {
    asm volatile("cp.async.wait_group %0;" :: "n"(N));
}

// ---------------- reduction helpers ----------------
__device__ __forceinline__ float blockSum(float v, float* sh) {
    int lane = threadIdx.x & 31, wid = threadIdx.x >> 5;
#pragma unroll
    for (int o = 16; o; o >>= 1) v += __shfl_down_sync(0xffffffffu, v, o);
    if (lane == 0) sh[wid] = v;
    __syncthreads();
    if (wid == 0) {
        float r = (lane < 8) ? sh[lane] : 0.f;
#pragma unroll
        for (int o = 4; o; o >>= 1) r += __shfl_down_sync(0xffffffffu, r, o);
        if (lane == 0) sh[0] = r;
    }
    __syncthreads();
    float out = sh[0];
    __syncthreads();
    return out;
}

__device__ __forceinline__ float gelu_exact(float x) {
    return 0.5f * x * (1.0f + erff(x * 0.70710678118654752f));
}

// ---------------- bias base / fill / scatter ----------------
__global__ void bias_base_kernel(const float* __restrict__ nonE,
                                 const float* __restrict__ bias_W,
                                 const float* __restrict__ bias_b) {
    __shared__ float sh[8];
    int t = threadIdx.x;
    float p = nonE[t] * bias_W[t];
    float s = blockSum(p, sh);
    if (t == 0) g_base = s + bias_b[0];
}

__global__ void bias_fill_kernel() {
    int i = blockIdx.x * 256 + threadIdx.x;
    g_bias[i] = g_base;
}

// one warp per (b,l); k loop serial on lane 0 => last write wins for duplicate idx
__global__ void bias_scatter_kernel(const float* __restrict__ E,
                                    const int* __restrict__ E_idx,
                                    const float* __restrict__ bias_W,
                                    const float* __restrict__ bias_b) {
    int w = (blockIdx.x * blockDim.x + threadIdx.x) >> 5;
    int lane = threadIdx.x & 31;
    if (w >= Bc * Lc) return;
    float bb = bias_b[0];
    for (int k = 0; k < Kc; k++) {
        const float* er = E + (w * Kc + k) * Dc;
        float p = 0.f;
#pragma unroll
        for (int c = lane; c < Dc; c += 32) p += er[c] * bias_W[c];
#pragma unroll
        for (int o = 16; o; o >>= 1) p += __shfl_down_sync(0xffffffffu, p, o);
        if (lane == 0) {
            int idx = E_idx[w * Kc + k];
            g_bias[w * Lc + idx] = p + bb;
        }
    }
}

// ---------------- 64x64 tiled fp32 GEMM with f32x2 (small M GEMMs) ----------------
__global__ void gemm64(const float* __restrict__ A, const float* __restrict__ Bm,
                       float* __restrict__ C, int M, int N, int Kd,
                       const float* __restrict__ bias, int act) {
    __shared__ float As[64][17];
    __shared__ float Bs[16][64];
    int t = threadIdx.x;
    int tx = t & 15, ty = t >> 4;
    int m0 = blockIdx.y * 64, n0 = blockIdx.x * 64;
    u64 acc[4][2] = {};
    for (int k0 = 0; k0 < Kd; k0 += 16) {
#pragma unroll
        for (int i = 0; i < 4; i++) {
            int e = t + i * 256; int r = e >> 4, c = e & 15;
            As[r][c] = A[(size_t)(m0 + r) * Kd + k0 + c];
        }
#pragma unroll
        for (int i = 0; i < 4; i++) {
            int e = t + i * 256; int kk = e >> 6, c = e & 63;
            Bs[kk][c] = Bm[(size_t)(k0 + kk) * N + n0 + c];
        }
        __syncthreads();
#pragma unroll
        for (int kk = 0; kk < 16; kk++) {
            ulonglong2 bb = *reinterpret_cast<const ulonglong2*>(&Bs[kk][tx * 4]);
#pragma unroll
            for (int i = 0; i < 4; i++) {
                float a = As[ty * 4 + i][kk];
                u64 aa = pack2(a, a);
                fma2(acc[i][0], aa, bb.x);
                fma2(acc[i][1], aa, bb.y);
            }
        }
        __syncthreads();
    }
#pragma unroll
    for (int i = 0; i < 4; i++) {
        int row = m0 + ty * 4 + i;
#pragma unroll
        for (int j = 0; j < 2; j++) {
            float2 v = unpack2(acc[i][j]);
            int col = n0 + tx * 4 + j * 2;
            float x0 = v.x + (bias ? bias[col] : 0.f);
            float x1 = v.y + (bias ? bias[col + 1] : 0.f);
            if (act == 1) { x0 = gelu_exact(x0); x1 = gelu_exact(x1); }
            C[(size_t)row * N + col] = x0;
            C[(size_t)row * N + col + 1] = x1;
        }
    }
}

// ====== cp.async-pipelined tensor-core tf32 128x128 GEMM, raw-accumulator store ======
// 3-stage cp.async pipeline; no register staging (regs stay well under cap).
// MODE 0: A_eff = A                                  (tf32 via HW truncation)
// MODE 1: A_eff = gelu(A + aux[rowbase + k])         (hvp, incl b11; rna cvt)
// MODE 2: A_eff = gelu(A + aux[k])                   (b12; rna cvt)
// Stores raw acc (no bias/act) to C. N == Dc.
template<int MODE>
__global__ void __launch_bounds__(256, 2)
gemm_tc(const float* __restrict__ A, const float* __restrict__ Bm,
        float* __restrict__ C, int M, int N, int Kd,
        const float* __restrict__ aux) {
    __shared__ float As[NSTAGE][128][20];
    __shared__ float Bs[NSTAGE][16][132];
    __shared__ int hvb[128];
    int t = threadIdx.x;
    int wid = t >> 5;
    int wm = wid & 3, wn = wid >> 2;
    int m0 = blockIdx.y * 128, n0 = blockIdx.x * 128;
    if (MODE == 1 && t < 128) hvb[t] = ((m0 + t) / Kc) * Dc;

    const float* Ablk = A + (size_t)m0 * Kd;
    const float* Bblk = Bm + n0;
    const int nk = Kd / 16;

    auto load_stage = [&](int s, int kt) {
        int k0 = kt * 16;
#pragma unroll
        for (int i = 0; i < 2; i++) {
            int f = t + i * 256;                   // 0..511
            int r = f >> 2, c4 = (f & 3) * 4;
            cp_async16(&As[s][r][c4], Ablk + (size_t)r * Kd + k0 + c4);
            int kk = f >> 5, c = (f & 31) * 4;
            cp_async16(&Bs[s][kk][c], Bblk + (size_t)(k0 + kk) * N + c);
        }
        cp_commit();
    };

    wmma::fragment<wmma::accumulator, 16, 16, 8, float> acc[2][4];
#pragma unroll
    for (int i = 0; i < 2; i++)
#pragma unroll
        for (int j = 0; j < 4; j++) wmma::fill_fragment(acc[i][j], 0.f);

    load_stage(0, 0);
    load_stage(1, 1);

    for (int kt = 0; kt < nk; kt++) {
        int s = kt % NSTAGE;
        cp_wait<NSTAGE - 2>();
        __syncthreads();
        if (kt + NSTAGE - 1 < nk)
            load_stage((kt + NSTAGE - 1) % NSTAGE, kt + NSTAGE - 1);
        if (MODE != 0) {
            int k0 = kt * 16;
#pragma unroll
            for (int i = 0; i < 2; i++) {
                int f = t + i * 256;
                int r = f >> 2, c4 = (f & 3) * 4;
                float4 v = *reinterpret_cast<const float4*>(&As[s][r][c4]);
                float4 x;
                if (MODE == 1) x = *reinterpret_cast<const float4*>(aux + hvb[r] + k0 + c4);
                else           x = *reinterpret_cast<const float4*>(aux + k0 + c4);
                v.x = to_tf32(gelu_exact(v.x + x.x));
                v.y = to_tf32(gelu_exact(v.y + x.y));
                v.z = to_tf32(gelu_exact(v.z + x.z));
                v.w = to_tf32(gelu_exact(v.w + x.w));
                *reinterpret_cast<float4*>(&As[s][r][c4]) = v;
            }
            __syncthreads();
        }
#pragma unroll
        for (int k8 = 0; k8 < 16; k8 += 8) {
            wmma::fragment<wmma::matrix_a, 16, 16, 8, wmma::precision::tf32, wmma::row_major> af[2];
            wmma::load_matrix_sync(af[0], &As[s][wm * 32][k8], 20);
            wmma::load_matrix_sync(af[1], &As[s][wm * 32 + 16][k8], 20);
#pragma unroll
            for (int ni = 0; ni < 4; ni++) {
                wmma::fragment<wmma::matrix_b, 16, 16, 8, wmma::precision::tf32, wmma::row_major> bf;
                wmma::load_matrix_sync(bf, &Bs[s][k8][wn * 64 + ni * 16], 132);
                wmma::mma_sync(acc[0][ni], af[0], bf, acc[0][ni]);
                wmma::mma_sync(acc[1][ni], af[1], bf, acc[1][ni]);
            }
        }
    }
#pragma unroll
    for (int mi = 0; mi < 2; mi++)
#pragma unroll
        for (int ni = 0; ni < 4; ni++) {
            float* cp = C + (size_t)(m0 + wm * 32 + mi * 16) * N + n0 + wn * 64 + ni * 16;
            wmma::store_matrix_sync(cp, acc[mi][ni], N, wmma::mem_row_major);
        }
}

// ---- layer1: gather + cp.async-pipelined tf32 TC GEMM, Kd=512 over [E | hVnew[E_idx]] ----
__global__ void __launch_bounds__(256, 2)
layer1_tc(const float* __restrict__ Ein,
          const int* __restrict__ E_idx,
          const float* __restrict__ hVnew,
          const float* __restrict__ W11) {
    __shared__ float As[NSTAGE][128][20];
    __shared__ float Bs[NSTAGE][16][132];
    __shared__ int nbb[128];
    int t = threadIdx.x;
    int wid = t >> 5;
    int wm = wid & 3, wn = wid >> 2;
    int m0 = blockIdx.y * 128, n0 = blockIdx.x * 128;
    if (t < 128) {
        int r = m0 + t;
        int b_ = r / (Lc * Kc);
        nbb[t] = (b_ * Lc + E_idx[r]) * Dc;
    }
    __syncthreads();   // nbb ready before any load_stage
    const float* Bblk = W11 + (size_t)256 * Dc + n0;
    const int nk = 512 / 16;

    auto load_stage = [&](int s, int kt) {
        int k0 = kt * 16;
#pragma unroll
        for (int i = 0; i < 2; i++) {
            int f = t + i * 256;
            int r = f >> 2, c4 = (f & 3) * 4;
            int kc = k0 + c4;
            const float* src;
            if (kc < 256) src = Ein + (size_t)(m0 + r) * Dc + kc;
            else          src = hVnew + nbb[r] + kc - 256;
            cp_async16(&As[s][r][c4], src);
            int kk = f >> 5, c = (f & 31) * 4;
            cp_async16(&Bs[s][kk][c], Bblk + (size_t)(k0 + kk) * Dc + c);
        }
        cp_commit();
    };

    wmma::fragment<wmma::accumulator, 16, 16, 8, float> acc[2][4];
#pragma unroll
    for (int i = 0; i < 2; i++)
#pragma unroll
        for (int j = 0; j < 4; j++) wmma::fill_fragment(acc[i][j], 0.f);

    load_stage(0, 0);
    load_stage(1, 1);

    for (int kt = 0; kt < nk; kt++) {
        int s = kt % NSTAGE;
        cp_wait<NSTAGE - 2>();
        __syncthreads();
        if (kt + NSTAGE - 1 < nk)
            load_stage((kt + NSTAGE - 1) % NSTAGE, kt + NSTAGE - 1);
#pragma unroll
        for (int k8 = 0; k8 < 16; k8 += 8) {
            wmma::fragment<wmma::matrix_a, 16, 16, 8, wmma::precision::tf32, wmma::row_major> af[2];
            wmma::load_matrix_sync(af[0], &As[s][wm * 32][k8], 20);
            wmma::load_matrix_sync(af[1], &As[s][wm * 32 + 16][k8], 20);
#pragma unroll
            for (int ni = 0; ni < 4; ni++) {
                wmma::fragment<wmma::matrix_b, 16, 16, 8, wmma::precision::tf32, wmma::row_major> bf;
                wmma::load_matrix_sync(bf, &Bs[s][k8][wn * 64 + ni * 16], 132);
                wmma::mma_sync(acc[0][ni], af[0], bf, acc[0][ni]);
                wmma::mma_sync(acc[1][ni], af[1], bf, acc[1][ni]);
            }
        }
    }
#pragma unroll
    for (int mi = 0; mi < 2; mi++)
#pragma unroll
        for (int ni = 0; ni < 4; ni++) {
            float* cp = g_m1 + (size_t)(m0 + wm * 32 + mi * 16) * Dc + n0 + wn * 64 + ni * 16;
            wmma::store_matrix_sync(cp, acc[mi][ni], Dc, wmma::mem_row_major);
        }
}

// ================= fused flash attention (tf32 WMMA QK^T & PV, exact softmax) ========
// q/k/v include their biases (added by gemm64).
__global__ void __launch_bounds__(128)
flash_kernel(const float* __restrict__ mask) {
    __shared__ float Qs[64][36];
    __shared__ float Ks[64][36];
    __shared__ float Vs[64][36];
    __shared__ float Ss[64][68];
    __shared__ float rowm[64][2];
    __shared__ float rowl[64][2];
    __shared__ float maskS[64];

    int t = threadIdx.x;
    int wid = t >> 5;
    int m0 = blockIdx.x * 64;
    int bh = blockIdx.y; int b = bh >> 3, h = bh & 7;
    int bL = b * Lc;
    int myrow = t >> 1, myhalf = (t & 1) * 32;
    const float scale = 0.17677669529663687f;  // 1/sqrt(32)

    // load Q tile (pre-scaled, tf32)
#pragma unroll
    for (int f = t; f < 512; f += 128) {
        int r = f >> 3, c4 = (f & 7) * 4;
        float4 v = *reinterpret_cast<const float4*>(
            g_q + (size_t)(bL + m0 + r) * Dc + h * DKc + c4);
        Qs[r][c4 + 0] = to_tf32(v.x * scale);
        Qs[r][c4 + 1] = to_tf32(v.y * scale);
        Qs[r][c4 + 2] = to_tf32(v.z * scale);
        Qs[r][c4 + 3] = to_tf32(v.w * scale);
    }

    // ---------- pass A: row max ----------
    float mymax = -3.0e38f;
    for (int kt = 0; kt < 16; kt++) {
        int k0 = kt * 64;
#pragma unroll
        for (int f = t; f < 512; f += 128) {
            int r = f >> 3, c4 = (f & 7) * 4;
            float4 v = *reinterpret_cast<const float4*>(
                g_k + (size_t)(bL + k0 + r) * Dc + h * DKc + c4);
            Ks[r][c4 + 0] = to_tf32(v.x);
            Ks[r][c4 + 1] = to_tf32(v.y);
            Ks[r][c4 + 2] = to_tf32(v.z);
            Ks[r][c4 + 3] = to_tf32(v.w);
        }
        if (t < 64) maskS[t] = mask[bL + k0 + t];
        __syncthreads();

        wmma::fragment<wmma::accumulator, 16, 16, 8, float> sfr[4];
#pragma unroll
        for (int ni = 0; ni < 4; ni++) wmma::fill_fragment(sfr[ni], 0.f);
#pragma unroll
        for (int k8 = 0; k8 < 32; k8 += 8) {
            wmma::fragment<wmma::matrix_a, 16, 16, 8, wmma::precision::tf32, wmma::row_major> af;
            wmma::load_matrix_sync(af, &Qs[wid * 16][k8], 36);
#pragma unroll
            for (int ni = 0; ni < 4; ni++) {
                wmma::fragment<wmma::matrix_b, 16, 16, 8, wmma::precision::tf32, wmma::col_major> bf;
                wmma::load_matrix_sync(bf, &Ks[ni * 16][k8], 36);
                wmma::mma_sync(sfr[ni], af, bf, sfr[ni]);
            }
        }
#pragma unroll
        for (int ni = 0; ni < 4; ni++)
            wmma::store_matrix_sync(&Ss[wid * 16][ni * 16], sfr[ni], 68, wmma::mem_row_major);
        __syncthreads();

        const float* brow = g_bias + (size_t)(bL + m0 + myrow) * Lc + k0 + myhalf;
        const float* srow = &Ss[myrow][myhalf];
#pragma unroll
        for (int i = 0; i < 32; i += 4) {
            float4 bb = *reinterpret_cast<const float4*>(brow + i);
            float s0 = srow[i + 0] + bb.x; if (maskS[myhalf + i + 0] <= 0.f) s0 = -1e9f;
            float s1 = srow[i + 1] + bb.y; if (maskS[myhalf + i + 1] <= 0.f) s1 = -1e9f;
            float s2 = srow[i + 2] + bb.z; if (maskS[myhalf + i + 2] <= 0.f) s2 = -1e9f;
            float s3 = srow[i + 3] + bb.w; if (maskS[myhalf + i + 3] <= 0.f) s3 = -1e9f;
            mymax = fmaxf(mymax, fmaxf(fmaxf(s0, s1), fmaxf(s2, s3)));
        }
        __syncthreads();
    }
    rowm[myrow][t & 1] = mymax;
    __syncthreads();
    float m_final = fmaxf(rowm[myrow][0], rowm[myrow][1]);

    // ---------- pass B: exp + sum + PV ----------
    float myl = 0.f;
    wmma::fragment<wmma::accumulator, 16, 16, 8, float> ofr[2];
    wmma::fill_fragment(ofr[0], 0.f);
    wmma::fill_fragment(ofr[1], 0.f);

    for (int kt = 0; kt < 16; kt++) {
        int k0 = kt * 64;
#pragma unroll
        for (int f = t; f < 1024; f += 128) {
            int r = (f >> 3) & 63, c4 = (f & 7) * 4;
            const float* src = (f < 512) ? g_k : g_v;
            float4 v = *reinterpret_cast<const float4*>(
                src + (size_t)(bL + k0 + r) * Dc + h * DKc + c4);
            float* dst = (f < 512) ? &Ks[r][c4] : &Vs[r][c4];
            dst[0] = to_tf32(v.x);
            dst[1] = to_tf32(v.y);
            dst[2] = to_tf32(v.z);
            dst[3] = to_tf32(v.w);
        }
        if (t < 64) maskS[t] = mask[bL + k0 + t];
        __syncthreads();

        wmma::fragment<wmma::accumulator, 16, 16, 8, float> sfr[4];
#pragma unroll
        for (int ni = 0; ni < 4; ni++) wmma::fill_fragment(sfr[ni], 0.f);
#pragma unroll
        for (int k8 = 0; k8 < 32; k8 += 8) {
            wmma::fragment<wmma::matrix_a, 16, 16, 8, wmma::precision::tf32, wmma::row_major> af;
            wmma::load_matrix_sync(af, &Qs[wid * 16][k8], 36);
#pragma unroll
            for (int ni = 0; ni < 4; ni++) {
                wmma::fragment<wmma::matrix_b, 16, 16, 8, wmma::precision::tf32, wmma::col_major> bf;
                wmma::load_matrix_sync(bf, &Ks[ni * 16][k8], 36);
                wmma::mma_sync(sfr[ni], af, bf, sfr[ni]);
            }
        }
#pragma unroll
        for (int ni = 0; ni < 4; ni++)
            wmma::store_matrix_sync(&Ss[wid * 16][ni * 16], sfr[ni], 68, wmma::mem_row_major);
        __syncthreads();

        const float* brow = g_bias + (size_t)(bL + m0 + myrow) * Lc + k0 + myhalf;
        float* srow = &Ss[myrow][myhalf];
#pragma unroll
        for (int i = 0; i < 32; i += 4) {
            float4 bb = *reinterpret_cast<const float4*>(brow + i);
            float s0 = srow[i + 0] + bb.x; if (maskS[myhalf + i + 0] <= 0.f) s0 = -1e9f;
            float s1 = srow[i + 1] + bb.y; if (maskS[myhalf + i + 1] <= 0.f) s1 = -1e9f;
            float s2 = srow[i + 2] + bb.z; if (maskS[myhalf + i + 2] <= 0.f) s2 = -1e9f;
            float s3 = srow[i + 3] + bb.w; if (maskS[myhalf + i + 3] <= 0.f) s3 = -1e9f;
            float p0 = __expf(s0 - m_final);
            float p1 = __expf(s1 - m_final);
            float p2 = __expf(s2 - m_final);
            float p3 = __expf(s3 - m_final);
            myl += (p0 + p1) + (p2 + p3);
            srow[i + 0] = to_tf32(p0);
            srow[i + 1] = to_tf32(p1);
            srow[i + 2] = to_tf32(p2);
            srow[i + 3] = to_tf32(p3);
        }
        __syncthreads();

#pragma unroll
        for (int k8 = 0; k8 < 64; k8 += 8) {
            wmma::fragment<wmma::matrix_a, 16, 16, 8, wmma::precision::tf32, wmma::row_major> af;
            wmma::load_matrix_sync(af, &Ss[wid * 16][k8], 68);
#pragma unroll
            for (int ni = 0; ni < 2; ni++) {
                wmma::fragment<wmma::matrix_b, 16, 16, 8, wmma::precision::tf32, wmma::row_major> bf;
                wmma::load_matrix_sync(bf, &Vs[k8][ni * 16], 36);
                wmma::mma_sync(ofr[ni], af, bf, ofr[ni]);
            }
        }
        __syncthreads();
    }

    rowl[myrow][t & 1] = myl;
    wmma::store_matrix_sync(&Ss[wid * 16][0], ofr[0], 68, wmma::mem_row_major);
    wmma::store_matrix_sync(&Ss[wid * 16][16], ofr[1], 68, wmma::mem_row_major);
    __syncthreads();
    float linv = 1.f / (rowl[myrow][0] + rowl[myrow][1]);
    int myq = (t & 1) * 16;
    float* op = g_ctx + (size_t)(bL + m0 + myrow) * Dc + h * DKc + myq;
#pragma unroll
    for (int i = 0; i < 16; i += 4) {
        float4 o;
        o.x = Ss[myrow][myq + i + 0] * linv;
        o.y = Ss[myrow][myq + i + 1] * linv;
        o.z = Ss[myrow][myq + i + 2] * linv;
        o.w = Ss[myrow][myq + i + 3] * linv;
        *reinterpret_cast<float4*>(op + i) = o;
    }
}

// ---------------- LN1: h_V_new = LN(h_V + ctx@Wo+bo) * mask ----------------
__global__ void ln1_kernel(const float* __restrict__ hV,
                           const float* __restrict__ gvec, const float* __restrict__ bvec,
                           const float* __restrict__ mask, float* __restrict__ out) {
    __shared__ float sh[8];
    int row = blockIdx.x, t = threadIdx.x;
    float x = hV[row * Dc + t] + g_tmp[row * Dc + t];
    float mean = blockSum(x, sh) * (1.f / Dc);
    float d = x - mean;
    float var = blockSum(d * d, sh) * (1.f / Dc);
    float y = d * rsqrtf(var + 1e-5f) * gvec[t] + bvec[t];
    out[row * Dc + t] = y * mask[row];
}

// ------- LN2 vectorized: h_E = LN(E + m1_raw + b13); 4 rows/block, float4 -------
__global__ void __launch_bounds__(256)
ln2v_kernel(const float* __restrict__ Ein,
            const float* __restrict__ b13,
            const float* __restrict__ gvec, const float* __restrict__ bvec,
            float* __restrict__ out) {
    __shared__ float s1[4][2], s2[4][2];
    int t = threadIdx.x;
    int rb = t >> 6;              // row in block 0..3
    int l6 = t & 63;              // lane within row
    int w2 = (t >> 5) & 1;        // warp-half within row
    size_t row = (size_t)blockIdx.x * 4 + rb;
    int c = l6 * 4;
    float4 e = *reinterpret_cast<const float4*>(Ein + row * Dc + c);
    float4 m = *reinterpret_cast<const float4*>(g_m1 + row * Dc + c);
    float4 bb = *reinterpret_cast<const float4*>(b13 + c);
    float x0 = e.x + m.x + bb.x;
    float x1 = e.y + m.y + bb.y;
    float x2 = e.z + m.z + bb.z;
    float x3 = e.w + m.w + bb.w;
    float sum = (x0 + x1) + (x2 + x3);
    float sq = x0 * x0 + x1 * x1 + x2 * x2 + x3 * x3;
#pragma unroll
    for (int o = 16; o; o >>= 1) {
        sum += __shfl_down_sync(0xffffffffu, sum, o);
        sq  += __shfl_down_sync(0xffffffffu, sq, o);
    }
    if ((t & 31) == 0) { s1[rb][w2] = sum; s2[rb][w2] = sq; }
    __syncthreads();
    float tot = s1[rb][0] + s1[rb][1];
    float tsq = s2[rb][0] + s2[rb][1];
    float mean = tot * (1.f / Dc);
    float var = tsq * (1.f / Dc) - mean * mean;
    float inv = rsqrtf(var + 1e-5f);
    float4 g4 = *reinterpret_cast<const float4*>(gvec + c);
    float4 b4 = *reinterpret_cast<const float4*>(bvec + c);
    float4 o;
    o.x = (x0 - mean) * inv * g4.x + b4.x;
    o.y = (x1 - mean) * inv * g4.y + b4.y;
    o.z = (x2 - mean) * inv * g4.z + b4.z;
    o.w = (x3 - mean) * inv * g4.w + b4.w;
    *reinterpret_cast<float4*>(out + row * Dc + c) = o;
}

// ---------------- host launch ----------------
extern "C" void kernel_launch(void* const* d_in, const int* in_sizes, int n_in,
                              void* d_out, int out_size) {
    const float* h_V    = (const float*)d_in[0];
    const float* E      = (const float*)d_in[1];
    const int*   E_idx  = (const int*)  d_in[2];
    const float* mask   = (const float*)d_in[3];
    const float* nonE   = (const float*)d_in[4];
    const float* bias_W = (const float*)d_in[5];
    const float* bias_b = (const float*)d_in[6];
    const float* Wq = (const float*)d_in[7];  const float* bq = (const float*)d_in[8];
    const float* Wk = (const float*)d_in[9];  const float* bk = (const float*)d_in[10];
    const float* Wv = (const float*)d_in[11]; const float* bv = (const float*)d_in[12];
    const float* Wo = (const float*)d_in[13]; const float* bo = (const float*)d_in[14];
    const float* ln1g = (const float*)d_in[15]; const float* ln1b = (const float*)d_in[16];
    const float* W11 = (const float*)d_in[17]; const float* b11 = (const float*)d_in[18];
    const float* W12 = (const float*)d_in[19]; const float* b12 = (const float*)d_in[20];
    const float* W13 = (const float*)d_in[21]; const float* b13 = (const float*)d_in[22];
    const float* ln2g = (const float*)d_in[23]; const float* ln2b = (const float*)d_in[24];

    float* out_hV = (float*)d_out;
    float* out_hE = out_hV + M1c * Dc;

    float *p_q, *p_k, *p_v, *p_ctx, *p_tmp, *p_hvp, *p_m1, *p_m2;
    cudaGetSymbolAddress((void**)&p_q,   g_q);
    cudaGetSymbolAddress((void**)&p_k,   g_k);
    cudaGetSymbolAddress((void**)&p_v,   g_v);
    cudaGetSymbolAddress((void**)&p_ctx, g_ctx);
    cudaGetSymbolAddress((void**)&p_tmp, g_tmp);
    cudaGetSymbolAddress((void**)&p_hvp, g_hvp);
    cudaGetSymbolAddress((void**)&p_m1,  g_m1);
    cudaGetSymbolAddress((void**)&p_m2,  g_m2);

    // attention bias
    bias_base_kernel<<<1, 256>>>(nonE, bias_W, bias_b);
    bias_fill_kernel<<<(Bc * Lc * Lc) / 256, 256>>>();
    bias_scatter_kernel<<<(Bc * Lc) / 8, 256>>>(E, E_idx, bias_W, bias_b);

    // qkv (SIMT gemm64, biases included — proven fastest at this size)
    dim3 gqkv(Dc / 64, M1c / 64);
    gemm64<<<gqkv, 256>>>(h_V, Wq, p_q, M1c, Dc, Dc, bq, 0);
    gemm64<<<gqkv, 256>>>(h_V, Wk, p_k, M1c, Dc, Dc, bk, 0);
    gemm64<<<gqkv, 256>>>(h_V, Wv, p_v, M1c, Dc, Dc, bv, 0);

    // fused flash attention -> g_ctx
    flash_kernel<<<dim3(Lc / 64, Bc * Hc), 128>>>(mask);

    // out proj + LN1 (writes h_V_new into d_out)
    gemm64<<<gqkv, 256>>>(p_ctx, Wo, p_tmp, M1c, Dc, Dc, bo, 0);
    ln1_kernel<<<M1c, 256>>>(h_V, ln1g, ln1b, mask, out_hV);

    // MLP (cp.async-pipelined TC tf32; raw-acc stores; bias+gelu fused into consumer's A path)
    gemm64<<<gqkv, 256>>>(out_hV, W11, p_hvp, M1c, Dc, Dc, b11, 0);  // hvp incl b11
    dim3 gbig(Dc / 128, M2c / 128);
    layer1_tc<<<gbig, 256>>>(E, E_idx, out_hV, W11);                 // m1 = raw
    gemm_tc<1><<<gbig, 256>>>(p_m1, W12, p_m2, M2c, Dc, Dc, p_hvp); // m2 = gelu(m1+hvp) @ W12 (raw)
    gemm_tc<2><<<gbig, 256>>>(p_m2, W13, p_m1, M2c, Dc, Dc, b12);   // m1 = gelu(m2+b12) @ W13 (raw)
    ln2v_kernel<<<M2c / 4, 256>>>(E, b13, ln2g, ln2b, out_hE);
}

// round 14
// speedup vs baseline: 1.1816x; 1.0875x over previous
#include <cuda_runtime.h>
#include <cstdint>
#include <math.h>
#include <mma.h>

using namespace nvcuda;

#define Bc 4
#define Lc 1024
#define Kc 30
#define Dc 256
#define Hc 8
#define DKc 32

#define M1c (Bc*Lc)          // 4096
#define M2c (Bc*Lc*Kc)       // 122880

#define NSTAGE 3

// ---------------- scratch (static device globals; no allocations) ----------------
__device__ float g_q[M1c*Dc];
__device__ float g_k[M1c*Dc];
__device__ float g_v[M1c*Dc];
__device__ float g_bias[Bc*Lc*Lc];              // 16 MB (fits in L2)
__device__ float g_ctx[M1c*Dc];
__device__ float g_tmp[M1c*Dc];
__device__ float g_hvp[M1c*Dc];                 // h_V_new @ W11[0:256] + b11
__device__ float g_hvw3[M1c*Dc];                // h_V_new @ W11[512:768]
__device__ float g_m1[M2c*Dc];                  // 126 MB
__device__ float g_m2[M2c*Dc];                  // 126 MB

// ---------------- packed f32x2 helpers (for gemm64) ----------------
typedef unsigned long long u64;

__device__ __forceinline__ u64 pack2(float x, float y) {
    u64 r;
    asm("mov.b64 %0, {%1, %2};" : "=l"(r) : "f"(x), "f"(y));
    return r;
}
__device__ __forceinline__ void fma2(u64& d, u64 a, u64 b) {
    asm("fma.rn.f32x2 %0, %1, %2, %0;" : "+l"(d) : "l"(a), "l"(b));
}
__device__ __forceinline__ float2 unpack2(u64 v) {
    float2 f;
    asm("mov.b64 {%0, %1}, %2;" : "=f"(f.x), "=f"(f.y) : "l"(v));
    return f;
}
__device__ __forceinline__ float to_tf32(float x) {
    float y;
    asm("cvt.rna.tf32.f32 %0, %1;" : "=f"(y) : "f"(x));
    return y;
}

// ---------------- cp.async helpers ----------------
__device__ __forceinline__ void cp_async16(void* smem_dst, const void* gsrc) {
    uint32_t s = (uint32_t)__cvta_generic_to_shared(smem_dst);
    asm volatile("cp.async.cg.shared.global [%0], [%1], 16;" :: "r"(s), "l"(gsrc));
}
__device__ __forceinline__ void cp_commit() {
    asm volatile("cp.async.commit_group;");
}
template<int N>
__device__ __forceinline__ void cp_wait() {
    asm volatile("cp.async.wait_group %0;" :: "n"(N));
}

// ---------------- reduction helpers ----------------
__device__ __forceinline__ float blockSum(float v, float* sh) {
    int lane = threadIdx.x & 31, wid = threadIdx.x >> 5;
#pragma unroll
    for (int o = 16; o; o >>= 1) v += __shfl_down_sync(0xffffffffu, v, o);
    if (lane == 0) sh[wid] = v;
    __syncthreads();
    if (wid == 0) {
        float r = (lane < 8) ? sh[lane] : 0.f;
#pragma unroll
        for (int o = 4; o; o >>= 1) r += __shfl_down_sync(0xffffffffu, r, o);
        if (lane == 0) sh[0] = r;
    }
    __syncthreads();
    float out = sh[0];
    __syncthreads();
    return out;
}

__device__ __forceinline__ float gelu_exact(float x) {
    return 0.5f * x * (1.0f + erff(x * 0.70710678118654752f));
}

// -------- bias fill (computes base per-block, fills plane) --------
__global__ void bias_fillbase_kernel(const float* __restrict__ nonE,
                                     const float* __restrict__ bias_W,
                                     const float* __restrict__ bias_b) {
    __shared__ float sh[8];
    int t = threadIdx.x;
    float p = nonE[t] * bias_W[t];
    float s = blockSum(p, sh);
    g_bias[(size_t)blockIdx.x * 256 + t] = s + bias_b[0];
}

// one warp per (b,l); k loop serial on lane 0 => last write wins for duplicate idx
__global__ void bias_scatter_kernel(const float* __restrict__ E,
                                    const int* __restrict__ E_idx,
                                    const float* __restrict__ bias_W,
                                    const float* __restrict__ bias_b) {
    int w = (blockIdx.x * blockDim.x + threadIdx.x) >> 5;
    int lane = threadIdx.x & 31;
    if (w >= Bc * Lc) return;
    float bb = bias_b[0];
    for (int k = 0; k < Kc; k++) {
        const float* er = E + (w * Kc + k) * Dc;
        float p = 0.f;
#pragma unroll
        for (int c = lane; c < Dc; c += 32) p += er[c] * bias_W[c];
#pragma unroll
        for (int o = 16; o; o >>= 1) p += __shfl_down_sync(0xffffffffu, p, o);
        if (lane == 0) {
            int idx = E_idx[w * Kc + k];
            g_bias[w * Lc + idx] = p + bb;
        }
    }
}

// ---------------- 64x64 tiled fp32 GEMM with f32x2 (small M GEMMs) ----------------
__global__ void gemm64(const float* __restrict__ A, const float* __restrict__ Bm,
                       float* __restrict__ C, int M, int N, int Kd,
                       const float* __restrict__ bias, int act) {
    __shared__ float As[64][17];
    __shared__ float Bs[16][64];
    int t = threadIdx.x;
    int tx = t & 15, ty = t >> 4;
    int m0 = blockIdx.y * 64, n0 = blockIdx.x * 64;
    u64 acc[4][2] = {};
    for (int k0 = 0; k0 < Kd; k0 += 16) {
#pragma unroll
        for (int i = 0; i < 4; i++) {
            int e = t + i * 256; int r = e >> 4, c = e & 15;
            As[r][c] = A[(size_t)(m0 + r) * Kd + k0 + c];
        }
#pragma unroll
        for (int i = 0; i < 4; i++) {
            int e = t + i * 256; int kk = e >> 6, c = e & 63;
            Bs[kk][c] = Bm[(size_t)(k0 + kk) * N + n0 + c];
        }
        __syncthreads();
#pragma unroll
        for (int kk = 0; kk < 16; kk++) {
            ulonglong2 bb = *reinterpret_cast<const ulonglong2*>(&Bs[kk][tx * 4]);
#pragma unroll
            for (int i = 0; i < 4; i++) {
                float a = As[ty * 4 + i][kk];
                u64 aa = pack2(a, a);
                fma2(acc[i][0], aa, bb.x);
                fma2(acc[i][1], aa, bb.y);
            }
        }
        __syncthreads();
    }
#pragma unroll
    for (int i = 0; i < 4; i++) {
        int row = m0 + ty * 4 + i;
#pragma unroll
        for (int j = 0; j < 2; j++) {
            float2 v = unpack2(acc[i][j]);
            int col = n0 + tx * 4 + j * 2;
            float x0 = v.x + (bias ? bias[col] : 0.f);
            float x1 = v.y + (bias ? bias[col + 1] : 0.f);
            if (act == 1) { x0 = gelu_exact(x0); x1 = gelu_exact(x1); }
            C[(size_t)row * N + col] = x0;
            C[(size_t)row * N + col + 1] = x1;
        }
    }
}

// ====== cp.async-pipelined tensor-core tf32 128x128 GEMM, raw-accumulator store ======
// 3-stage cp.async pipeline. In-smem transform applies RNA tf32 rounding to A and B
// (and the fused epilogue-of-previous-GEMM for MODE 1/2).
// MODE 0: A_eff = A
// MODE 1: A_eff = gelu(A + aux[hvb[r] + k] + aux2[nbb[r] + k])   (hvp + gathered hvW3)
// MODE 2: A_eff = gelu(A + aux[k])                                (b12)
// Stores raw acc (no bias/act) to C. N == Dc.
template<int MODE>
__global__ void __launch_bounds__(256, 2)
gemm_tc(const float* __restrict__ A, const float* __restrict__ Bm,
        float* __restrict__ C, int M, int N, int Kd,
        const float* __restrict__ aux, const float* __restrict__ aux2,
        const int* __restrict__ E_idx) {
    __shared__ float As[NSTAGE][128][20];
    __shared__ float Bs[NSTAGE][16][132];
    __shared__ int hvb[128];
    __shared__ int nbb[128];
    int t = threadIdx.x;
    int wid = t >> 5;
    int wm = wid & 3, wn = wid >> 2;
    int m0 = blockIdx.y * 128, n0 = blockIdx.x * 128;
    if (MODE == 1 && t < 128) {
        int r = m0 + t;
        hvb[t] = (r / Kc) * Dc;
        int b_ = r / (Lc * Kc);
        nbb[t] = (b_ * Lc + E_idx[r]) * Dc;
    }
    if (MODE == 1) __syncthreads();

    const float* Ablk = A + (size_t)m0 * Kd;
    const float* Bblk = Bm + n0;
    const int nk = Kd / 16;

    auto load_stage = [&](int s, int kt) {
        int k0 = kt * 16;
#pragma unroll
        for (int i = 0; i < 2; i++) {
            int f = t + i * 256;                   // 0..511
            int r = f >> 2, c4 = (f & 3) * 4;
            cp_async16(&As[s][r][c4], Ablk + (size_t)r * Kd + k0 + c4);
            int kk = f >> 5, c = (f & 31) * 4;
            cp_async16(&Bs[s][kk][c], Bblk + (size_t)(k0 + kk) * N + c);
        }
        cp_commit();
    };

    wmma::fragment<wmma::accumulator, 16, 16, 8, float> acc[2][4];
#pragma unroll
    for (int i = 0; i < 2; i++)
#pragma unroll
        for (int j = 0; j < 4; j++) wmma::fill_fragment(acc[i][j], 0.f);

    load_stage(0, 0);
    load_stage(1, 1);

    for (int kt = 0; kt < nk; kt++) {
        int s = kt % NSTAGE;
        cp_wait<NSTAGE - 2>();
        __syncthreads();
        if (kt + NSTAGE - 1 < nk)
            load_stage((kt + NSTAGE - 1) % NSTAGE, kt + NSTAGE - 1);
        // in-smem transform: fused adds/gelu (MODE 1/2) + RNA tf32 rounding (all modes)
        {
            int k0 = kt * 16;
#pragma unroll
            for (int i = 0; i < 2; i++) {
                int f = t + i * 256;
                int r = f >> 2, c4 = (f & 3) * 4;
                float4 v = *reinterpret_cast<const float4*>(&As[s][r][c4]);
                if (MODE == 1) {
                    float4 x = *reinterpret_cast<const float4*>(aux + hvb[r] + k0 + c4);
                    float4 y = *reinterpret_cast<const float4*>(aux2 + nbb[r] + k0 + c4);
                    v.x = gelu_exact(v.x + x.x + y.x);
                    v.y = gelu_exact(v.y + x.y + y.y);
                    v.z = gelu_exact(v.z + x.z + y.z);
                    v.w = gelu_exact(v.w + x.w + y.w);
                } else if (MODE == 2) {
                    float4 x = *reinterpret_cast<const float4*>(aux + k0 + c4);
                    v.x = gelu_exact(v.x + x.x);
                    v.y = gelu_exact(v.y + x.y);
                    v.z = gelu_exact(v.z + x.z);
                    v.w = gelu_exact(v.w + x.w);
                }
                v.x = to_tf32(v.x); v.y = to_tf32(v.y);
                v.z = to_tf32(v.z); v.w = to_tf32(v.w);
                *reinterpret_cast<float4*>(&As[s][r][c4]) = v;
                int kk = f >> 5, c = (f & 31) * 4;
                float4 b = *reinterpret_cast<const float4*>(&Bs[s][kk][c]);
                b.x = to_tf32(b.x); b.y = to_tf32(b.y);
                b.z = to_tf32(b.z); b.w = to_tf32(b.w);
                *reinterpret_cast<float4*>(&Bs[s][kk][c]) = b;
            }
            __syncthreads();
        }
#pragma unroll
        for (int k8 = 0; k8 < 16; k8 += 8) {
            wmma::fragment<wmma::matrix_a, 16, 16, 8, wmma::precision::tf32, wmma::row_major> af[2];
            wmma::load_matrix_sync(af[0], &As[s][wm * 32][k8], 20);
            wmma::load_matrix_sync(af[1], &As[s][wm * 32 + 16][k8], 20);
#pragma unroll
            for (int ni = 0; ni < 4; ni++) {
                wmma::fragment<wmma::matrix_b, 16, 16, 8, wmma::precision::tf32, wmma::row_major> bf;
                wmma::load_matrix_sync(bf, &Bs[s][k8][wn * 64 + ni * 16], 132);
                wmma::mma_sync(acc[0][ni], af[0], bf, acc[0][ni]);
                wmma::mma_sync(acc[1][ni], af[1], bf, acc[1][ni]);
            }
        }
    }
#pragma unroll
    for (int mi = 0; mi < 2; mi++)
#pragma unroll
        for (int ni = 0; ni < 4; ni++) {
            float* cp = C + (size_t)(m0 + wm * 32 + mi * 16) * N + n0 + wn * 64 + ni * 16;
            wmma::store_matrix_sync(cp, acc[mi][ni], N, wmma::mem_row_major);
        }
}

// ================= fused flash attention (tf32 WMMA QK^T & PV, exact softmax) ========
// q/k/v include their biases (added by gemm64).
__global__ void __launch_bounds__(128)
flash_kernel(const float* __restrict__ mask) {
    __shared__ float Qs[64][36];
    __shared__ float Ks[64][36];
    __shared__ float Vs[64][36];
    __shared__ float Ss[64][68];
    __shared__ float rowm[64][2];
    __shared__ float rowl[64][2];
    __shared__ float maskS[64];

    int t = threadIdx.x;
    int wid = t >> 5;
    int m0 = blockIdx.x * 64;
    int bh = blockIdx.y; int b = bh >> 3, h = bh & 7;
    int bL = b * Lc;
    int myrow = t >> 1, myhalf = (t & 1) * 32;
    const float scale = 0.17677669529663687f;  // 1/sqrt(32)

    // load Q tile (pre-scaled, tf32)
#pragma unroll
    for (int f = t; f < 512; f += 128) {
        int r = f >> 3, c4 = (f & 7) * 4;
        float4 v = *reinterpret_cast<const float4*>(
            g_q + (size_t)(bL + m0 + r) * Dc + h * DKc + c4);
        Qs[r][c4 + 0] = to_tf32(v.x * scale);
        Qs[r][c4 + 1] = to_tf32(v.y * scale);
        Qs[r][c4 + 2] = to_tf32(v.z * scale);
        Qs[r][c4 + 3] = to_tf32(v.w * scale);
    }

    // ---------- pass A: row max ----------
    float mymax = -3.0e38f;
    for (int kt = 0; kt < 16; kt++) {
        int k0 = kt * 64;
#pragma unroll
        for (int f = t; f < 512; f += 128) {
            int r = f >> 3, c4 = (f & 7) * 4;
            float4 v = *reinterpret_cast<const float4*>(
                g_k + (size_t)(bL + k0 + r) * Dc + h * DKc + c4);
            Ks[r][c4 + 0] = to_tf32(v.x);
            Ks[r][c4 + 1] = to_tf32(v.y);
            Ks[r][c4 + 2] = to_tf32(v.z);
            Ks[r][c4 + 3] = to_tf32(v.w);
        }
        if (t < 64) maskS[t] = mask[bL + k0 + t];
        __syncthreads();

        wmma::fragment<wmma::accumulator, 16, 16, 8, float> sfr[4];
#pragma unroll
        for (int ni = 0; ni < 4; ni++) wmma::fill_fragment(sfr[ni], 0.f);
#pragma unroll
        for (int k8 = 0; k8 < 32; k8 += 8) {
            wmma::fragment<wmma::matrix_a, 16, 16, 8, wmma::precision::tf32, wmma::row_major> af;
            wmma::load_matrix_sync(af, &Qs[wid * 16][k8], 36);
#pragma unroll
            for (int ni = 0; ni < 4; ni++) {
                wmma::fragment<wmma::matrix_b, 16, 16, 8, wmma::precision::tf32, wmma::col_major> bf;
                wmma::load_matrix_sync(bf, &Ks[ni * 16][k8], 36);
                wmma::mma_sync(sfr[ni], af, bf, sfr[ni]);
            }
        }
#pragma unroll
        for (int ni = 0; ni < 4; ni++)
            wmma::store_matrix_sync(&Ss[wid * 16][ni * 16], sfr[ni], 68, wmma::mem_row_major);
        __syncthreads();

        const float* brow = g_bias + (size_t)(bL + m0 + myrow) * Lc + k0 + myhalf;
        const float* srow = &Ss[myrow][myhalf];
#pragma unroll
        for (int i = 0; i < 32; i += 4) {
            float4 bb = *reinterpret_cast<const float4*>(brow + i);
            float s0 = srow[i + 0] + bb.x; if (maskS[myhalf + i + 0] <= 0.f) s0 = -1e9f;
            float s1 = srow[i + 1] + bb.y; if (maskS[myhalf + i + 1] <= 0.f) s1 = -1e9f;
            float s2 = srow[i + 2] + bb.z; if (maskS[myhalf + i + 2] <= 0.f) s2 = -1e9f;
            float s3 = srow[i + 3] + bb.w; if (maskS[myhalf + i + 3] <= 0.f) s3 = -1e9f;
            mymax = fmaxf(mymax, fmaxf(fmaxf(s0, s1), fmaxf(s2, s3)));
        }
        __syncthreads();
    }
    rowm[myrow][t & 1] = mymax;
    __syncthreads();
    float m_final = fmaxf(rowm[myrow][0], rowm[myrow][1]);

    // ---------- pass B: exp + sum + PV ----------
    float myl = 0.f;
    wmma::fragment<wmma::accumulator, 16, 16, 8, float> ofr[2];
    wmma::fill_fragment(ofr[0], 0.f);
    wmma::fill_fragment(ofr[1], 0.f);

    for (int kt = 0; kt < 16; kt++) {
        int k0 = kt * 64;
#pragma unroll
        for (int f = t; f < 1024; f += 128) {
            int r = (f >> 3) & 63, c4 = (f & 7) * 4;
            const float* src = (f < 512) ? g_k : g_v;
            float4 v = *reinterpret_cast<const float4*>(
                src + (size_t)(bL + k0 + r) * Dc + h * DKc + c4);
            float* dst = (f < 512) ? &Ks[r][c4] : &Vs[r][c4];
            dst[0] = to_tf32(v.x);
            dst[1] = to_tf32(v.y);
            dst[2] = to_tf32(v.z);
            dst[3] = to_tf32(v.w);
        }
        if (t < 64) maskS[t] = mask[bL + k0 + t];
        __syncthreads();

        wmma::fragment<wmma::accumulator, 16, 16, 8, float> sfr[4];
#pragma unroll
        for (int ni = 0; ni < 4; ni++) wmma::fill_fragment(sfr[ni], 0.f);
#pragma unroll
        for (int k8 = 0; k8 < 32; k8 += 8) {
            wmma::fragment<wmma::matrix_a, 16, 16, 8, wmma::precision::tf32, wmma::row_major> af;
            wmma::load_matrix_sync(af, &Qs[wid * 16][k8], 36);
#pragma unroll
            for (int ni = 0; ni < 4; ni++) {
                wmma::fragment<wmma::matrix_b, 16, 16, 8, wmma::precision::tf32, wmma::col_major> bf;
                wmma::load_matrix_sync(bf, &Ks[ni * 16][k8], 36);
                wmma::mma_sync(sfr[ni], af, bf, sfr[ni]);
            }
        }
#pragma unroll
        for (int ni = 0; ni < 4; ni++)
            wmma::store_matrix_sync(&Ss[wid * 16][ni * 16], sfr[ni], 68, wmma::mem_row_major);
        __syncthreads();

        const float* brow = g_bias + (size_t)(bL + m0 + myrow) * Lc + k0 + myhalf;
        float* srow = &Ss[myrow][myhalf];
#pragma unroll
        for (int i = 0; i < 32; i += 4) {
            float4 bb = *reinterpret_cast<const float4*>(brow + i);
            float s0 = srow[i + 0] + bb.x; if (maskS[myhalf + i + 0] <= 0.f) s0 = -1e9f;
            float s1 = srow[i + 1] + bb.y; if (maskS[myhalf + i + 1] <= 0.f) s1 = -1e9f;
            float s2 = srow[i + 2] + bb.z; if (maskS[myhalf + i + 2] <= 0.f) s2 = -1e9f;
            float s3 = srow[i + 3] + bb.w; if (maskS[myhalf + i + 3] <= 0.f) s3 = -1e9f;
            float p0 = __expf(s0 - m_final);
            float p1 = __expf(s1 - m_final);
            float p2 = __expf(s2 - m_final);
            float p3 = __expf(s3 - m_final);
            myl += (p0 + p1) + (p2 + p3);
            srow[i + 0] = to_tf32(p0);
            srow[i + 1] = to_tf32(p1);
            srow[i + 2] = to_tf32(p2);
            srow[i + 3] = to_tf32(p3);
        }
        __syncthreads();

#pragma unroll
        for (int k8 = 0; k8 < 64; k8 += 8) {
            wmma::fragment<wmma::matrix_a, 16, 16, 8, wmma::precision::tf32, wmma::row_major> af;
            wmma::load_matrix_sync(af, &Ss[wid * 16][k8], 68);
#pragma unroll
            for (int ni = 0; ni < 2; ni++) {
                wmma::fragment<wmma::matrix_b, 16, 16, 8, wmma::precision::tf32, wmma::row_major> bf;
                wmma::load_matrix_sync(bf, &Vs[k8][ni * 16], 36);
                wmma::mma_sync(ofr[ni], af, bf, ofr[ni]);
            }
        }
        __syncthreads();
    }

    rowl[myrow][t & 1] = myl;
    wmma::store_matrix_sync(&Ss[wid * 16][0], ofr[0], 68, wmma::mem_row_major);
    wmma::store_matrix_sync(&Ss[wid * 16][16], ofr[1], 68, wmma::mem_row_major);
    __syncthreads();
    float linv = 1.f / (rowl[myrow][0] + rowl[myrow][1]);
    int myq = (t & 1) * 16;
    float* op = g_ctx + (size_t)(bL + m0 + myrow) * Dc + h * DKc + myq;
#pragma unroll
    for (int i = 0; i < 16; i += 4) {
        float4 o;
        o.x = Ss[myrow][myq + i + 0] * linv;
        o.y = Ss[myrow][myq + i + 1] * linv;
        o.z = Ss[myrow][myq + i + 2] * linv;
        o.w = Ss[myrow][myq + i + 3] * linv;
        *reinterpret_cast<float4*>(op + i) = o;
    }
}

// ---------------- LN1: h_V_new = LN(h_V + ctx@Wo+bo) * mask ----------------
__global__ void ln1_kernel(const float* __restrict__ hV,
                           const float* __restrict__ gvec, const float* __restrict__ bvec,
                           const float* __restrict__ mask, float* __restrict__ out) {
    __shared__ float sh[8];
    int row = blockIdx.x, t = threadIdx.x;
    float x = hV[row * Dc + t] + g_tmp[row * Dc + t];
    float mean = blockSum(x, sh) * (1.f / Dc);
    float d = x - mean;
    float var = blockSum(d * d, sh) * (1.f / Dc);
    float y = d * rsqrtf(var + 1e-5f) * gvec[t] + bvec[t];
    out[row * Dc + t] = y * mask[row];
}

// ------- LN2 vectorized: h_E = LN(E + m1_raw + b13); 4 rows/block, float4 -------
__global__ void __launch_bounds__(256)
ln2v_kernel(const float* __restrict__ Ein,
            const float* __restrict__ b13,
            const float* __restrict__ gvec, const float* __restrict__ bvec,
            float* __restrict__ out) {
    __shared__ float s1[4][2], s2[4][2];
    int t = threadIdx.x;
    int rb = t >> 6;              // row in block 0..3
    int l6 = t & 63;              // lane within row
    int w2 = (t >> 5) & 1;        // warp-half within row
    size_t row = (size_t)blockIdx.x * 4 + rb;
    int c = l6 * 4;
    float4 e = *reinterpret_cast<const float4*>(Ein + row * Dc + c);
    float4 m = *reinterpret_cast<const float4*>(g_m1 + row * Dc + c);
    float4 bb = *reinterpret_cast<const float4*>(b13 + c);
    float x0 = e.x + m.x + bb.x;
    float x1 = e.y + m.y + bb.y;
    float x2 = e.z + m.z + bb.z;
    float x3 = e.w + m.w + bb.w;
    float sum = (x0 + x1) + (x2 + x3);
    float sq = x0 * x0 + x1 * x1 + x2 * x2 + x3 * x3;
#pragma unroll
    for (int o = 16; o; o >>= 1) {
        sum += __shfl_down_sync(0xffffffffu, sum, o);
        sq  += __shfl_down_sync(0xffffffffu, sq, o);
    }
    if ((t & 31) == 0) { s1[rb][w2] = sum; s2[rb][w2] = sq; }
    __syncthreads();
    float tot = s1[rb][0] + s1[rb][1];
    float tsq = s2[rb][0] + s2[rb][1];
    float mean = tot * (1.f / Dc);
    float var = tsq * (1.f / Dc) - mean * mean;
    float inv = rsqrtf(var + 1e-5f);
    float4 g4 = *reinterpret_cast<const float4*>(gvec + c);
    float4 b4 = *reinterpret_cast<const float4*>(bvec + c);
    float4 o;
    o.x = (x0 - mean) * inv * g4.x + b4.x;
    o.y = (x1 - mean) * inv * g4.y + b4.y;
    o.z = (x2 - mean) * inv * g4.z + b4.z;
    o.w = (x3 - mean) * inv * g4.w + b4.w;
    *reinterpret_cast<float4*>(out + row * Dc + c) = o;
}

// ---------------- host launch ----------------
extern "C" void kernel_launch(void* const* d_in, const int* in_sizes, int n_in,
                              void* d_out, int out_size) {
    const float* h_V    = (const float*)d_in[0];
    const float* E      = (const float*)d_in[1];
    const int*   E_idx  = (const int*)  d_in[2];
    const float* mask   = (const float*)d_in[3];
    const float* nonE   = (const float*)d_in[4];
    const float* bias_W = (const float*)d_in[5];
    const float* bias_b = (const float*)d_in[6];
    const float* Wq = (const float*)d_in[7];  const float* bq = (const float*)d_in[8];
    const float* Wk = (const float*)d_in[9];  const float* bk = (const float*)d_in[10];
    const float* Wv = (const float*)d_in[11]; const float* bv = (const float*)d_in[12];
    const float* Wo = (const float*)d_in[13]; const float* bo = (const float*)d_in[14];
    const float* ln1g = (const float*)d_in[15]; const float* ln1b = (const float*)d_in[16];
    const float* W11 = (const float*)d_in[17]; const float* b11 = (const float*)d_in[18];
    const float* W12 = (const float*)d_in[19]; const float* b12 = (const float*)d_in[20];
    const float* W13 = (const float*)d_in[21]; const float* b13 = (const float*)d_in[22];
    const float* ln2g = (const float*)d_in[23]; const float* ln2b = (const float*)d_in[24];

    float* out_hV = (float*)d_out;
    float* out_hE = out_hV + M1c * Dc;

    float *p_q, *p_k, *p_v, *p_ctx, *p_tmp, *p_hvp, *p_hvw3, *p_m1, *p_m2;
    cudaGetSymbolAddress((void**)&p_q,    g_q);
    cudaGetSymbolAddress((void**)&p_k,    g_k);
    cudaGetSymbolAddress((void**)&p_v,    g_v);
    cudaGetSymbolAddress((void**)&p_ctx,  g_ctx);
    cudaGetSymbolAddress((void**)&p_tmp,  g_tmp);
    cudaGetSymbolAddress((void**)&p_hvp,  g_hvp);
    cudaGetSymbolAddress((void**)&p_hvw3, g_hvw3);
    cudaGetSymbolAddress((void**)&p_m1,   g_m1);
    cudaGetSymbolAddress((void**)&p_m2,   g_m2);

    // attention bias (launch 1, 2)
    bias_fillbase_kernel<<<(Bc * Lc * Lc) / 256, 256>>>(nonE, bias_W, bias_b);
    bias_scatter_kernel<<<(Bc * Lc) / 8, 256>>>(E, E_idx, bias_W, bias_b);

    // qkv (launches 3-5)
    dim3 gqkv(Dc / 64, M1c / 64);
    gemm64<<<gqkv, 256>>>(h_V, Wq, p_q, M1c, Dc, Dc, bq, 0);
    gemm64<<<gqkv, 256>>>(h_V, Wk, p_k, M1c, Dc, Dc, bk, 0);
    gemm64<<<gqkv, 256>>>(h_V, Wv, p_v, M1c, Dc, Dc, bv, 0);

    // fused flash attention -> g_ctx (launch 6 — profiled by ncu -s 5 -c 1)
    flash_kernel<<<dim3(Lc / 64, Bc * Hc), 128>>>(mask);

    // out proj + LN1 (writes h_V_new into d_out)
    gemm64<<<gqkv, 256>>>(p_ctx, Wo, p_tmp, M1c, Dc, Dc, bo, 0);
    ln1_kernel<<<M1c, 256>>>(h_V, ln1g, ln1b, mask, out_hV);

    // hvp = h_V_new @ W11[0:256] + b11 ; hvW3 = h_V_new @ W11[512:768]
    gemm64<<<gqkv, 256>>>(out_hV, W11, p_hvp, M1c, Dc, Dc, b11, 0);
    gemm64<<<gqkv, 256>>>(out_hV, W11 + (size_t)512 * Dc, p_hvw3, M1c, Dc, Dc, nullptr, 0);

    // MLP big GEMMs: layer1 is now a plain Kd=256 GEMM on E (gather hoisted to hvW3)
    dim3 gbig(Dc / 128, M2c / 128);
    gemm_tc<0><<<gbig, 256>>>(E, W11 + (size_t)256 * Dc, p_m1, M2c, Dc, Dc,
                              nullptr, nullptr, nullptr);                    // m1 = E @ W11mid (raw)
    gemm_tc<1><<<gbig, 256>>>(p_m1, W12, p_m2, M2c, Dc, Dc,
                              p_hvp, p_hvw3, E_idx);   // m2 = gelu(m1+hvp+hvW3[E_idx]) @ W12 (raw)
    gemm_tc<2><<<gbig, 256>>>(p_m2, W13, p_m1, M2c, Dc, Dc,
                              b12, nullptr, nullptr);  // m1 = gelu(m2+b12) @ W13 (raw)
    ln2v_kernel<<<M2c / 4, 256>>>(E, b13, ln2g, ln2b, out_hE);
}

// round 15
// speedup vs baseline: 1.3345x; 1.1294x over previous
#include <cuda_runtime.h>
#include <cstdint>
#include <math.h>
#include <mma.h>

using namespace nvcuda;

#define Bc 4
#define Lc 1024
#define Kc 30
#define Dc 256
#define Hc 8
#define DKc 32

#define M1c (Bc*Lc)          // 4096
#define M2c (Bc*Lc*Kc)       // 122880

#define NSTAGE 3

// ---------------- scratch (static device globals; no allocations) ----------------
__device__ float g_q[M1c*Dc];
__device__ float g_k[M1c*Dc];
__device__ float g_v[M1c*Dc];
__device__ float g_bias[Bc*Lc*Lc];              // 16 MB (fits in L2)
__device__ float g_ctx[M1c*Dc];
__device__ float g_tmp[M1c*Dc];
__device__ float g_hvp[M1c*Dc];                 // h_V_new @ W11[0:256] + b11
__device__ float g_hvw3[M1c*Dc];                // h_V_new @ W11[512:768]
__device__ float g_m1[M2c*Dc];                  // 126 MB
__device__ float g_m2[M2c*Dc];                  // 126 MB
__device__ float g_w1r[Dc*Dc];                  // rna(W11[256:512])
__device__ float g_w2r[Dc*Dc];                  // rna(W12)
__device__ float g_w3r[Dc*Dc];                  // rna(W13)

// ---------------- packed f32x2 helpers (for gemm64) ----------------
typedef unsigned long long u64;

__device__ __forceinline__ u64 pack2(float x, float y) {
    u64 r;
    asm("mov.b64 %0, {%1, %2};" : "=l"(r) : "f"(x), "f"(y));
    return r;
}
__device__ __forceinline__ void fma2(u64& d, u64 a, u64 b) {
    asm("fma.rn.f32x2 %0, %1, %2, %0;" : "+l"(d) : "l"(a), "l"(b));
}
__device__ __forceinline__ float2 unpack2(u64 v) {
    float2 f;
    asm("mov.b64 {%0, %1}, %2;" : "=f"(f.x), "=f"(f.y) : "l"(v));
    return f;
}
__device__ __forceinline__ float to_tf32(float x) {
    float y;
    asm("cvt.rna.tf32.f32 %0, %1;" : "=f"(y) : "f"(x));
    return y;
}

// ---------------- cp.async helpers ----------------
__device__ __forceinline__ void cp_async16(void* smem_dst, const void* gsrc) {
    uint32_t s = (uint32_t)__cvta_generic_to_shared(smem_dst);
    asm volatile("cp.async.cg.shared.global [%0], [%1], 16;" :: "r"(s), "l"(gsrc));
}
__device__ __forceinline__ void cp_commit() {
    asm volatile("cp.async.commit_group;");
}
template<int N>
__device__ __forceinline__ void cp_wait() {
    asm volatile("cp.async.wait_group %0;" :: "n"(N));
}

// ---------------- reduction helpers ----------------
__device__ __forceinline__ float blockSum(float v, float* sh) {
    int lane = threadIdx.x & 31, wid = threadIdx.x >> 5;
#pragma unroll
    for (int o = 16; o; o >>= 1) v += __shfl_down_sync(0xffffffffu, v, o);
    if (lane == 0) sh[wid] = v;
    __syncthreads();
    if (wid == 0) {
        float r = (lane < 8) ? sh[lane] : 0.f;
#pragma unroll
        for (int o = 4; o; o >>= 1) r += __shfl_down_sync(0xffffffffu, r, o);
        if (lane == 0) sh[0] = r;
    }
    __syncthreads();
    float out = sh[0];
    __syncthreads();
    return out;
}

__device__ __forceinline__ float gelu_exact(float x) {
    return 0.5f * x * (1.0f + erff(x * 0.70710678118654752f));
}

// -------- weight pre-rounding (RNA tf32) --------
__global__ void round_w_kernel(const float* __restrict__ W11,
                               const float* __restrict__ W12,
                               const float* __restrict__ W13) {
    int i = blockIdx.x * 256 + threadIdx.x;   // 0 .. 65535
    g_w1r[i] = to_tf32(W11[(size_t)256 * Dc + i]);
    g_w2r[i] = to_tf32(W12[i]);
    g_w3r[i] = to_tf32(W13[i]);
}

// -------- bias fill (computes base per-block, fills plane) --------
__global__ void bias_fillbase_kernel(const float* __restrict__ nonE,
                                     const float* __restrict__ bias_W,
                                     const float* __restrict__ bias_b) {
    __shared__ float sh[8];
    int t = threadIdx.x;
    float p = nonE[t] * bias_W[t];
    float s = blockSum(p, sh);
    g_bias[(size_t)blockIdx.x * 256 + t] = s + bias_b[0];
}

// one warp per (b,l); k loop serial on lane 0 => last write wins for duplicate idx
__global__ void bias_scatter_kernel(const float* __restrict__ E,
                                    const int* __restrict__ E_idx,
                                    const float* __restrict__ bias_W,
                                    const float* __restrict__ bias_b) {
    int w = (blockIdx.x * blockDim.x + threadIdx.x) >> 5;
    int lane = threadIdx.x & 31;
    if (w >= Bc * Lc) return;
    float bb = bias_b[0];
    for (int k = 0; k < Kc; k++) {
        const float* er = E + (w * Kc + k) * Dc;
        float p = 0.f;
#pragma unroll
        for (int c = lane; c < Dc; c += 32) p += er[c] * bias_W[c];
#pragma unroll
        for (int o = 16; o; o >>= 1) p += __shfl_down_sync(0xffffffffu, p, o);
        if (lane == 0) {
            int idx = E_idx[w * Kc + k];
            g_bias[w * Lc + idx] = p + bb;
        }
    }
}

// ---------------- 64x64 tiled fp32 GEMM with f32x2 (small M GEMMs) ----------------
__global__ void gemm64(const float* __restrict__ A, const float* __restrict__ Bm,
                       float* __restrict__ C, int M, int N, int Kd,
                       const float* __restrict__ bias, int act) {
    __shared__ float As[64][17];
    __shared__ float Bs[16][64];
    int t = threadIdx.x;
    int tx = t & 15, ty = t >> 4;
    int m0 = blockIdx.y * 64, n0 = blockIdx.x * 64;
    u64 acc[4][2] = {};
    for (int k0 = 0; k0 < Kd; k0 += 16) {
#pragma unroll
        for (int i = 0; i < 4; i++) {
            int e = t + i * 256; int r = e >> 4, c = e & 15;
            As[r][c] = A[(size_t)(m0 + r) * Kd + k0 + c];
        }
#pragma unroll
        for (int i = 0; i < 4; i++) {
            int e = t + i * 256; int kk = e >> 6, c = e & 63;
            Bs[kk][c] = Bm[(size_t)(k0 + kk) * N + n0 + c];
        }
        __syncthreads();
#pragma unroll
        for (int kk = 0; kk < 16; kk++) {
            ulonglong2 bb = *reinterpret_cast<const ulonglong2*>(&Bs[kk][tx * 4]);
#pragma unroll
            for (int i = 0; i < 4; i++) {
                float a = As[ty * 4 + i][kk];
                u64 aa = pack2(a, a);
                fma2(acc[i][0], aa, bb.x);
                fma2(acc[i][1], aa, bb.y);
            }
        }
        __syncthreads();
    }
#pragma unroll
    for (int i = 0; i < 4; i++) {
        int row = m0 + ty * 4 + i;
#pragma unroll
        for (int j = 0; j < 2; j++) {
            float2 v = unpack2(acc[i][j]);
            int col = n0 + tx * 4 + j * 2;
            float x0 = v.x + (bias ? bias[col] : 0.f);
            float x1 = v.y + (bias ? bias[col + 1] : 0.f);
            if (act == 1) { x0 = gelu_exact(x0); x1 = gelu_exact(x1); }
            C[(size_t)row * N + col] = x0;
            C[(size_t)row * N + col + 1] = x1;
        }
    }
}

// ====== cp.async-pipelined tensor-core tf32 128x128 GEMM, K=256, N=256 ======
// NO per-kstep transform (weights pre-rounded; A either HW-truncated (E) or
// already rna'd by producer epilogue). One sync per k-step.
// Epilogue (fused transform of the NEXT layer's input, applied to this GEMM's output):
//   EPI 0: C = acc                                   (raw; consumed by ln2v)
//   EPI 1: C = rna(gelu(acc + aux[row/Kc] + aux2[gather(E_idx)]))    (GEMM1)
//   EPI 2: C = rna(gelu(acc + aux[col]))                             (GEMM2)
template<int EPI>
__global__ void __launch_bounds__(256, 2)
gemm_tc(const float* __restrict__ A, const float* __restrict__ Bm,
        float* __restrict__ C,
        const float* __restrict__ aux, const float* __restrict__ aux2,
        const int* __restrict__ E_idx) {
    __shared__ float As[NSTAGE][128][20];
    __shared__ float Bs[NSTAGE][16][132];
    __shared__ float St[8][16][20];     // per-warp epilogue staging
    __shared__ int hvb[128];
    __shared__ int nbb[128];
    int t = threadIdx.x;
    int wid = t >> 5, lane = t & 31;
    int wm = wid & 3, wn = wid >> 2;
    int m0 = blockIdx.y * 128, n0 = blockIdx.x * 128;
    if (EPI == 1 && t < 128) {
        int r = m0 + t;
        hvb[t] = (r / Kc) * Dc;
        int b_ = r / (Lc * Kc);
        nbb[t] = (b_ * Lc + E_idx[r]) * Dc;
    }

    const float* Ablk = A + (size_t)m0 * Dc;
    const float* Bblk = Bm + n0;
    const int nk = Dc / 16;   // 16

    auto load_stage = [&](int s, int kt) {
        int k0 = kt * 16;
#pragma unroll
        for (int i = 0; i < 2; i++) {
            int f = t + i * 256;                   // 0..511
            int r = f >> 2, c4 = (f & 3) * 4;
            cp_async16(&As[s][r][c4], Ablk + (size_t)r * Dc + k0 + c4);
            int kk = f >> 5, c = (f & 31) * 4;
            cp_async16(&Bs[s][kk][c], Bblk + (size_t)(k0 + kk) * Dc + c);
        }
        cp_commit();
    };

    wmma::fragment<wmma::accumulator, 16, 16, 8, float> acc[2][4];
#pragma unroll
    for (int i = 0; i < 2; i++)
#pragma unroll
        for (int j = 0; j < 4; j++) wmma::fill_fragment(acc[i][j], 0.f);

    load_stage(0, 0);
    load_stage(1, 1);

    for (int kt = 0; kt < nk; kt++) {
        int s = kt % NSTAGE;
        cp_wait<NSTAGE - 2>();
        __syncthreads();
        if (kt + NSTAGE - 1 < nk)
            load_stage((kt + NSTAGE - 1) % NSTAGE, kt + NSTAGE - 1);
#pragma unroll
        for (int k8 = 0; k8 < 16; k8 += 8) {
            wmma::fragment<wmma::matrix_a, 16, 16, 8, wmma::precision::tf32, wmma::row_major> af[2];
            wmma::load_matrix_sync(af[0], &As[s][wm * 32][k8], 20);
            wmma::load_matrix_sync(af[1], &As[s][wm * 32 + 16][k8], 20);
#pragma unroll
            for (int ni = 0; ni < 4; ni++) {
                wmma::fragment<wmma::matrix_b, 16, 16, 8, wmma::precision::tf32, wmma::row_major> bf;
                wmma::load_matrix_sync(bf, &Bs[s][k8][wn * 64 + ni * 16], 132);
                wmma::mma_sync(acc[0][ni], af[0], bf, acc[0][ni]);
                wmma::mma_sync(acc[1][ni], af[1], bf, acc[1][ni]);
            }
        }
    }

    if (EPI == 0) {
        // raw store, no staging
#pragma unroll
        for (int mi = 0; mi < 2; mi++)
#pragma unroll
            for (int ni = 0; ni < 4; ni++) {
                float* cp = C + (size_t)(m0 + wm * 32 + mi * 16) * Dc + n0 + wn * 64 + ni * 16;
                wmma::store_matrix_sync(cp, acc[mi][ni], Dc, wmma::mem_row_major);
            }
    } else {
#pragma unroll
        for (int mi = 0; mi < 2; mi++)
#pragma unroll
            for (int ni = 0; ni < 4; ni++) {
                wmma::store_matrix_sync(&St[wid][0][0], acc[mi][ni], 20, wmma::mem_row_major);
                __syncwarp();
#pragma unroll
                for (int e = lane; e < 256; e += 32) {
                    int r = e >> 4, c = e & 15;
                    int lrow = wm * 32 + mi * 16 + r;      // 0..127 within tile
                    int grow = m0 + lrow;
                    int gcol = n0 + wn * 64 + ni * 16 + c;
                    float v = St[wid][r][c];
                    if (EPI == 1)
                        v = to_tf32(gelu_exact(v + aux[hvb[lrow] + gcol] + aux2[nbb[lrow] + gcol]));
                    else
                        v = to_tf32(gelu_exact(v + aux[gcol]));
                    C[(size_t)grow * Dc + gcol] = v;
                }
                __syncwarp();
            }
    }
}

// ================= fused flash attention (tf32 WMMA QK^T & PV, exact softmax) ========
// q/k/v include their biases (added by gemm64).
__global__ void __launch_bounds__(128)
flash_kernel(const float* __restrict__ mask) {
    __shared__ float Qs[64][36];
    __shared__ float Ks[64][36];
    __shared__ float Vs[64][36];
    __shared__ float Ss[64][68];
    __shared__ float rowm[64][2];
    __shared__ float rowl[64][2];
    __shared__ float maskS[64];

    int t = threadIdx.x;
    int wid = t >> 5;
    int m0 = blockIdx.x * 64;
    int bh = blockIdx.y; int b = bh >> 3, h = bh & 7;
    int bL = b * Lc;
    int myrow = t >> 1, myhalf = (t & 1) * 32;
    const float scale = 0.17677669529663687f;  // 1/sqrt(32)

    // load Q tile (pre-scaled, tf32)
#pragma unroll
    for (int f = t; f < 512; f += 128) {
        int r = f >> 3, c4 = (f & 7) * 4;
        float4 v = *reinterpret_cast<const float4*>(
            g_q + (size_t)(bL + m0 + r) * Dc + h * DKc + c4);
        Qs[r][c4 + 0] = to_tf32(v.x * scale);
        Qs[r][c4 + 1] = to_tf32(v.y * scale);
        Qs[r][c4 + 2] = to_tf32(v.z * scale);
        Qs[r][c4 + 3] = to_tf32(v.w * scale);
    }

    // ---------- pass A: row max ----------
    float mymax = -3.0e38f;
    for (int kt = 0; kt < 16; kt++) {
        int k0 = kt * 64;
#pragma unroll
        for (int f = t; f < 512; f += 128) {
            int r = f >> 3, c4 = (f & 7) * 4;
            float4 v = *reinterpret_cast<const float4*>(
                g_k + (size_t)(bL + k0 + r) * Dc + h * DKc + c4);
            Ks[r][c4 + 0] = to_tf32(v.x);
            Ks[r][c4 + 1] = to_tf32(v.y);
            Ks[r][c4 + 2] = to_tf32(v.z);
            Ks[r][c4 + 3] = to_tf32(v.w);
        }
        if (t < 64) maskS[t] = mask[bL + k0 + t];
        __syncthreads();

        wmma::fragment<wmma::accumulator, 16, 16, 8, float> sfr[4];
#pragma unroll
        for (int ni = 0; ni < 4; ni++) wmma::fill_fragment(sfr[ni], 0.f);
#pragma unroll
        for (int k8 = 0; k8 < 32; k8 += 8) {
            wmma::fragment<wmma::matrix_a, 16, 16, 8, wmma::precision::tf32, wmma::row_major> af;
            wmma::load_matrix_sync(af, &Qs[wid * 16][k8], 36);
#pragma unroll
            for (int ni = 0; ni < 4; ni++) {
                wmma::fragment<wmma::matrix_b, 16, 16, 8, wmma::precision::tf32, wmma::col_major> bf;
                wmma::load_matrix_sync(bf, &Ks[ni * 16][k8], 36);
                wmma::mma_sync(sfr[ni], af, bf, sfr[ni]);
            }
        }
#pragma unroll
        for (int ni = 0; ni < 4; ni++)
            wmma::store_matrix_sync(&Ss[wid * 16][ni * 16], sfr[ni], 68, wmma::mem_row_major);
        __syncthreads();

        const float* brow = g_bias + (size_t)(bL + m0 + myrow) * Lc + k0 + myhalf;
        const float* srow = &Ss[myrow][myhalf];
#pragma unroll
        for (int i = 0; i < 32; i += 4) {
            float4 bb = *reinterpret_cast<const float4*>(brow + i);
            float s0 = srow[i + 0] + bb.x; if (maskS[myhalf + i + 0] <= 0.f) s0 = -1e9f;
            float s1 = srow[i + 1] + bb.y; if (maskS[myhalf + i + 1] <= 0.f) s1 = -1e9f;
            float s2 = srow[i + 2] + bb.z; if (maskS[myhalf + i + 2] <= 0.f) s2 = -1e9f;
            float s3 = srow[i + 3] + bb.w; if (maskS[myhalf + i + 3] <= 0.f) s3 = -1e9f;
            mymax = fmaxf(mymax, fmaxf(fmaxf(s0, s1), fmaxf(s2, s3)));
        }
        __syncthreads();
    }
    rowm[myrow][t & 1] = mymax;
    __syncthreads();
    float m_final = fmaxf(rowm[myrow][0], rowm[myrow][1]);

    // ---------- pass B: exp + sum + PV ----------
    float myl = 0.f;
    wmma::fragment<wmma::accumulator, 16, 16, 8, float> ofr[2];
    wmma::fill_fragment(ofr[0], 0.f);
    wmma::fill_fragment(ofr[1], 0.f);

    for (int kt = 0; kt < 16; kt++) {
        int k0 = kt * 64;
#pragma unroll
        for (int f = t; f < 1024; f += 128) {
            int r = (f >> 3) & 63, c4 = (f & 7) * 4;
            const float* src = (f < 512) ? g_k : g_v;
            float4 v = *reinterpret_cast<const float4*>(
                src + (size_t)(bL + k0 + r) * Dc + h * DKc + c4);
            float* dst = (f < 512) ? &Ks[r][c4] : &Vs[r][c4];
            dst[0] = to_tf32(v.x);
            dst[1] = to_tf32(v.y);
            dst[2] = to_tf32(v.z);
            dst[3] = to_tf32(v.w);
        }
        if (t < 64) maskS[t] = mask[bL + k0 + t];
        __syncthreads();

        wmma::fragment<wmma::accumulator, 16, 16, 8, float> sfr[4];
#pragma unroll
        for (int ni = 0; ni < 4; ni++) wmma::fill_fragment(sfr[ni], 0.f);
#pragma unroll
        for (int k8 = 0; k8 < 32; k8 += 8) {
            wmma::fragment<wmma::matrix_a, 16, 16, 8, wmma::precision::tf32, wmma::row_major> af;
            wmma::load_matrix_sync(af, &Qs[wid * 16][k8], 36);
#pragma unroll
            for (int ni = 0; ni < 4; ni++) {
                wmma::fragment<wmma::matrix_b, 16, 16, 8, wmma::precision::tf32, wmma::col_major> bf;
                wmma::load_matrix_sync(bf, &Ks[ni * 16][k8], 36);
                wmma::mma_sync(sfr[ni], af, bf, sfr[ni]);
            }
        }
#pragma unroll
        for (int ni = 0; ni < 4; ni++)
            wmma::store_matrix_sync(&Ss[wid * 16][ni * 16], sfr[ni], 68, wmma::mem_row_major);
        __syncthreads();

        const float* brow = g_bias + (size_t)(bL + m0 + myrow) * Lc + k0 + myhalf;
        float* srow = &Ss[myrow][myhalf];
#pragma unroll
        for (int i = 0; i < 32; i += 4) {
            float4 bb = *reinterpret_cast<const float4*>(brow + i);
            float s0 = srow[i + 0] + bb.x; if (maskS[myhalf + i + 0] <= 0.f) s0 = -1e9f;
            float s1 = srow[i + 1] + bb.y; if (maskS[myhalf + i + 1] <= 0.f) s1 = -1e9f;
            float s2 = srow[i + 2] + bb.z; if (maskS[myhalf + i + 2] <= 0.f) s2 = -1e9f;
            float s3 = srow[i + 3] + bb.w; if (maskS[myhalf + i + 3] <= 0.f) s3 = -1e9f;
            float p0 = __expf(s0 - m_final);
            float p1 = __expf(s1 - m_final);
            float p2 = __expf(s2 - m_final);
            float p3 = __expf(s3 - m_final);
            myl += (p0 + p1) + (p2 + p3);
            srow[i + 0] = to_tf32(p0);
            srow[i + 1] = to_tf32(p1);
            srow[i + 2] = to_tf32(p2);
            srow[i + 3] = to_tf32(p3);
        }
        __syncthreads();

#pragma unroll
        for (int k8 = 0; k8 < 64; k8 += 8) {
            wmma::fragment<wmma::matrix_a, 16, 16, 8, wmma::precision::tf32, wmma::row_major> af;
            wmma::load_matrix_sync(af, &Ss[wid * 16][k8], 68);
#pragma unroll
            for (int ni = 0; ni < 2; ni++) {
                wmma::fragment<wmma::matrix_b, 16, 16, 8, wmma::precision::tf32, wmma::row_major> bf;
                wmma::load_matrix_sync(bf, &Vs[k8][ni * 16], 36);
                wmma::mma_sync(ofr[ni], af, bf, ofr[ni]);
            }
        }
        __syncthreads();
    }

    rowl[myrow][t & 1] = myl;
    wmma::store_matrix_sync(&Ss[wid * 16][0], ofr[0], 68, wmma::mem_row_major);
    wmma::store_matrix_sync(&Ss[wid * 16][16], ofr[1], 68, wmma::mem_row_major);
    __syncthreads();
    float linv = 1.f / (rowl[myrow][0] + rowl[myrow][1]);
    int myq = (t & 1) * 16;
    float* op = g_ctx + (size_t)(bL + m0 + myrow) * Dc + h * DKc + myq;
#pragma unroll
    for (int i = 0; i < 16; i += 4) {
        float4 o;
        o.x = Ss[myrow][myq + i + 0] * linv;
        o.y = Ss[myrow][myq + i + 1] * linv;
        o.z = Ss[myrow][myq + i + 2] * linv;
        o.w = Ss[myrow][myq + i + 3] * linv;
        *reinterpret_cast<float4*>(op + i) = o;
    }
}

// ---------------- LN1: h_V_new = LN(h_V + ctx@Wo+bo) * mask ----------------
__global__ void ln1_kernel(const float* __restrict__ hV,
                           const float* __restrict__ gvec, const float* __restrict__ bvec,
                           const float* __restrict__ mask, float* __restrict__ out) {
    __shared__ float sh[8];
    int row = blockIdx.x, t = threadIdx.x;
    float x = hV[row * Dc + t] + g_tmp[row * Dc + t];
    float mean = blockSum(x, sh) * (1.f / Dc);
    float d = x - mean;
    float var = blockSum(d * d, sh) * (1.f / Dc);
    float y = d * rsqrtf(var + 1e-5f) * gvec[t] + bvec[t];
    out[row * Dc + t] = y * mask[row];
}

// ------- LN2 vectorized: h_E = LN(E + m1_raw + b13); 4 rows/block, float4 -------
__global__ void __launch_bounds__(256)
ln2v_kernel(const float* __restrict__ Ein,
            const float* __restrict__ b13,
            const float* __restrict__ gvec, const float* __restrict__ bvec,
            float* __restrict__ out) {
    __shared__ float s1[4][2], s2[4][2];
    int t = threadIdx.x;
    int rb = t >> 6;              // row in block 0..3
    int l6 = t & 63;              // lane within row
    int w2 = (t >> 5) & 1;        // warp-half within row
    size_t row = (size_t)blockIdx.x * 4 + rb;
    int c = l6 * 4;
    float4 e = *reinterpret_cast<const float4*>(Ein + row * Dc + c);
    float4 m = *reinterpret_cast<const float4*>(g_m1 + row * Dc + c);
    float4 bb = *reinterpret_cast<const float4*>(b13 + c);
    float x0 = e.x + m.x + bb.x;
    float x1 = e.y + m.y + bb.y;
    float x2 = e.z + m.z + bb.z;
    float x3 = e.w + m.w + bb.w;
    float sum = (x0 + x1) + (x2 + x3);
    float sq = x0 * x0 + x1 * x1 + x2 * x2 + x3 * x3;
#pragma unroll
    for (int o = 16; o; o >>= 1) {
        sum += __shfl_down_sync(0xffffffffu, sum, o);
        sq  += __shfl_down_sync(0xffffffffu, sq, o);
    }
    if ((t & 31) == 0) { s1[rb][w2] = sum; s2[rb][w2] = sq; }
    __syncthreads();
    float tot = s1[rb][0] + s1[rb][1];
    float tsq = s2[rb][0] + s2[rb][1];
    float mean = tot * (1.f / Dc);
    float var = tsq * (1.f / Dc) - mean * mean;
    float inv = rsqrtf(var + 1e-5f);
    float4 g4 = *reinterpret_cast<const float4*>(gvec + c);
    float4 b4 = *reinterpret_cast<const float4*>(bvec + c);
    float4 o;
    o.x = (x0 - mean) * inv * g4.x + b4.x;
    o.y = (x1 - mean) * inv * g4.y + b4.y;
    o.z = (x2 - mean) * inv * g4.z + b4.z;
    o.w = (x3 - mean) * inv * g4.w + b4.w;
    *reinterpret_cast<float4*>(out + row * Dc + c) = o;
}

// ---------------- host launch ----------------
extern "C" void kernel_launch(void* const* d_in, const int* in_sizes, int n_in,
                              void* d_out, int out_size) {
    const float* h_V    = (const float*)d_in[0];
    const float* E      = (const float*)d_in[1];
    const int*   E_idx  = (const int*)  d_in[2];
    const float* mask   = (const float*)d_in[3];
    const float* nonE   = (const float*)d_in[4];
    const float* bias_W = (const float*)d_in[5];
    const float* bias_b = (const float*)d_in[6];
    const float* Wq = (const float*)d_in[7];  const float* bq = (const float*)d_in[8];
    const float* Wk = (const float*)d_in[9];  const float* bk = (const float*)d_in[10];
    const float* Wv = (const float*)d_in[11]; const float* bv = (const float*)d_in[12];
    const float* Wo = (const float*)d_in[13]; const float* bo = (const float*)d_in[14];
    const float* ln1g = (const float*)d_in[15]; const float* ln1b = (const float*)d_in[16];
    const float* W11 = (const float*)d_in[17]; const float* b11 = (const float*)d_in[18];
    const float* W12 = (const float*)d_in[19]; const float* b12 = (const float*)d_in[20];
    const float* W13 = (const float*)d_in[21]; const float* b13 = (const float*)d_in[22];
    const float* ln2g = (const float*)d_in[23]; const float* ln2b = (const float*)d_in[24];

    float* out_hV = (float*)d_out;
    float* out_hE = out_hV + M1c * Dc;

    float *p_q, *p_k, *p_v, *p_ctx, *p_tmp, *p_hvp, *p_hvw3, *p_m1, *p_m2;
    float *p_w1r, *p_w2r, *p_w3r;
    cudaGetSymbolAddress((void**)&p_q,    g_q);
    cudaGetSymbolAddress((void**)&p_k,    g_k);
    cudaGetSymbolAddress((void**)&p_v,    g_v);
    cudaGetSymbolAddress((void**)&p_ctx,  g_ctx);
    cudaGetSymbolAddress((void**)&p_tmp,  g_tmp);
    cudaGetSymbolAddress((void**)&p_hvp,  g_hvp);
    cudaGetSymbolAddress((void**)&p_hvw3, g_hvw3);
    cudaGetSymbolAddress((void**)&p_m1,   g_m1);
    cudaGetSymbolAddress((void**)&p_m2,   g_m2);
    cudaGetSymbolAddress((void**)&p_w1r,  g_w1r);
    cudaGetSymbolAddress((void**)&p_w2r,  g_w2r);
    cudaGetSymbolAddress((void**)&p_w3r,  g_w3r);

    // weight pre-rounding + attention bias
    round_w_kernel<<<256, 256>>>(W11, W12, W13);
    bias_fillbase_kernel<<<(Bc * Lc * Lc) / 256, 256>>>(nonE, bias_W, bias_b);
    bias_scatter_kernel<<<(Bc * Lc) / 8, 256>>>(E, E_idx, bias_W, bias_b);

    // qkv
    dim3 gqkv(Dc / 64, M1c / 64);
    gemm64<<<gqkv, 256>>>(h_V, Wq, p_q, M1c, Dc, Dc, bq, 0);
    gemm64<<<gqkv, 256>>>(h_V, Wk, p_k, M1c, Dc, Dc, bk, 0);
    gemm64<<<gqkv, 256>>>(h_V, Wv, p_v, M1c, Dc, Dc, bv, 0);

    // fused flash attention -> g_ctx
    flash_kernel<<<dim3(Lc / 64, Bc * Hc), 128>>>(mask);

    // out proj + LN1 (writes h_V_new into d_out)
    gemm64<<<gqkv, 256>>>(p_ctx, Wo, p_tmp, M1c, Dc, Dc, bo, 0);
    ln1_kernel<<<M1c, 256>>>(h_V, ln1g, ln1b, mask, out_hV);

    // hvp = h_V_new @ W11[0:256] + b11 ; hvW3 = h_V_new @ W11[512:768]
    gemm64<<<gqkv, 256>>>(out_hV, W11, p_hvp, M1c, Dc, Dc, b11, 0);
    gemm64<<<gqkv, 256>>>(out_hV, W11 + (size_t)512 * Dc, p_hvw3, M1c, Dc, Dc, nullptr, 0);

    // MLP big GEMMs (producer-side fused epilogues; no in-loop transforms)
    dim3 gbig(Dc / 128, M2c / 128);
    gemm_tc<1><<<gbig, 256>>>(E, p_w1r, p_m1, p_hvp, p_hvw3, E_idx);   // m1 = rna(gelu(E@W11mid + hvp + hvW3[nb]))
    gemm_tc<2><<<gbig, 256>>>(p_m1, p_w2r, p_m2, b12, nullptr, nullptr); // m2 = rna(gelu(m1@W12 + b12))
    gemm_tc<0><<<gbig, 256>>>(p_m2, p_w3r, p_m1, nullptr, nullptr, nullptr); // m1 = m2@W13 (raw)
    ln2v_kernel<<<M2c / 4, 256>>>(E, b13, ln2g, ln2b, out_hE);
}

// round 16
// speedup vs baseline: 1.3571x; 1.0169x over previous
#include <cuda_runtime.h>
#include <cstdint>
#include <math.h>
#include <mma.h>

using namespace nvcuda;

#define Bc 4
#define Lc 1024
#define Kc 30
#define Dc 256
#define Hc 8
#define DKc 32

#define M1c (Bc*Lc)          // 4096
#define M2c (Bc*Lc*Kc)       // 122880

#define NSTAGE 3

// ---------------- scratch (static device globals; no allocations) ----------------
__device__ float g_qkv[M1c*768];                // fused q|k|v projections
__device__ float g_bias[Bc*Lc*Lc];              // 16 MB (fits in L2)
__device__ float g_ctx[M1c*Dc];
__device__ float g_tmp[M1c*Dc];
__device__ float g_hvpair[M1c*512];             // [hvp+b11 | hvW3] per row
__device__ float g_m1[M2c*Dc];                  // 126 MB
__device__ float g_m2[M2c*Dc];                  // 126 MB
__device__ float g_w1r[Dc*Dc];                  // rna(W11[256:512])
__device__ float g_w2r[Dc*Dc];                  // rna(W12)
__device__ float g_w3r[Dc*Dc];                  // rna(W13)
__device__ float g_wqkv[Dc*768];                // Wq|Wk|Wv packed
__device__ float g_bqkv[768];                   // bq|bk|bv packed
__device__ float g_w11p[Dc*512];                // W11[0:256]|W11[512:768] packed
__device__ float g_b11p[512];                   // b11|0

// ---------------- packed f32x2 helpers (for gemm64) ----------------
typedef unsigned long long u64;

__device__ __forceinline__ u64 pack2(float x, float y) {
    u64 r;
    asm("mov.b64 %0, {%1, %2};" : "=l"(r) : "f"(x), "f"(y));
    return r;
}
__device__ __forceinline__ void fma2(u64& d, u64 a, u64 b) {
    asm("fma.rn.f32x2 %0, %1, %2, %0;" : "+l"(d) : "l"(a), "l"(b));
}
__device__ __forceinline__ float2 unpack2(u64 v) {
    float2 f;
    asm("mov.b64 {%0, %1}, %2;" : "=f"(f.x), "=f"(f.y) : "l"(v));
    return f;
}
__device__ __forceinline__ float to_tf32(float x) {
    float y;
    asm("cvt.rna.tf32.f32 %0, %1;" : "=f"(y) : "f"(x));
    return y;
}

// ---------------- cp.async helpers ----------------
__device__ __forceinline__ void cp_async16(void* smem_dst, const void* gsrc) {
    uint32_t s = (uint32_t)__cvta_generic_to_shared(smem_dst);
    asm volatile("cp.async.cg.shared.global [%0], [%1], 16;" :: "r"(s), "l"(gsrc));
}
__device__ __forceinline__ void cp_commit() {
    asm volatile("cp.async.commit_group;");
}
template<int N>
__device__ __forceinline__ void cp_wait() {
    asm volatile("cp.async.wait_group %0;" :: "n"(N));
}

// ---------------- reduction helpers ----------------
__device__ __forceinline__ float blockSum(float v, float* sh) {
    int lane = threadIdx.x & 31, wid = threadIdx.x >> 5;
#pragma unroll
    for (int o = 16; o; o >>= 1) v += __shfl_down_sync(0xffffffffu, v, o);
    if (lane == 0) sh[wid] = v;
    __syncthreads();
    if (wid == 0) {
        float r = (lane < 8) ? sh[lane] : 0.f;
#pragma unroll
        for (int o = 4; o; o >>= 1) r += __shfl_down_sync(0xffffffffu, r, o);
        if (lane == 0) sh[0] = r;
    }
    __syncthreads();
    float out = sh[0];
    __syncthreads();
    return out;
}

__device__ __forceinline__ float gelu_exact(float x) {
    return 0.5f * x * (1.0f + erff(x * 0.70710678118654752f));
}

// -------- weight packing: Wq|Wk|Wv, W11lo|W11hi, biases --------
__global__ void wpack_kernel(const float* __restrict__ Wq, const float* __restrict__ Wk,
                             const float* __restrict__ Wv,
                             const float* __restrict__ bq, const float* __restrict__ bk,
                             const float* __restrict__ bv,
                             const float* __restrict__ W11, const float* __restrict__ b11) {
    int bid = blockIdx.x, t = threadIdx.x;
    if (bid < 768) {
        int i = bid * 256 + t;
        int k = i / 768, c = i % 768;
        float v;
        if (c < 256)      v = Wq[k * 256 + c];
        else if (c < 512) v = Wk[k * 256 + c - 256];
        else              v = Wv[k * 256 + c - 512];
        g_wqkv[i] = v;
    } else if (bid < 1280) {
        int i = (bid - 768) * 256 + t;
        int k = i / 512, c = i % 512;
        g_w11p[i] = (c < 256) ? W11[(size_t)k * 256 + c]
                              : W11[(size_t)(512 + k) * 256 + (c - 256)];
    } else {
        g_bqkv[t]       = bq[t];
        g_bqkv[256 + t] = bk[t];
        g_bqkv[512 + t] = bv[t];
        g_b11p[t]       = b11[t];
        g_b11p[256 + t] = 0.f;
    }
}

// -------- weight pre-rounding (RNA tf32) --------
__global__ void round_w_kernel(const float* __restrict__ W11,
                               const float* __restrict__ W12,
                               const float* __restrict__ W13) {
    int i = blockIdx.x * 256 + threadIdx.x;   // 0 .. 65535
    g_w1r[i] = to_tf32(W11[(size_t)256 * Dc + i]);
    g_w2r[i] = to_tf32(W12[i]);
    g_w3r[i] = to_tf32(W13[i]);
}

// -------- bias fill (computes base per-block, fills plane) --------
__global__ void bias_fillbase_kernel(const float* __restrict__ nonE,
                                     const float* __restrict__ bias_W,
                                     const float* __restrict__ bias_b) {
    __shared__ float sh[8];
    int t = threadIdx.x;
    float p = nonE[t] * bias_W[t];
    float s = blockSum(p, sh);
    g_bias[(size_t)blockIdx.x * 256 + t] = s + bias_b[0];
}

// one warp per (b,l); k loop serial on lane 0 => last write wins for duplicate idx
__global__ void bias_scatter_kernel(const float* __restrict__ E,
                                    const int* __restrict__ E_idx,
                                    const float* __restrict__ bias_W,
                                    const float* __restrict__ bias_b) {
    int w = (blockIdx.x * blockDim.x + threadIdx.x) >> 5;
    int lane = threadIdx.x & 31;
    if (w >= Bc * Lc) return;
    float bb = bias_b[0];
    for (int k = 0; k < Kc; k++) {
        const float* er = E + (w * Kc + k) * Dc;
        float p = 0.f;
#pragma unroll
        for (int c = lane; c < Dc; c += 32) p += er[c] * bias_W[c];
#pragma unroll
        for (int o = 16; o; o >>= 1) p += __shfl_down_sync(0xffffffffu, p, o);
        if (lane == 0) {
            int idx = E_idx[w * Kc + k];
            g_bias[w * Lc + idx] = p + bb;
        }
    }
}

// ---------------- 64x64 tiled fp32 GEMM with f32x2 (small M GEMMs) ----------------
__global__ void gemm64(const float* __restrict__ A, const float* __restrict__ Bm,
                       float* __restrict__ C, int M, int N, int Kd,
                       const float* __restrict__ bias, int act) {
    __shared__ float As[64][17];
    __shared__ float Bs[16][64];
    int t = threadIdx.x;
    int tx = t & 15, ty = t >> 4;
    int m0 = blockIdx.y * 64, n0 = blockIdx.x * 64;
    u64 acc[4][2] = {};
    for (int k0 = 0; k0 < Kd; k0 += 16) {
#pragma unroll
        for (int i = 0; i < 4; i++) {
            int e = t + i * 256; int r = e >> 4, c = e & 15;
            As[r][c] = A[(size_t)(m0 + r) * Kd + k0 + c];
        }
#pragma unroll
        for (int i = 0; i < 4; i++) {
            int e = t + i * 256; int kk = e >> 6, c = e & 63;
            Bs[kk][c] = Bm[(size_t)(k0 + kk) * N + n0 + c];
        }
        __syncthreads();
#pragma unroll
        for (int kk = 0; kk < 16; kk++) {
            ulonglong2 bb = *reinterpret_cast<const ulonglong2*>(&Bs[kk][tx * 4]);
#pragma unroll
            for (int i = 0; i < 4; i++) {
                float a = As[ty * 4 + i][kk];
                u64 aa = pack2(a, a);
                fma2(acc[i][0], aa, bb.x);
                fma2(acc[i][1], aa, bb.y);
            }
        }
        __syncthreads();
    }
#pragma unroll
    for (int i = 0; i < 4; i++) {
        int row = m0 + ty * 4 + i;
#pragma unroll
        for (int j = 0; j < 2; j++) {
            float2 v = unpack2(acc[i][j]);
            int col = n0 + tx * 4 + j * 2;
            float x0 = v.x + (bias ? bias[col] : 0.f);
            float x1 = v.y + (bias ? bias[col + 1] : 0.f);
            if (act == 1) { x0 = gelu_exact(x0); x1 = gelu_exact(x1); }
            C[(size_t)row * N + col] = x0;
            C[(size_t)row * N + col + 1] = x1;
        }
    }
}

// ====== cp.async-pipelined tensor-core tf32 128x128 GEMM, K=256, N=256 ======
// Weights pre-rounded; A either HW-truncated (E) or producer-rounded.
// EPI 0: C = acc                                   (raw; consumed by ln2v)
// EPI 1: C = rna(gelu(acc + aux[hvb] + aux[nbb]))  (hvpair: hvp + gathered hvW3)
// EPI 2: C = rna(gelu(acc + aux[col]))             (b12)
template<int EPI>
__global__ void __launch_bounds__(256, 2)
gemm_tc(const float* __restrict__ A, const float* __restrict__ Bm,
        float* __restrict__ C,
        const float* __restrict__ aux,
        const int* __restrict__ E_idx) {
    __shared__ float As[NSTAGE][128][20];
    __shared__ float Bs[NSTAGE][16][132];
    __shared__ int hvb[128];
    __shared__ int nbb[128];
    int t = threadIdx.x;
    int wid = t >> 5, lane = t & 31;
    int wm = wid & 3, wn = wid >> 2;
    int m0 = blockIdx.y * 128, n0 = blockIdx.x * 128;
    if (EPI == 1 && t < 128) {
        int r = m0 + t;
        hvb[t] = (r / Kc) * 512;                     // hvp columns 0-255 of hvpair
        int b_ = r / (Lc * Kc);
        nbb[t] = (b_ * Lc + E_idx[r]) * 512 + 256;   // hvW3 columns 256-511
    }

    const float* Ablk = A + (size_t)m0 * Dc;
    const float* Bblk = Bm + n0;
    const int nk = Dc / 16;   // 16

    auto load_stage = [&](int s, int kt) {
        int k0 = kt * 16;
#pragma unroll
        for (int i = 0; i < 2; i++) {
            int f = t + i * 256;                   // 0..511
            int r = f >> 2, c4 = (f & 3) * 4;
            cp_async16(&As[s][r][c4], Ablk + (size_t)r * Dc + k0 + c4);
            int kk = f >> 5, c = (f & 31) * 4;
            cp_async16(&Bs[s][kk][c], Bblk + (size_t)(k0 + kk) * Dc + c);
        }
        cp_commit();
    };

    wmma::fragment<wmma::accumulator, 16, 16, 8, float> acc[2][4];
#pragma unroll
    for (int i = 0; i < 2; i++)
#pragma unroll
        for (int j = 0; j < 4; j++) wmma::fill_fragment(acc[i][j], 0.f);

    load_stage(0, 0);
    load_stage(1, 1);

    for (int kt = 0; kt < nk; kt++) {
        int s = kt % NSTAGE;
        cp_wait<NSTAGE - 2>();
        __syncthreads();
        if (kt + NSTAGE - 1 < nk)
            load_stage((kt + NSTAGE - 1) % NSTAGE, kt + NSTAGE - 1);
#pragma unroll
        for (int k8 = 0; k8 < 16; k8 += 8) {
            wmma::fragment<wmma::matrix_a, 16, 16, 8, wmma::precision::tf32, wmma::row_major> af[2];
            wmma::load_matrix_sync(af[0], &As[s][wm * 32][k8], 20);
            wmma::load_matrix_sync(af[1], &As[s][wm * 32 + 16][k8], 20);
#pragma unroll
            for (int ni = 0; ni < 4; ni++) {
                wmma::fragment<wmma::matrix_b, 16, 16, 8, wmma::precision::tf32, wmma::row_major> bf;
                wmma::load_matrix_sync(bf, &Bs[s][k8][wn * 64 + ni * 16], 132);
                wmma::mma_sync(acc[0][ni], af[0], bf, acc[0][ni]);
                wmma::mma_sync(acc[1][ni], af[1], bf, acc[1][ni]);
            }
        }
    }

    if (EPI == 0) {
#pragma unroll
        for (int mi = 0; mi < 2; mi++)
#pragma unroll
            for (int ni = 0; ni < 4; ni++) {
                float* cp = C + (size_t)(m0 + wm * 32 + mi * 16) * Dc + n0 + wn * 64 + ni * 16;
                wmma::store_matrix_sync(cp, acc[mi][ni], Dc, wmma::mem_row_major);
            }
    } else {
        // stage through (now dead) As[0] memory: per-warp 16x20 region
        __syncthreads();
        float* St = &As[0][0][0] + wid * 320;   // [16][20]
#pragma unroll
        for (int mi = 0; mi < 2; mi++)
#pragma unroll
            for (int ni = 0; ni < 4; ni++) {
                wmma::store_matrix_sync(St, acc[mi][ni], 20, wmma::mem_row_major);
                __syncwarp();
#pragma unroll
                for (int e = lane; e < 256; e += 32) {
                    int r = e >> 4, c = e & 15;
                    int lrow = wm * 32 + mi * 16 + r;      // 0..127 within tile
                    int grow = m0 + lrow;
                    int gcol = n0 + wn * 64 + ni * 16 + c;
                    float v = St[r * 20 + c];
                    if (EPI == 1)
                        v = to_tf32(gelu_exact(v + aux[hvb[lrow] + gcol] + aux[nbb[lrow] + gcol]));
                    else
                        v = to_tf32(gelu_exact(v + aux[gcol]));
                    C[(size_t)grow * Dc + gcol] = v;
                }
                __syncwarp();
            }
    }
}

// ================= fused flash attention (tf32 WMMA QK^T & PV, exact softmax) ========
// q/k/v read from fused g_qkv[row][768] (biases already added by gemm64).
__global__ void __launch_bounds__(128)
flash_kernel(const float* __restrict__ mask) {
    __shared__ float Qs[64][36];
    __shared__ float Ks[64][36];
    __shared__ float Vs[64][36];
    __shared__ float Ss[64][68];
    __shared__ float rowm[64][2];
    __shared__ float rowl[64][2];
    __shared__ float maskS[64];

    int t = threadIdx.x;
    int wid = t >> 5;
    int m0 = blockIdx.x * 64;
    int bh = blockIdx.y; int b = bh >> 3, h = bh & 7;
    int bL = b * Lc;
    int myrow = t >> 1, myhalf = (t & 1) * 32;
    const float scale = 0.17677669529663687f;  // 1/sqrt(32)

    // load Q tile (pre-scaled, tf32)
#pragma unroll
    for (int f = t; f < 512; f += 128) {
        int r = f >> 3, c4 = (f & 7) * 4;
        float4 v = *reinterpret_cast<const float4*>(
            g_qkv + (size_t)(bL + m0 + r) * 768 + h * DKc + c4);
        Qs[r][c4 + 0] = to_tf32(v.x * scale);
        Qs[r][c4 + 1] = to_tf32(v.y * scale);
        Qs[r][c4 + 2] = to_tf32(v.z * scale);
        Qs[r][c4 + 3] = to_tf32(v.w * scale);
    }

    // ---------- pass A: row max ----------
    float mymax = -3.0e38f;
    for (int kt = 0; kt < 16; kt++) {
        int k0 = kt * 64;
#pragma unroll
        for (int f = t; f < 512; f += 128) {
            int r = f >> 3, c4 = (f & 7) * 4;
            float4 v = *reinterpret_cast<const float4*>(
                g_qkv + (size_t)(bL + k0 + r) * 768 + 256 + h * DKc + c4);
            Ks[r][c4 + 0] = to_tf32(v.x);
            Ks[r][c4 + 1] = to_tf32(v.y);
            Ks[r][c4 + 2] = to_tf32(v.z);
            Ks[r][c4 + 3] = to_tf32(v.w);
        }
        if (t < 64) maskS[t] = mask[bL + k0 + t];
        __syncthreads();

        wmma::fragment<wmma::accumulator, 16, 16, 8, float> sfr[4];
#pragma unroll
        for (int ni = 0; ni < 4; ni++) wmma::fill_fragment(sfr[ni], 0.f);
#pragma unroll
        for (int k8 = 0; k8 < 32; k8 += 8) {
            wmma::fragment<wmma::matrix_a, 16, 16, 8, wmma::precision::tf32, wmma::row_major> af;
            wmma::load_matrix_sync(af, &Qs[wid * 16][k8], 36);
#pragma unroll
            for (int ni = 0; ni < 4; ni++) {
                wmma::fragment<wmma::matrix_b, 16, 16, 8, wmma::precision::tf32, wmma::col_major> bf;
                wmma::load_matrix_sync(bf, &Ks[ni * 16][k8], 36);
                wmma::mma_sync(sfr[ni], af, bf, sfr[ni]);
            }
        }
#pragma unroll
        for (int ni = 0; ni < 4; ni++)
            wmma::store_matrix_sync(&Ss[wid * 16][ni * 16], sfr[ni], 68, wmma::mem_row_major);
        __syncthreads();

        const float* brow = g_bias + (size_t)(bL + m0 + myrow) * Lc + k0 + myhalf;
        const float* srow = &Ss[myrow][myhalf];
#pragma unroll
        for (int i = 0; i < 32; i += 4) {
            float4 bb = *reinterpret_cast<const float4*>(brow + i);
            float s0 = srow[i + 0] + bb.x; if (maskS[myhalf + i + 0] <= 0.f) s0 = -1e9f;
            float s1 = srow[i + 1] + bb.y; if (maskS[myhalf + i + 1] <= 0.f) s1 = -1e9f;
            float s2 = srow[i + 2] + bb.z; if (maskS[myhalf + i + 2] <= 0.f) s2 = -1e9f;
            float s3 = srow[i + 3] + bb.w; if (maskS[myhalf + i + 3] <= 0.f) s3 = -1e9f;
            mymax = fmaxf(mymax, fmaxf(fmaxf(s0, s1), fmaxf(s2, s3)));
        }
        __syncthreads();
    }
    rowm[myrow][t & 1] = mymax;
    __syncthreads();
    float m_final = fmaxf(rowm[myrow][0], rowm[myrow][1]);

    // ---------- pass B: exp + sum + PV ----------
    float myl = 0.f;
    wmma::fragment<wmma::accumulator, 16, 16, 8, float> ofr[2];
    wmma::fill_fragment(ofr[0], 0.f);
    wmma::fill_fragment(ofr[1], 0.f);

    for (int kt = 0; kt < 16; kt++) {
        int k0 = kt * 64;
#pragma unroll
        for (int f = t; f < 1024; f += 128) {
            int r = (f >> 3) & 63, c4 = (f & 7) * 4;
            int off = (f < 512) ? 256 : 512;
            float4 v = *reinterpret_cast<const float4*>(
                g_qkv + (size_t)(bL + k0 + r) * 768 + off + h * DKc + c4);
            float* dst = (f < 512) ? &Ks[r][c4] : &Vs[r][c4];
            dst[0] = to_tf32(v.x);
            dst[1] = to_tf32(v.y);
            dst[2] = to_tf32(v.z);
            dst[3] = to_tf32(v.w);
        }
        if (t < 64) maskS[t] = mask[bL + k0 + t];
        __syncthreads();

        wmma::fragment<wmma::accumulator, 16, 16, 8, float> sfr[4];
#pragma unroll
        for (int ni = 0; ni < 4; ni++) wmma::fill_fragment(sfr[ni], 0.f);
#pragma unroll
        for (int k8 = 0; k8 < 32; k8 += 8) {
            wmma::fragment<wmma::matrix_a, 16, 16, 8, wmma::precision::tf32, wmma::row_major> af;
            wmma::load_matrix_sync(af, &Qs[wid * 16][k8], 36);
#pragma unroll
            for (int ni = 0; ni < 4; ni++) {
                wmma::fragment<wmma::matrix_b, 16, 16, 8, wmma::precision::tf32, wmma::col_major> bf;
                wmma::load_matrix_sync(bf, &Ks[ni * 16][k8], 36);
                wmma::mma_sync(sfr[ni], af, bf, sfr[ni]);
            }
        }
#pragma unroll
        for (int ni = 0; ni < 4; ni++)
            wmma::store_matrix_sync(&Ss[wid * 16][ni * 16], sfr[ni], 68, wmma::mem_row_major);
        __syncthreads();

        const float* brow = g_bias + (size_t)(bL + m0 + myrow) * Lc + k0 + myhalf;
        float* srow = &Ss[myrow][myhalf];
#pragma unroll
        for (int i = 0; i < 32; i += 4) {
            float4 bb = *reinterpret_cast<const float4*>(brow + i);
            float s0 = srow[i + 0] + bb.x; if (maskS[myhalf + i + 0] <= 0.f) s0 = -1e9f;
            float s1 = srow[i + 1] + bb.y; if (maskS[myhalf + i + 1] <= 0.f) s1 = -1e9f;
            float s2 = srow[i + 2] + bb.z; if (maskS[myhalf + i + 2] <= 0.f) s2 = -1e9f;
            float s3 = srow[i + 3] + bb.w; if (maskS[myhalf + i + 3] <= 0.f) s3 = -1e9f;
            float p0 = __expf(s0 - m_final);
            float p1 = __expf(s1 - m_final);
            float p2 = __expf(s2 - m_final);
            float p3 = __expf(s3 - m_final);
            myl += (p0 + p1) + (p2 + p3);
            srow[i + 0] = to_tf32(p0);
            srow[i + 1] = to_tf32(p1);
            srow[i + 2] = to_tf32(p2);
            srow[i + 3] = to_tf32(p3);
        }
        __syncthreads();

#pragma unroll
        for (int k8 = 0; k8 < 64; k8 += 8) {
            wmma::fragment<wmma::matrix_a, 16, 16, 8, wmma::precision::tf32, wmma::row_major> af;
            wmma::load_matrix_sync(af, &Ss[wid * 16][k8], 68);
#pragma unroll
            for (int ni = 0; ni < 2; ni++) {
                wmma::fragment<wmma::matrix_b, 16, 16, 8, wmma::precision::tf32, wmma::row_major> bf;
                wmma::load_matrix_sync(bf, &Vs[k8][ni * 16], 36);
                wmma::mma_sync(ofr[ni], af, bf, ofr[ni]);
            }
        }
        __syncthreads();
    }

    rowl[myrow][t & 1] = myl;
    wmma::store_matrix_sync(&Ss[wid * 16][0], ofr[0], 68, wmma::mem_row_major);
    wmma::store_matrix_sync(&Ss[wid * 16][16], ofr[1], 68, wmma::mem_row_major);
    __syncthreads();
    float linv = 1.f / (rowl[myrow][0] + rowl[myrow][1]);
    int myq = (t & 1) * 16;
    float* op = g_ctx + (size_t)(bL + m0 + myrow) * Dc + h * DKc + myq;
#pragma unroll
    for (int i = 0; i < 16; i += 4) {
        float4 o;
        o.x = Ss[myrow][myq + i + 0] * linv;
        o.y = Ss[myrow][myq + i + 1] * linv;
        o.z = Ss[myrow][myq + i + 2] * linv;
        o.w = Ss[myrow][myq + i + 3] * linv;
        *reinterpret_cast<float4*>(op + i) = o;
    }
}

// ---------------- LN1: h_V_new = LN(h_V + ctx@Wo+bo) * mask ----------------
__global__ void ln1_kernel(const float* __restrict__ hV,
                           const float* __restrict__ gvec, const float* __restrict__ bvec,
                           const float* __restrict__ mask, float* __restrict__ out) {
    __shared__ float sh[8];
    int row = blockIdx.x, t = threadIdx.x;
    float x = hV[row * Dc + t] + g_tmp[row * Dc + t];
    float mean = blockSum(x, sh) * (1.f / Dc);
    float d = x - mean;
    float var = blockSum(d * d, sh) * (1.f / Dc);
    float y = d * rsqrtf(var + 1e-5f) * gvec[t] + bvec[t];
    out[row * Dc + t] = y * mask[row];
}

// ------- LN2 vectorized: h_E = LN(E + m1_raw + b13); 4 rows/block, float4 -------
__global__ void __launch_bounds__(256)
ln2v_kernel(const float* __restrict__ Ein,
            const float* __restrict__ b13,
            const float* __restrict__ gvec, const float* __restrict__ bvec,
            float* __restrict__ out) {
    __shared__ float s1[4][2], s2[4][2];
    int t = threadIdx.x;
    int rb = t >> 6;              // row in block 0..3
    int l6 = t & 63;              // lane within row
    int w2 = (t >> 5) & 1;        // warp-half within row
    size_t row = (size_t)blockIdx.x * 4 + rb;
    int c = l6 * 4;
    float4 e = *reinterpret_cast<const float4*>(Ein + row * Dc + c);
    float4 m = *reinterpret_cast<const float4*>(g_m1 + row * Dc + c);
    float4 bb = *reinterpret_cast<const float4*>(b13 + c);
    float x0 = e.x + m.x + bb.x;
    float x1 = e.y + m.y + bb.y;
    float x2 = e.z + m.z + bb.z;
    float x3 = e.w + m.w + bb.w;
    float sum = (x0 + x1) + (x2 + x3);
    float sq = x0 * x0 + x1 * x1 + x2 * x2 + x3 * x3;
#pragma unroll
    for (int o = 16; o; o >>= 1) {
        sum += __shfl_down_sync(0xffffffffu, sum, o);
        sq  += __shfl_down_sync(0xffffffffu, sq, o);
    }
    if ((t & 31) == 0) { s1[rb][w2] = sum; s2[rb][w2] = sq; }
    __syncthreads();
    float tot = s1[rb][0] + s1[rb][1];
    float tsq = s2[rb][0] + s2[rb][1];
    float mean = tot * (1.f / Dc);
    float var = tsq * (1.f / Dc) - mean * mean;
    float inv = rsqrtf(var + 1e-5f);
    float4 g4 = *reinterpret_cast<const float4*>(gvec + c);
    float4 b4 = *reinterpret_cast<const float4*>(bvec + c);
    float4 o;
    o.x = (x0 - mean) * inv * g4.x + b4.x;
    o.y = (x1 - mean) * inv * g4.y + b4.y;
    o.z = (x2 - mean) * inv * g4.z + b4.z;
    o.w = (x3 - mean) * inv * g4.w + b4.w;
    *reinterpret_cast<float4*>(out + row * Dc + c) = o;
}

// ---------------- host launch ----------------
extern "C" void kernel_launch(void* const* d_in, const int* in_sizes, int n_in,
                              void* d_out, int out_size) {
    const float* h_V    = (const float*)d_in[0];
    const float* E      = (const float*)d_in[1];
    const int*   E_idx  = (const int*)  d_in[2];
    const float* mask   = (const float*)d_in[3];
    const float* nonE   = (const float*)d_in[4];
    const float* bias_W = (const float*)d_in[5];
    const float* bias_b = (const float*)d_in[6];
    const float* Wq = (const float*)d_in[7];  const float* bq = (const float*)d_in[8];
    const float* Wk = (const float*)d_in[9];  const float* bk = (const float*)d_in[10];
    const float* Wv = (const float*)d_in[11]; const float* bv = (const float*)d_in[12];
    const float* Wo = (const float*)d_in[13]; const float* bo = (const float*)d_in[14];
    const float* ln1g = (const float*)d_in[15]; const float* ln1b = (const float*)d_in[16];
    const float* W11 = (const float*)d_in[17]; const float* b11 = (const float*)d_in[18];
    const float* W12 = (const float*)d_in[19]; const float* b12 = (const float*)d_in[20];
    const float* W13 = (const float*)d_in[21]; const float* b13 = (const float*)d_in[22];
    const float* ln2g = (const float*)d_in[23]; const float* ln2b = (const float*)d_in[24];

    float* out_hV = (float*)d_out;
    float* out_hE = out_hV + M1c * Dc;

    float *p_qkv, *p_ctx, *p_tmp, *p_hvpair, *p_m1, *p_m2;
    float *p_w1r, *p_w2r, *p_w3r, *p_wqkv, *p_bqkv, *p_w11p, *p_b11p;
    cudaGetSymbolAddress((void**)&p_qkv,   g_qkv);
    cudaGetSymbolAddress((void**)&p_ctx,   g_ctx);
    cudaGetSymbolAddress((void**)&p_tmp,   g_tmp);
    cudaGetSymbolAddress((void**)&p_hvpair,g_hvpair);
    cudaGetSymbolAddress((void**)&p_m1,    g_m1);
    cudaGetSymbolAddress((void**)&p_m2,    g_m2);
    cudaGetSymbolAddress((void**)&p_w1r,   g_w1r);
    cudaGetSymbolAddress((void**)&p_w2r,   g_w2r);
    cudaGetSymbolAddress((void**)&p_w3r,   g_w3r);
    cudaGetSymbolAddress((void**)&p_wqkv,  g_wqkv);
    cudaGetSymbolAddress((void**)&p_bqkv,  g_bqkv);
    cudaGetSymbolAddress((void**)&p_w11p,  g_w11p);
    cudaGetSymbolAddress((void**)&p_b11p,  g_b11p);

    // 1: weight packing   2: weight rounding   3-4: attention bias
    wpack_kernel<<<1281, 256>>>(Wq, Wk, Wv, bq, bk, bv, W11, b11);
    round_w_kernel<<<256, 256>>>(W11, W12, W13);
    bias_fillbase_kernel<<<(Bc * Lc * Lc) / 256, 256>>>(nonE, bias_W, bias_b);
    bias_scatter_kernel<<<(Bc * Lc) / 8, 256>>>(E, E_idx, bias_W, bias_b);

    // 5: fused qkv GEMM (M=4096, N=768)
    gemm64<<<dim3(768 / 64, M1c / 64), 256>>>(h_V, p_wqkv, p_qkv, M1c, 768, Dc, p_bqkv, 0);

    // 6: fused flash attention -> g_ctx  (profiled slot)
    flash_kernel<<<dim3(Lc / 64, Bc * Hc), 128>>>(mask);

    // 7-8: out proj + LN1 (writes h_V_new into d_out)
    dim3 gqkv(Dc / 64, M1c / 64);
    gemm64<<<gqkv, 256>>>(p_ctx, Wo, p_tmp, M1c, Dc, Dc, bo, 0);
    ln1_kernel<<<M1c, 256>>>(h_V, ln1g, ln1b, mask, out_hV);

    // 9: hvpair = [h_V_new @ W11lo + b11 | h_V_new @ W11hi]  (M=4096, N=512)
    gemm64<<<dim3(512 / 64, M1c / 64), 256>>>(out_hV, p_w11p, p_hvpair, M1c, 512, Dc, p_b11p, 0);

    // 10-12: MLP big GEMMs (producer-side fused epilogues)
    dim3 gbig(Dc / 128, M2c / 128);
    gemm_tc<1><<<gbig, 256>>>(E, p_w1r, p_m1, p_hvpair, E_idx);   // m1 = rna(gelu(E@W11mid + hvp + hvW3[nb]))
    gemm_tc<2><<<gbig, 256>>>(p_m1, p_w2r, p_m2, b12, nullptr);   // m2 = rna(gelu(m1@W12 + b12))
    gemm_tc<0><<<gbig, 256>>>(p_m2, p_w3r, p_m1, nullptr, nullptr); // m1 = m2@W13 (raw)

    // 13: LN2
    ln2v_kernel<<<M2c / 4, 256>>>(E, b13, ln2g, ln2b, out_hE);
}

// round 17
// speedup vs baseline: 2.1491x; 1.5836x over previous
#include <cuda_runtime.h>
#include <cuda_fp16.h>
#include <cstdint>
#include <math.h>
#include <mma.h>

using namespace nvcuda;

#define Bc 4
#define Lc 1024
#define Kc 30
#define Dc 256
#define Hc 8
#define DKc 32

#define M1c (Bc*Lc)          // 4096
#define M2c (Bc*Lc*Kc)       // 122880

#define NSTAGE 3

// ---------------- scratch (static device globals; no allocations) ----------------
__device__ float g_qkv[M1c*768];                // fused q|k|v projections
__device__ float g_bias[Bc*Lc*Lc];              // 16 MB (fits in L2)
__device__ float g_ctx[M1c*Dc];
__device__ float g_tmp[M1c*Dc];
__device__ float g_hvpair[M1c*512];             // [hvp+b11 | hvW3] per row
__device__ __half g_eh[M2c*Dc];                 // E in fp16 (63 MB)
__device__ __half g_m1h[M2c*Dc];                // 63 MB
__device__ __half g_m2h[M2c*Dc];                // 63 MB
__device__ float g_mraw[M2c*Dc];                // 126 MB (GEMM3 raw out)
__device__ __half g_w1h[Dc*Dc];                 // fp16(W11[256:512])
__device__ __half g_w2h[Dc*Dc];                 // fp16(W12)
__device__ __half g_w3h[Dc*Dc];                 // fp16(W13)
__device__ float g_wqkv[Dc*768];                // Wq|Wk|Wv packed
__device__ float g_bqkv[768];                   // bq|bk|bv packed
__device__ float g_w11p[Dc*512];                // W11[0:256]|W11[512:768] packed
__device__ float g_b11p[512];                   // b11|0

// ---------------- packed f32x2 helpers (for gemm64) ----------------
typedef unsigned long long u64;

__device__ __forceinline__ u64 pack2(float x, float y) {
    u64 r;
    asm("mov.b64 %0, {%1, %2};" : "=l"(r) : "f"(x), "f"(y));
    return r;
}
__device__ __forceinline__ void fma2(u64& d, u64 a, u64 b) {
    asm("fma.rn.f32x2 %0, %1, %2, %0;" : "+l"(d) : "l"(a), "l"(b));
}
__device__ __forceinline__ float2 unpack2(u64 v) {
    float2 f;
    asm("mov.b64 {%0, %1}, %2;" : "=f"(f.x), "=f"(f.y) : "l"(v));
    return f;
}
__device__ __forceinline__ float to_tf32(float x) {
    float y;
    asm("cvt.rna.tf32.f32 %0, %1;" : "=f"(y) : "f"(x));
    return y;
}

// ---------------- cp.async helpers ----------------
__device__ __forceinline__ void cp_async16(void* smem_dst, const void* gsrc) {
    uint32_t s = (uint32_t)__cvta_generic_to_shared(smem_dst);
    asm volatile("cp.async.cg.shared.global [%0], [%1], 16;" :: "r"(s), "l"(gsrc));
}
__device__ __forceinline__ void cp_commit() {
    asm volatile("cp.async.commit_group;");
}
template<int N>
__device__ __forceinline__ void cp_wait() {
    asm volatile("cp.async.wait_group %0;" :: "n"(N));
}

// ---------------- reduction helpers ----------------
__device__ __forceinline__ float blockSum(float v, float* sh) {
    int lane = threadIdx.x & 31, wid = threadIdx.x >> 5;
#pragma unroll
    for (int o = 16; o; o >>= 1) v += __shfl_down_sync(0xffffffffu, v, o);
    if (lane == 0) sh[wid] = v;
    __syncthreads();
    if (wid == 0) {
        float r = (lane < 8) ? sh[lane] : 0.f;
#pragma unroll
        for (int o = 4; o; o >>= 1) r += __shfl_down_sync(0xffffffffu, r, o);
        if (lane == 0) sh[0] = r;
    }
    __syncthreads();
    float out = sh[0];
    __syncthreads();
    return out;
}

__device__ __forceinline__ float gelu_exact(float x) {
    return 0.5f * x * (1.0f + erff(x * 0.70710678118654752f));
}

// -------- E -> fp16 conversion (RN) --------
__global__ void e2h_kernel(const float* __restrict__ E) {
    size_t i = ((size_t)blockIdx.x * 256 + threadIdx.x) * 8;
    float4 a = *reinterpret_cast<const float4*>(E + i);
    float4 b = *reinterpret_cast<const float4*>(E + i + 4);
    __half2* o = reinterpret_cast<__half2*>(g_eh + i);
    o[0] = __floats2half2_rn(a.x, a.y);
    o[1] = __floats2half2_rn(a.z, a.w);
    o[2] = __floats2half2_rn(b.x, b.y);
    o[3] = __floats2half2_rn(b.z, b.w);
}

// -------- weight packing: Wq|Wk|Wv, W11lo|W11hi, biases --------
__global__ void wpack_kernel(const float* __restrict__ Wq, const float* __restrict__ Wk,
                             const float* __restrict__ Wv,
                             const float* __restrict__ bq, const float* __restrict__ bk,
                             const float* __restrict__ bv,
                             const float* __restrict__ W11, const float* __restrict__ b11) {
    int bid = blockIdx.x, t = threadIdx.x;
    if (bid < 768) {
        int i = bid * 256 + t;
        int k = i / 768, c = i % 768;
        float v;
        if (c < 256)      v = Wq[k * 256 + c];
        else if (c < 512) v = Wk[k * 256 + c - 256];
        else              v = Wv[k * 256 + c - 512];
        g_wqkv[i] = v;
    } else if (bid < 1280) {
        int i = (bid - 768) * 256 + t;
        int k = i / 512, c = i % 512;
        g_w11p[i] = (c < 256) ? W11[(size_t)k * 256 + c]
                              : W11[(size_t)(512 + k) * 256 + (c - 256)];
    } else {
        g_bqkv[t]       = bq[t];
        g_bqkv[256 + t] = bk[t];
        g_bqkv[512 + t] = bv[t];
        g_b11p[t]       = b11[t];
        g_b11p[256 + t] = 0.f;
    }
}

// -------- weight pre-conversion to fp16 --------
__global__ void round_w_kernel(const float* __restrict__ W11,
                               const float* __restrict__ W12,
                               const float* __restrict__ W13) {
    int i = blockIdx.x * 256 + threadIdx.x;   // 0 .. 65535
    g_w1h[i] = __float2half(W11[(size_t)256 * Dc + i]);
    g_w2h[i] = __float2half(W12[i]);
    g_w3h[i] = __float2half(W13[i]);
}

// -------- bias fill (computes base per-block, fills plane) --------
__global__ void bias_fillbase_kernel(const float* __restrict__ nonE,
                                     const float* __restrict__ bias_W,
                                     const float* __restrict__ bias_b) {
    __shared__ float sh[8];
    int t = threadIdx.x;
    float p = nonE[t] * bias_W[t];
    float s = blockSum(p, sh);
    g_bias[(size_t)blockIdx.x * 256 + t] = s + bias_b[0];
}

// one warp per (b,l); k loop serial on lane 0 => last write wins for duplicate idx
__global__ void bias_scatter_kernel(const float* __restrict__ E,
                                    const int* __restrict__ E_idx,
                                    const float* __restrict__ bias_W,
                                    const float* __restrict__ bias_b) {
    int w = (blockIdx.x * blockDim.x + threadIdx.x) >> 5;
    int lane = threadIdx.x & 31;
    if (w >= Bc * Lc) return;
    float bb = bias_b[0];
    for (int k = 0; k < Kc; k++) {
        const float* er = E + (w * Kc + k) * Dc;
        float p = 0.f;
#pragma unroll
        for (int c = lane; c < Dc; c += 32) p += er[c] * bias_W[c];
#pragma unroll
        for (int o = 16; o; o >>= 1) p += __shfl_down_sync(0xffffffffu, p, o);
        if (lane == 0) {
            int idx = E_idx[w * Kc + k];
            g_bias[w * Lc + idx] = p + bb;
        }
    }
}

// ---------------- 64x64 tiled fp32 GEMM with f32x2 (small M GEMMs) ----------------
__global__ void gemm64(const float* __restrict__ A, const float* __restrict__ Bm,
                       float* __restrict__ C, int M, int N, int Kd,
                       const float* __restrict__ bias, int act) {
    __shared__ float As[64][17];
    __shared__ float Bs[16][64];
    int t = threadIdx.x;
    int tx = t & 15, ty = t >> 4;
    int m0 = blockIdx.y * 64, n0 = blockIdx.x * 64;
    u64 acc[4][2] = {};
    for (int k0 = 0; k0 < Kd; k0 += 16) {
#pragma unroll
        for (int i = 0; i < 4; i++) {
            int e = t + i * 256; int r = e >> 4, c = e & 15;
            As[r][c] = A[(size_t)(m0 + r) * Kd + k0 + c];
        }
#pragma unroll
        for (int i = 0; i < 4; i++) {
            int e = t + i * 256; int kk = e >> 6, c = e & 63;
            Bs[kk][c] = Bm[(size_t)(k0 + kk) * N + n0 + c];
        }
        __syncthreads();
#pragma unroll
        for (int kk = 0; kk < 16; kk++) {
            ulonglong2 bb = *reinterpret_cast<const ulonglong2*>(&Bs[kk][tx * 4]);
#pragma unroll
            for (int i = 0; i < 4; i++) {
                float a = As[ty * 4 + i][kk];
                u64 aa = pack2(a, a);
                fma2(acc[i][0], aa, bb.x);
                fma2(acc[i][1], aa, bb.y);
            }
        }
        __syncthreads();
    }
#pragma unroll
    for (int i = 0; i < 4; i++) {
        int row = m0 + ty * 4 + i;
#pragma unroll
        for (int j = 0; j < 2; j++) {
            float2 v = unpack2(acc[i][j]);
            int col = n0 + tx * 4 + j * 2;
            float x0 = v.x + (bias ? bias[col] : 0.f);
            float x1 = v.y + (bias ? bias[col + 1] : 0.f);
            if (act == 1) { x0 = gelu_exact(x0); x1 = gelu_exact(x1); }
            C[(size_t)row * N + col] = x0;
            C[(size_t)row * N + col + 1] = x1;
        }
    }
}

// ====== cp.async-pipelined fp16 tensor-core 128x128 GEMM, K=256, N=256 ======
// A, B are __half (pre-converted). fp32 accumulate.
// EPI 0: C(float) = acc                                  (raw; consumed by ln2v)
// EPI 1: C(half) = h(gelu(acc + aux[hvb] + aux[nbb]))    (hvpair fused)
// EPI 2: C(half) = h(gelu(acc + aux[col]))               (b12 fused)
template<int EPI>
__global__ void __launch_bounds__(256, 2)
gemm_tc(const __half* __restrict__ A, const __half* __restrict__ Bm,
        void* __restrict__ Cv,
        const float* __restrict__ aux,
        const int* __restrict__ E_idx) {
    __shared__ __half As[NSTAGE][128][40];   // K-chunk 32 halves + pad
    __shared__ __half Bs[NSTAGE][32][136];   // 32 k-rows x 128 cols + pad
    __shared__ float St[8][16][20];
    __shared__ int hvb[128];
    __shared__ int nbb[128];
    int t = threadIdx.x;
    int wid = t >> 5, lane = t & 31;
    int wm = wid & 3, wn = wid >> 2;
    int m0 = blockIdx.y * 128, n0 = blockIdx.x * 128;
    if (EPI == 1 && t < 128) {
        int r = m0 + t;
        hvb[t] = (r / Kc) * 512;                     // hvp columns 0-255 of hvpair
        int b_ = r / (Lc * Kc);
        nbb[t] = (b_ * Lc + E_idx[r]) * 512 + 256;   // hvW3 columns 256-511
    }

    const __half* Ablk = A + (size_t)m0 * Dc;
    const __half* Bblk = Bm + n0;
    const int nk = Dc / 32;   // 8 k-chunks

    auto load_stage = [&](int s, int kt) {
        int k0 = kt * 32;
#pragma unroll
        for (int i = 0; i < 4; i++) {
            int f = t + i * 256;                   // 0..1023
            if (f < 512) {
                int r = f >> 2, c8 = (f & 3) * 8;  // 4 chunks x 8 halves per A row
                cp_async16(&As[s][r][c8], Ablk + (size_t)r * Dc + k0 + c8);
            } else {
                int g = f - 512;
                int kk = g >> 4, c = (g & 15) * 8; // 16 chunks per B row
                cp_async16(&Bs[s][kk][c], Bblk + (size_t)(k0 + kk) * Dc + c);
            }
        }
        cp_commit();
    };

    wmma::fragment<wmma::accumulator, 16, 16, 16, float> acc[2][4];
#pragma unroll
    for (int i = 0; i < 2; i++)
#pragma unroll
        for (int j = 0; j < 4; j++) wmma::fill_fragment(acc[i][j], 0.f);

    load_stage(0, 0);
    load_stage(1, 1);

    for (int kt = 0; kt < nk; kt++) {
        int s = kt % NSTAGE;
        cp_wait<NSTAGE - 2>();
        __syncthreads();
        if (kt + NSTAGE - 1 < nk)
            load_stage((kt + NSTAGE - 1) % NSTAGE, kt + NSTAGE - 1);
#pragma unroll
        for (int k16 = 0; k16 < 32; k16 += 16) {
            wmma::fragment<wmma::matrix_a, 16, 16, 16, __half, wmma::row_major> af[2];
            wmma::load_matrix_sync(af[0], &As[s][wm * 32][k16], 40);
            wmma::load_matrix_sync(af[1], &As[s][wm * 32 + 16][k16], 40);
#pragma unroll
            for (int ni = 0; ni < 4; ni++) {
                wmma::fragment<wmma::matrix_b, 16, 16, 16, __half, wmma::row_major> bf;
                wmma::load_matrix_sync(bf, &Bs[s][k16][wn * 64 + ni * 16], 136);
                wmma::mma_sync(acc[0][ni], af[0], bf, acc[0][ni]);
                wmma::mma_sync(acc[1][ni], af[1], bf, acc[1][ni]);
            }
        }
    }

    if (EPI == 0) {
        float* C = (float*)Cv;
#pragma unroll
        for (int mi = 0; mi < 2; mi++)
#pragma unroll
            for (int ni = 0; ni < 4; ni++) {
                float* cp = C + (size_t)(m0 + wm * 32 + mi * 16) * Dc + n0 + wn * 64 + ni * 16;
                wmma::store_matrix_sync(cp, acc[mi][ni], Dc, wmma::mem_row_major);
            }
    } else {
        __half* C = (__half*)Cv;
#pragma unroll
        for (int mi = 0; mi < 2; mi++)
#pragma unroll
            for (int ni = 0; ni < 4; ni++) {
                wmma::store_matrix_sync(&St[wid][0][0], acc[mi][ni], 20, wmma::mem_row_major);
                __syncwarp();
#pragma unroll
                for (int e = lane; e < 256; e += 32) {
                    int r = e >> 4, c = e & 15;
                    int lrow = wm * 32 + mi * 16 + r;      // 0..127 within tile
                    int grow = m0 + lrow;
                    int gcol = n0 + wn * 64 + ni * 16 + c;
                    float v = St[wid][r][c];
                    if (EPI == 1)
                        v = gelu_exact(v + aux[hvb[lrow] + gcol] + aux[nbb[lrow] + gcol]);
                    else
                        v = gelu_exact(v + aux[gcol]);
                    C[(size_t)grow * Dc + gcol] = __float2half(v);
                }
                __syncwarp();
            }
    }
}

// ================= fused flash attention (tf32 WMMA QK^T & PV, exact softmax) ========
// q/k/v read from fused g_qkv[row][768] (biases already added by gemm64).
__global__ void __launch_bounds__(128)
flash_kernel(const float* __restrict__ mask) {
    __shared__ float Qs[64][36];
    __shared__ float Ks[64][36];
    __shared__ float Vs[64][36];
    __shared__ float Ss[64][68];
    __shared__ float rowm[64][2];
    __shared__ float rowl[64][2];
    __shared__ float maskS[64];

    int t = threadIdx.x;
    int wid = t >> 5;
    int m0 = blockIdx.x * 64;
    int bh = blockIdx.y; int b = bh >> 3, h = bh & 7;
    int bL = b * Lc;
    int myrow = t >> 1, myhalf = (t & 1) * 32;
    const float scale = 0.17677669529663687f;  // 1/sqrt(32)

    // load Q tile (pre-scaled, tf32)
#pragma unroll
    for (int f = t; f < 512; f += 128) {
        int r = f >> 3, c4 = (f & 7) * 4;
        float4 v = *reinterpret_cast<const float4*>(
            g_qkv + (size_t)(bL + m0 + r) * 768 + h * DKc + c4);
        Qs[r][c4 + 0] = to_tf32(v.x * scale);
        Qs[r][c4 + 1] = to_tf32(v.y * scale);
        Qs[r][c4 + 2] = to_tf32(v.z * scale);
        Qs[r][c4 + 3] = to_tf32(v.w * scale);
    }

    // ---------- pass A: row max ----------
    float mymax = -3.0e38f;
    for (int kt = 0; kt < 16; kt++) {
        int k0 = kt * 64;
#pragma unroll
        for (int f = t; f < 512; f += 128) {
            int r = f >> 3, c4 = (f & 7) * 4;
            float4 v = *reinterpret_cast<const float4*>(
                g_qkv + (size_t)(bL + k0 + r) * 768 + 256 + h * DKc + c4);
            Ks[r][c4 + 0] = to_tf32(v.x);
            Ks[r][c4 + 1] = to_tf32(v.y);
            Ks[r][c4 + 2] = to_tf32(v.z);
            Ks[r][c4 + 3] = to_tf32(v.w);
        }
        if (t < 64) maskS[t] = mask[bL + k0 + t];
        __syncthreads();

        wmma::fragment<wmma::accumulator, 16, 16, 8, float> sfr[4];
#pragma unroll
        for (int ni = 0; ni < 4; ni++) wmma::fill_fragment(sfr[ni], 0.f);
#pragma unroll
        for (int k8 = 0; k8 < 32; k8 += 8) {
            wmma::fragment<wmma::matrix_a, 16, 16, 8, wmma::precision::tf32, wmma::row_major> af;
            wmma::load_matrix_sync(af, &Qs[wid * 16][k8], 36);
#pragma unroll
            for (int ni = 0; ni < 4; ni++) {
                wmma::fragment<wmma::matrix_b, 16, 16, 8, wmma::precision::tf32, wmma::col_major> bf;
                wmma::load_matrix_sync(bf, &Ks[ni * 16][k8], 36);
                wmma::mma_sync(sfr[ni], af, bf, sfr[ni]);
            }
        }
#pragma unroll
        for (int ni = 0; ni < 4; ni++)
            wmma::store_matrix_sync(&Ss[wid * 16][ni * 16], sfr[ni], 68, wmma::mem_row_major);
        __syncthreads();

        const float* brow = g_bias + (size_t)(bL + m0 + myrow) * Lc + k0 + myhalf;
        const float* srow = &Ss[myrow][myhalf];
#pragma unroll
        for (int i = 0; i < 32; i += 4) {
            float4 bb = *reinterpret_cast<const float4*>(brow + i);
            float s0 = srow[i + 0] + bb.x; if (maskS[myhalf + i + 0] <= 0.f) s0 = -1e9f;
            float s1 = srow[i + 1] + bb.y; if (maskS[myhalf + i + 1] <= 0.f) s1 = -1e9f;
            float s2 = srow[i + 2] + bb.z; if (maskS[myhalf + i + 2] <= 0.f) s2 = -1e9f;
            float s3 = srow[i + 3] + bb.w; if (maskS[myhalf + i + 3] <= 0.f) s3 = -1e9f;
            mymax = fmaxf(mymax, fmaxf(fmaxf(s0, s1), fmaxf(s2, s3)));
        }
        __syncthreads();
    }
    rowm[myrow][t & 1] = mymax;
    __syncthreads();
    float m_final = fmaxf(rowm[myrow][0], rowm[myrow][1]);

    // ---------- pass B: exp + sum + PV ----------
    float myl = 0.f;
    wmma::fragment<wmma::accumulator, 16, 16, 8, float> ofr[2];
    wmma::fill_fragment(ofr[0], 0.f);
    wmma::fill_fragment(ofr[1], 0.f);

    for (int kt = 0; kt < 16; kt++) {
        int k0 = kt * 64;
#pragma unroll
        for (int f = t; f < 1024; f += 128) {
            int r = (f >> 3) & 63, c4 = (f & 7) * 4;
            int off = (f < 512) ? 256 : 512;
            float4 v = *reinterpret_cast<const float4*>(
                g_qkv + (size_t)(bL + k0 + r) * 768 + off + h * DKc + c4);
            float* dst = (f < 512) ? &Ks[r][c4] : &Vs[r][c4];
            dst[0] = to_tf32(v.x);
            dst[1] = to_tf32(v.y);
            dst[2] = to_tf32(v.z);
            dst[3] = to_tf32(v.w);
        }
        if (t < 64) maskS[t] = mask[bL + k0 + t];
        __syncthreads();

        wmma::fragment<wmma::accumulator, 16, 16, 8, float> sfr[4];
#pragma unroll
        for (int ni = 0; ni < 4; ni++) wmma::fill_fragment(sfr[ni], 0.f);
#pragma unroll
        for (int k8 = 0; k8 < 32; k8 += 8) {
            wmma::fragment<wmma::matrix_a, 16, 16, 8, wmma::precision::tf32, wmma::row_major> af;
            wmma::load_matrix_sync(af, &Qs[wid * 16][k8], 36);
#pragma unroll
            for (int ni = 0; ni < 4; ni++) {
                wmma::fragment<wmma::matrix_b, 16, 16, 8, wmma::precision::tf32, wmma::col_major> bf;
                wmma::load_matrix_sync(bf, &Ks[ni * 16][k8], 36);
                wmma::mma_sync(sfr[ni], af, bf, sfr[ni]);
            }
        }
#pragma unroll
        for (int ni = 0; ni < 4; ni++)
            wmma::store_matrix_sync(&Ss[wid * 16][ni * 16], sfr[ni], 68, wmma::mem_row_major);
        __syncthreads();

        const float* brow = g_bias + (size_t)(bL + m0 + myrow) * Lc + k0 + myhalf;
        float* srow = &Ss[myrow][myhalf];
#pragma unroll
        for (int i = 0; i < 32; i += 4) {
            float4 bb = *reinterpret_cast<const float4*>(brow + i);
            float s0 = srow[i + 0] + bb.x; if (maskS[myhalf + i + 0] <= 0.f) s0 = -1e9f;
            float s1 = srow[i + 1] + bb.y; if (maskS[myhalf + i + 1] <= 0.f) s1 = -1e9f;
            float s2 = srow[i + 2] + bb.z; if (maskS[myhalf + i + 2] <= 0.f) s2 = -1e9f;
            float s3 = srow[i + 3] + bb.w; if (maskS[myhalf + i + 3] <= 0.f) s3 = -1e9f;
            float p0 = __expf(s0 - m_final);
            float p1 = __expf(s1 - m_final);
            float p2 = __expf(s2 - m_final);
            float p3 = __expf(s3 - m_final);
            myl += (p0 + p1) + (p2 + p3);
            srow[i + 0] = to_tf32(p0);
            srow[i + 1] = to_tf32(p1);
            srow[i + 2] = to_tf32(p2);
            srow[i + 3] = to_tf32(p3);
        }
        __syncthreads();

#pragma unroll
        for (int k8 = 0; k8 < 64; k8 += 8) {
            wmma::fragment<wmma::matrix_a, 16, 16, 8, wmma::precision::tf32, wmma::row_major> af;
            wmma::load_matrix_sync(af, &Ss[wid * 16][k8], 68);
#pragma unroll
            for (int ni = 0; ni < 2; ni++) {
                wmma::fragment<wmma::matrix_b, 16, 16, 8, wmma::precision::tf32, wmma::row_major> bf;
                wmma::load_matrix_sync(bf, &Vs[k8][ni * 16], 36);
                wmma::mma_sync(ofr[ni], af, bf, ofr[ni]);
            }
        }
        __syncthreads();
    }

    rowl[myrow][t & 1] = myl;
    wmma::store_matrix_sync(&Ss[wid * 16][0], ofr[0], 68, wmma::mem_row_major);
    wmma::store_matrix_sync(&Ss[wid * 16][16], ofr[1], 68, wmma::mem_row_major);
    __syncthreads();
    float linv = 1.f / (rowl[myrow][0] + rowl[myrow][1]);
    int myq = (t & 1) * 16;
    float* op = g_ctx + (size_t)(bL + m0 + myrow) * Dc + h * DKc + myq;
#pragma unroll
    for (int i = 0; i < 16; i += 4) {
        float4 o;
        o.x = Ss[myrow][myq + i + 0] * linv;
        o.y = Ss[myrow][myq + i + 1] * linv;
        o.z = Ss[myrow][myq + i + 2] * linv;
        o.w = Ss[myrow][myq + i + 3] * linv;
        *reinterpret_cast<float4*>(op + i) = o;
    }
}

// ---------------- LN1: h_V_new = LN(h_V + ctx@Wo+bo) * mask ----------------
__global__ void ln1_kernel(const float* __restrict__ hV,
                           const float* __restrict__ gvec, const float* __restrict__ bvec,
                           const float* __restrict__ mask, float* __restrict__ out) {
    __shared__ float sh[8];
    int row = blockIdx.x, t = threadIdx.x;
    float x = hV[row * Dc + t] + g_tmp[row * Dc + t];
    float mean = blockSum(x, sh) * (1.f / Dc);
    float d = x - mean;
    float var = blockSum(d * d, sh) * (1.f / Dc);
    float y = d * rsqrtf(var + 1e-5f) * gvec[t] + bvec[t];
    out[row * Dc + t] = y * mask[row];
}

// ------- LN2 vectorized: h_E = LN(E + mraw + b13); 4 rows/block, float4 -------
__global__ void __launch_bounds__(256)
ln2v_kernel(const float* __restrict__ Ein,
            const float* __restrict__ b13,
            const float* __restrict__ gvec, const float* __restrict__ bvec,
            float* __restrict__ out) {
    __shared__ float s1[4][2], s2[4][2];
    int t = threadIdx.x;
    int rb = t >> 6;              // row in block 0..3
    int l6 = t & 63;              // lane within row
    int w2 = (t >> 5) & 1;        // warp-half within row
    size_t row = (size_t)blockIdx.x * 4 + rb;
    int c = l6 * 4;
    float4 e = *reinterpret_cast<const float4*>(Ein + row * Dc + c);
    float4 m = *reinterpret_cast<const float4*>(g_mraw + row * Dc + c);
    float4 bb = *reinterpret_cast<const float4*>(b13 + c);
    float x0 = e.x + m.x + bb.x;
    float x1 = e.y + m.y + bb.y;
    float x2 = e.z + m.z + bb.z;
    float x3 = e.w + m.w + bb.w;
    float sum = (x0 + x1) + (x2 + x3);
    float sq = x0 * x0 + x1 * x1 + x2 * x2 + x3 * x3;
#pragma unroll
    for (int o = 16; o; o >>= 1) {
        sum += __shfl_down_sync(0xffffffffu, sum, o);
        sq  += __shfl_down_sync(0xffffffffu, sq, o);
    }
    if ((t & 31) == 0) { s1[rb][w2] = sum; s2[rb][w2] = sq; }
    __syncthreads();
    float tot = s1[rb][0] + s1[rb][1];
    float tsq = s2[rb][0] + s2[rb][1];
    float mean = tot * (1.f / Dc);
    float var = tsq * (1.f / Dc) - mean * mean;
    float inv = rsqrtf(var + 1e-5f);
    float4 g4 = *reinterpret_cast<const float4*>(gvec + c);
    float4 b4 = *reinterpret_cast<const float4*>(bvec + c);
    float4 o;
    o.x = (x0 - mean) * inv * g4.x + b4.x;
    o.y = (x1 - mean) * inv * g4.y + b4.y;
    o.z = (x2 - mean) * inv * g4.z + b4.z;
    o.w = (x3 - mean) * inv * g4.w + b4.w;
    *reinterpret_cast<float4*>(out + row * Dc + c) = o;
}

// ---------------- host launch ----------------
extern "C" void kernel_launch(void* const* d_in, const int* in_sizes, int n_in,
                              void* d_out, int out_size) {
    const float* h_V    = (const float*)d_in[0];
    const float* E      = (const float*)d_in[1];
    const int*   E_idx  = (const int*)  d_in[2];
    const float* mask   = (const float*)d_in[3];
    const float* nonE   = (const float*)d_in[4];
    const float* bias_W = (const float*)d_in[5];
    const float* bias_b = (const float*)d_in[6];
    const float* Wq = (const float*)d_in[7];  const float* bq = (const float*)d_in[8];
    const float* Wk = (const float*)d_in[9];  const float* bk = (const float*)d_in[10];
    const float* Wv = (const float*)d_in[11]; const float* bv = (const float*)d_in[12];
    const float* Wo = (const float*)d_in[13]; const float* bo = (const float*)d_in[14];
    const float* ln1g = (const float*)d_in[15]; const float* ln1b = (const float*)d_in[16];
    const float* W11 = (const float*)d_in[17]; const float* b11 = (const float*)d_in[18];
    const float* W12 = (const float*)d_in[19]; const float* b12 = (const float*)d_in[20];
    const float* W13 = (const float*)d_in[21]; const float* b13 = (const float*)d_in[22];
    const float* ln2g = (const float*)d_in[23]; const float* ln2b = (const float*)d_in[24];

    float* out_hV = (float*)d_out;
    float* out_hE = out_hV + M1c * Dc;

    float *p_qkv, *p_ctx, *p_tmp, *p_hvpair, *p_mraw;
    float *p_wqkv, *p_bqkv, *p_w11p, *p_b11p;
    __half *p_eh, *p_m1h, *p_m2h, *p_w1h, *p_w2h, *p_w3h;
    cudaGetSymbolAddress((void**)&p_qkv,   g_qkv);
    cudaGetSymbolAddress((void**)&p_ctx,   g_ctx);
    cudaGetSymbolAddress((void**)&p_tmp,   g_tmp);
    cudaGetSymbolAddress((void**)&p_hvpair,g_hvpair);
    cudaGetSymbolAddress((void**)&p_mraw,  g_mraw);
    cudaGetSymbolAddress((void**)&p_wqkv,  g_wqkv);
    cudaGetSymbolAddress((void**)&p_bqkv,  g_bqkv);
    cudaGetSymbolAddress((void**)&p_w11p,  g_w11p);
    cudaGetSymbolAddress((void**)&p_b11p,  g_b11p);
    cudaGetSymbolAddress((void**)&p_eh,    g_eh);
    cudaGetSymbolAddress((void**)&p_m1h,   g_m1h);
    cudaGetSymbolAddress((void**)&p_m2h,   g_m2h);
    cudaGetSymbolAddress((void**)&p_w1h,   g_w1h);
    cudaGetSymbolAddress((void**)&p_w2h,   g_w2h);
    cudaGetSymbolAddress((void**)&p_w3h,   g_w3h);

    // setup: packing, conversion, attention bias
    wpack_kernel<<<1281, 256>>>(Wq, Wk, Wv, bq, bk, bv, W11, b11);
    round_w_kernel<<<256, 256>>>(W11, W12, W13);
    e2h_kernel<<<(M2c * Dc) / 2048, 256>>>(E);
    bias_fillbase_kernel<<<(Bc * Lc * Lc) / 256, 256>>>(nonE, bias_W, bias_b);
    bias_scatter_kernel<<<(Bc * Lc) / 8, 256>>>(E, E_idx, bias_W, bias_b);

    // fused qkv GEMM (M=4096, N=768)
    gemm64<<<dim3(768 / 64, M1c / 64), 256>>>(h_V, p_wqkv, p_qkv, M1c, 768, Dc, p_bqkv, 0);

    // fused flash attention -> g_ctx
    flash_kernel<<<dim3(Lc / 64, Bc * Hc), 128>>>(mask);

    // out proj + LN1 (writes h_V_new into d_out)
    dim3 gqkv(Dc / 64, M1c / 64);
    gemm64<<<gqkv, 256>>>(p_ctx, Wo, p_tmp, M1c, Dc, Dc, bo, 0);
    ln1_kernel<<<M1c, 256>>>(h_V, ln1g, ln1b, mask, out_hV);

    // hvpair = [h_V_new @ W11lo + b11 | h_V_new @ W11hi]  (M=4096, N=512)
    gemm64<<<dim3(512 / 64, M1c / 64), 256>>>(out_hV, p_w11p, p_hvpair, M1c, 512, Dc, p_b11p, 0);

    // MLP big GEMMs: fp16 HMMA, producer-side fused epilogues
    dim3 gbig(Dc / 128, M2c / 128);
    gemm_tc<1><<<gbig, 256>>>(p_eh, p_w1h, p_m1h, p_hvpair, E_idx);  // m1h = h(gelu(E@W11mid + hvp + hvW3[nb]))
    gemm_tc<2><<<gbig, 256>>>(p_m1h, p_w2h, p_m2h, b12, nullptr);    // m2h = h(gelu(m1@W12 + b12))
    gemm_tc<0><<<gbig, 256>>>(p_m2h, p_w3h, p_mraw, nullptr, nullptr); // mraw = m2@W13 (fp32)
    ln2v_kernel<<<M2c / 4, 256>>>(E, b13, ln2g, ln2b, out_hE);
}